// round 1
// baseline (speedup 1.0000x reference)
#include <cuda_runtime.h>
#include <math.h>

#define B_  4
#define LQ_ 1024
#define LKV_ 4096
#define D_  512
#define H_  4
#define HD_ 128
#define SCALE_ 0.08838834764831845f  // 1/sqrt(128)

// Static device scratch (allocation-free per harness rules)
__device__ float g_q[(size_t)B_ * LQ_ * D_];        //   8 MB
__device__ float g_k[(size_t)B_ * LKV_ * D_];       //  32 MB
__device__ float g_v[(size_t)B_ * LKV_ * D_];       //  32 MB
__device__ float g_ctx[(size_t)B_ * LQ_ * D_];      //   8 MB
__device__ float g_s[(size_t)B_ * H_ * LQ_ * LKV_]; // 256 MB

// ---------------------------------------------------------------------------
// NT tile GEMM: C[m,n] = scale * sum_k A[m,k]*B[n,k] (+bias[n])
// 128x128 tile, K-step 16, 256 threads, 8x8 per-thread register blocking.
// ---------------------------------------------------------------------------
__device__ __forceinline__ void tile_gemm_nt(
    const float* __restrict__ A, int lda,
    const float* __restrict__ Bm, int ldb,
    float* __restrict__ C, int ldc,
    int m0, int n0, int K, float scale, const float* __restrict__ bias)
{
    __shared__ float As[128][17];
    __shared__ float Bs[128][17];
    const int t = threadIdx.x;
    const int tx = t & 15, ty = t >> 4;

    float acc[8][8];
#pragma unroll
    for (int i = 0; i < 8; i++)
#pragma unroll
        for (int j = 0; j < 8; j++) acc[i][j] = 0.f;

    const float* Ab = A + (size_t)m0 * lda;
    const float* Bb = Bm + (size_t)n0 * ldb;

    for (int k0 = 0; k0 < K; k0 += 16) {
#pragma unroll
        for (int i = 0; i < 8; i++) {
            int lin = t + i * 256;
            int r = lin >> 4, kk = lin & 15;
            As[r][kk] = Ab[(size_t)r * lda + (k0 + kk)];
            Bs[r][kk] = Bb[(size_t)r * ldb + (k0 + kk)];
        }
        __syncthreads();
#pragma unroll
        for (int kk = 0; kk < 16; kk++) {
            float a[8], b[8];
#pragma unroll
            for (int i = 0; i < 4; i++) {
                a[i]     = As[ty * 4 + i][kk];
                a[4 + i] = As[64 + ty * 4 + i][kk];
                b[i]     = Bs[tx * 4 + i][kk];
                b[4 + i] = Bs[64 + tx * 4 + i][kk];
            }
#pragma unroll
            for (int i = 0; i < 8; i++)
#pragma unroll
                for (int j = 0; j < 8; j++) acc[i][j] += a[i] * b[j];
        }
        __syncthreads();
    }

#pragma unroll
    for (int i = 0; i < 8; i++) {
        int m = m0 + ((i < 4) ? (ty * 4 + i) : (64 + ty * 4 + i - 4));
#pragma unroll
        for (int j = 0; j < 8; j++) {
            int n = n0 + ((j < 4) ? (tx * 4 + j) : (64 + tx * 4 + j - 4));
            float vv = acc[i][j] * scale;
            if (bias) vv += bias[n];
            C[(size_t)m * ldc + n] = vv;
        }
    }
}

// Projections: C[M,512] = A[M,512] @ W^T + bias
__global__ __launch_bounds__(256) void proj_kernel(
    const float* __restrict__ A, const float* __restrict__ W,
    const float* __restrict__ bias, float* __restrict__ C)
{
    tile_gemm_nt(A, D_, W, D_, C, D_,
                 blockIdx.y * 128, blockIdx.x * 128, D_, 1.0f, bias);
}

// Scores: S[z, q, kv] = scale * Q_bh[q,:] . K_bh[kv,:]
__global__ __launch_bounds__(256) void scores_kernel(
    const float* __restrict__ q, const float* __restrict__ k, float* __restrict__ s)
{
    int z = blockIdx.z;
    int b = z >> 2, h = z & 3;
    const float* A  = q + (size_t)b * LQ_ * D_ + h * HD_;
    const float* Bm = k + (size_t)b * LKV_ * D_ + h * HD_;
    float* C = s + (size_t)z * LQ_ * LKV_;
    tile_gemm_nt(A, D_, Bm, D_, C, LKV_,
                 blockIdx.y * 128, blockIdx.x * 128, HD_, SCALE_, nullptr);
}

// Row softmax over LKV_, one block per row
__global__ __launch_bounds__(256) void softmax_kernel(float* __restrict__ S)
{
    float* row = S + (size_t)blockIdx.x * LKV_;
    const int t = threadIdx.x;
    __shared__ float red[8];

    float mx = -1e30f;
    for (int i = t; i < LKV_; i += 256) mx = fmaxf(mx, row[i]);
#pragma unroll
    for (int o = 16; o; o >>= 1) mx = fmaxf(mx, __shfl_xor_sync(0xffffffffu, mx, o));
    if ((t & 31) == 0) red[t >> 5] = mx;
    __syncthreads();
    if (t < 32) {
        float v = (t < 8) ? red[t] : -1e30f;
#pragma unroll
        for (int o = 4; o; o >>= 1) v = fmaxf(v, __shfl_xor_sync(0xffffffffu, v, o));
        if (t == 0) red[0] = v;
    }
    __syncthreads();
    mx = red[0];
    __syncthreads();

    float sum = 0.f;
    for (int i = t; i < LKV_; i += 256) {
        float e = __expf(row[i] - mx);
        row[i] = e;
        sum += e;
    }
#pragma unroll
    for (int o = 16; o; o >>= 1) sum += __shfl_xor_sync(0xffffffffu, sum, o);
    if ((t & 31) == 0) red[t >> 5] = sum;
    __syncthreads();
    if (t < 32) {
        float v = (t < 8) ? red[t] : 0.f;
#pragma unroll
        for (int o = 4; o; o >>= 1) v += __shfl_xor_sync(0xffffffffu, v, o);
        if (t == 0) red[0] = v;
    }
    __syncthreads();
    float inv = 1.0f / red[0];
    for (int i = t; i < LKV_; i += 256) row[i] *= inv;
}

// PV: ctx_bh[q, d] = sum_kv P[q,kv] * V_bh[kv,d]   (NN GEMM, N=HD_=128 covered fully)
__global__ __launch_bounds__(256) void av_kernel(
    const float* __restrict__ P, const float* __restrict__ v, float* __restrict__ ctx)
{
    int z = blockIdx.y;
    int b = z >> 2, h = z & 3;
    const float* A  = P + (size_t)z * LQ_ * LKV_;
    const float* Bm = v + (size_t)b * LKV_ * D_ + h * HD_;  // rows LKV_, ld D_
    float* C = ctx + (size_t)b * LQ_ * D_ + h * HD_;        // ld D_
    const int m0 = blockIdx.x * 128;

    __shared__ float As[128][17];
    __shared__ float Bs[16][128];
    const int t = threadIdx.x;
    const int tx = t & 15, ty = t >> 4;

    float acc[8][8];
#pragma unroll
    for (int i = 0; i < 8; i++)
#pragma unroll
        for (int j = 0; j < 8; j++) acc[i][j] = 0.f;

    for (int k0 = 0; k0 < LKV_; k0 += 16) {
#pragma unroll
        for (int i = 0; i < 8; i++) {
            int lin = t + i * 256;
            {
                int r = lin >> 4, kk = lin & 15;
                As[r][kk] = A[(size_t)(m0 + r) * LKV_ + (k0 + kk)];
            }
            {
                int kk = lin >> 7, n = lin & 127;
                Bs[kk][n] = Bm[(size_t)(k0 + kk) * D_ + n];
            }
        }
        __syncthreads();
#pragma unroll
        for (int kk = 0; kk < 16; kk++) {
            float a[8], b[8];
#pragma unroll
            for (int i = 0; i < 4; i++) {
                a[i]     = As[ty * 4 + i][kk];
                a[4 + i] = As[64 + ty * 4 + i][kk];
                b[i]     = Bs[kk][tx * 4 + i];
                b[4 + i] = Bs[kk][64 + tx * 4 + i];
            }
#pragma unroll
            for (int i = 0; i < 8; i++)
#pragma unroll
                for (int j = 0; j < 8; j++) acc[i][j] += a[i] * b[j];
        }
        __syncthreads();
    }

#pragma unroll
    for (int i = 0; i < 8; i++) {
        int m = m0 + ((i < 4) ? (ty * 4 + i) : (64 + ty * 4 + i - 4));
#pragma unroll
        for (int j = 0; j < 8; j++) {
            int n = (j < 4) ? (tx * 4 + j) : (64 + tx * 4 + j - 4);
            C[(size_t)m * D_ + n] = acc[i][j];
        }
    }
}

extern "C" void kernel_launch(void* const* d_in, const int* in_sizes, int n_in,
                              void* d_out, int out_size)
{
    const float* x   = (const float*)d_in[0];
    const float* enc = (const float*)d_in[1];
    const float* Wq  = (const float*)d_in[2];
    const float* Wk  = (const float*)d_in[3];
    const float* Wv  = (const float*)d_in[4];
    const float* bq  = (const float*)d_in[5];
    const float* bk  = (const float*)d_in[6];
    const float* bv  = (const float*)d_in[7];
    const float* Wo  = (const float*)d_in[8];
    const float* bo  = (const float*)d_in[9];
    float* out = (float*)d_out;

    float *q, *k, *v, *ctx, *s;
    cudaGetSymbolAddress((void**)&q,   g_q);
    cudaGetSymbolAddress((void**)&k,   g_k);
    cudaGetSymbolAddress((void**)&v,   g_v);
    cudaGetSymbolAddress((void**)&ctx, g_ctx);
    cudaGetSymbolAddress((void**)&s,   g_s);

    dim3 blk(256);

    // Projections
    proj_kernel<<<dim3(D_ / 128, (B_ * LQ_) / 128),  blk>>>(x,   Wq, bq, q);
    proj_kernel<<<dim3(D_ / 128, (B_ * LKV_) / 128), blk>>>(enc, Wk, bk, k);
    proj_kernel<<<dim3(D_ / 128, (B_ * LKV_) / 128), blk>>>(enc, Wv, bv, v);

    // Attention
    scores_kernel<<<dim3(LKV_ / 128, LQ_ / 128, B_ * H_), blk>>>(q, k, s);
    softmax_kernel<<<B_ * H_ * LQ_, 256>>>(s);
    av_kernel<<<dim3(LQ_ / 128, B_ * H_), blk>>>(s, v, ctx);

    // Output projection
    proj_kernel<<<dim3(D_ / 128, (B_ * LQ_) / 128), blk>>>(ctx, Wo, bo, out);
}

// round 3
// speedup vs baseline: 2.7231x; 2.7231x over previous
#include <cuda_runtime.h>
#include <cuda_bf16.h>
#include <cstdint>
#include <math.h>

#define B_   4
#define LQ_  1024
#define LKV_ 4096
#define D_   512
#define H_   4
#define HD_  128
#define SCALE_ 0.08838834764831845f  // 1/sqrt(128)

// ---------------------------------------------------------------------------
// Helpers
// ---------------------------------------------------------------------------
__device__ __forceinline__ uint32_t smem_u32(const void* p) {
    uint32_t a;
    asm("{ .reg .u64 t; cvta.to.shared.u64 t, %1; cvt.u32.u64 %0, t; }" : "=r"(a) : "l"(p));
    return a;
}
#define SW64(x) ((x) ^ (((x) >> 3) & 0x30))

#define CP_ASYNC16(sa, g) \
    asm volatile("cp.async.cg.shared.global [%0], [%1], 16;" :: "r"(sa), "l"(g))
#define CP_COMMIT() asm volatile("cp.async.commit_group;" ::: "memory")
#define CP_WAIT(n)  asm volatile("cp.async.wait_group %0;" :: "n"(n) : "memory")

__device__ __forceinline__ void ldsm4(uint32_t* r, uint32_t a) {
    asm volatile("ldmatrix.sync.aligned.m8n8.x4.shared.b16 {%0,%1,%2,%3}, [%4];"
                 : "=r"(r[0]), "=r"(r[1]), "=r"(r[2]), "=r"(r[3]) : "r"(a));
}
__device__ __forceinline__ void mma16816(float* c, const uint32_t* a, const uint32_t* b) {
    asm volatile("mma.sync.aligned.m16n8k16.row.col.f32.bf16.bf16.f32 "
                 "{%0,%1,%2,%3}, {%4,%5,%6,%7}, {%8,%9}, {%0,%1,%2,%3};"
                 : "+f"(c[0]), "+f"(c[1]), "+f"(c[2]), "+f"(c[3])
                 : "r"(a[0]), "r"(a[1]), "r"(a[2]), "r"(a[3]), "r"(b[0]), "r"(b[1]));
}

// ---------------------------------------------------------------------------
// Device scratch (allocation-free)
// ---------------------------------------------------------------------------
#define NX  ((size_t)B_ * LQ_ * D_)
#define NE  ((size_t)B_ * LKV_ * D_)
#define NW  ((size_t)D_ * D_)
#define NS  ((size_t)B_ * H_ * LQ_ * LKV_)

__device__ __nv_bfloat16 g_xhi[NX],  g_xlo[NX];
__device__ __nv_bfloat16 g_ehi[NE],  g_elo[NE];
__device__ __nv_bfloat16 g_wqhi[NW], g_wqlo[NW];
__device__ __nv_bfloat16 g_wkhi[NW], g_wklo[NW];
__device__ __nv_bfloat16 g_wvhi[NW], g_wvlo[NW];
__device__ __nv_bfloat16 g_wohi[NW], g_wolo[NW];
__device__ __nv_bfloat16 g_qhi[NX],  g_qlo[NX];
__device__ __nv_bfloat16 g_khi[NE],  g_klo[NE];
__device__ __nv_bfloat16 g_vthi[NE], g_vtlo[NE];   // [b][hd_global=512][lkv]
__device__ __nv_bfloat16 g_phi[NS],  g_plo[NS];
__device__ __nv_bfloat16 g_cthi[NX], g_ctlo[NX];
__device__ float g_s[NS];

// ---------------------------------------------------------------------------
// fp32 -> (hi, lo) bf16 split
// ---------------------------------------------------------------------------
__global__ __launch_bounds__(256) void split_kernel(
    const float* __restrict__ in, __nv_bfloat16* __restrict__ hi,
    __nv_bfloat16* __restrict__ lo, int n4)
{
    int stride = gridDim.x * blockDim.x;
    for (int i = blockIdx.x * blockDim.x + threadIdx.x; i < n4; i += stride) {
        float4 v = ((const float4*)in)[i];
        float f[4] = {v.x, v.y, v.z, v.w};
        __nv_bfloat16 h[4], l[4];
#pragma unroll
        for (int j = 0; j < 4; j++) {
            h[j] = __float2bfloat16(f[j]);
            l[j] = __float2bfloat16(f[j] - __bfloat162float(h[j]));
        }
        ((__nv_bfloat162*)hi)[i * 2]     = __nv_bfloat162(h[0], h[1]);
        ((__nv_bfloat162*)hi)[i * 2 + 1] = __nv_bfloat162(h[2], h[3]);
        ((__nv_bfloat162*)lo)[i * 2]     = __nv_bfloat162(l[0], l[1]);
        ((__nv_bfloat162*)lo)[i * 2 + 1] = __nv_bfloat162(l[2], l[3]);
    }
}

// ---------------------------------------------------------------------------
// Generic NT GEMM, bf16x3 emulated fp32, warp-level mma.sync (HMMA).
// C[m,n] = scale * sum_k A[m,k]*B[n,k] (+bias[n])
// CTA tile 128x128, warp tile 64x32, K-chunk 32, double-buffered cp.async.
// MODE 0: fp32 out; 1: hi/lo bf16 out; 2: hi/lo transposed (V producer).
// ---------------------------------------------------------------------------
#define STG_BYTES 32768   // 4 tiles x 8 KB
#define OFF_AH 0
#define OFF_AL 8192
#define OFF_BH 16384
#define OFF_BL 24576
#define SMEM_SZ (2 * STG_BYTES)

template <int MODE>
__global__ __launch_bounds__(256) void gemm_kernel(
    const __nv_bfloat16* __restrict__ Ah, const __nv_bfloat16* __restrict__ Al, int lda,
    long long sAb, long long sAh_,
    const __nv_bfloat16* __restrict__ Bh, const __nv_bfloat16* __restrict__ Bl, int ldb,
    long long sBb, long long sBh_,
    float* __restrict__ Cf, __nv_bfloat16* __restrict__ Chi, __nv_bfloat16* __restrict__ Clo,
    int ldc, long long sCb, long long sCh_,
    int K, const float* __restrict__ bias, float scale)
{
    extern __shared__ char smem[];
    const uint32_t sb = smem_u32(smem);
    const int t = threadIdx.x, wid = t >> 5, lid = t & 31;
    const int wm = wid & 1, wn = wid >> 1;
    const int zb = blockIdx.z >> 2, zh = blockIdx.z & 3;
    const int m0 = blockIdx.y * 128, n0 = blockIdx.x * 128;

    const size_t offA = (size_t)zb * sAb + (size_t)zh * sAh_;
    const size_t offB = (size_t)zb * sBb + (size_t)zh * sBh_;
    const __nv_bfloat16* Abh = Ah + offA + (size_t)m0 * lda;
    const __nv_bfloat16* Abl = Al + offA + (size_t)m0 * lda;
    const __nv_bfloat16* Bbh = Bh + offB + (size_t)n0 * ldb;
    const __nv_bfloat16* Bbl = Bl + offB + (size_t)n0 * ldb;

    float acc[4][4][4];
#pragma unroll
    for (int i = 0; i < 4; i++)
#pragma unroll
        for (int j = 0; j < 4; j++)
#pragma unroll
            for (int r = 0; r < 4; r++) acc[i][j][r] = 0.f;

    const int nch = K >> 5;

    auto load_stage = [&](int c, int st) {
        const int k0 = c << 5;
        const uint32_t sbase = sb + st * STG_BYTES;
#pragma unroll
        for (int i = 0; i < 2; i++) {
            int idx = t + i * 256;
            int r = idx >> 2, s = idx & 3;
            uint32_t so = SW64(r * 64 + s * 16);
            const __nv_bfloat16* ga = (const __nv_bfloat16*)nullptr;
            size_t oa = (size_t)r * lda + k0 + s * 8;
            size_t ob = (size_t)r * ldb + k0 + s * 8;
            CP_ASYNC16(sbase + OFF_AH + so, Abh + oa);
            CP_ASYNC16(sbase + OFF_AL + so, Abl + oa);
            CP_ASYNC16(sbase + OFF_BH + so, Bbh + ob);
            CP_ASYNC16(sbase + OFF_BL + so, Bbl + ob);
            (void)ga;
        }
        CP_COMMIT();
    };

    load_stage(0, 0);

    for (int c = 0; c < nch; c++) {
        if (c + 1 < nch) { load_stage(c + 1, (c + 1) & 1); CP_WAIT(1); }
        else             { CP_WAIT(0); }
        __syncthreads();

        const uint32_t sbase = sb + (c & 1) * STG_BYTES;
#pragma unroll
        for (int ks = 0; ks < 2; ks++) {
            uint32_t ah[4][4], al[4][4], bh[2][4], bl[2][4];
            // A: rows = wm*64 + im*16 + lane%16; kbyte = ks*32 + (lane>>4)*16
            const int ar = wm * 64 + (lid & 15);
            const int akb = ks * 32 + ((lid >> 4) << 4);
#pragma unroll
            for (int im = 0; im < 4; im++) {
                uint32_t off = SW64((uint32_t)(ar + im * 16) * 64 + akb);
                ldsm4(ah[im], sbase + OFF_AH + off);
                ldsm4(al[im], sbase + OFF_AL + off);
            }
            // B: rows = wn*32 + g*16 + (lane&7) + ((lane>>4)&1)*8; kbyte = ks*32 + ((lane>>3)&1)*16
            const int br = wn * 32 + (lid & 7) + ((lid >> 4) & 1) * 8;
            const int bkb = ks * 32 + ((lid >> 3) & 1) * 16;
#pragma unroll
            for (int g = 0; g < 2; g++) {
                uint32_t off = SW64((uint32_t)(br + g * 16) * 64 + bkb);
                ldsm4(bh[g], sbase + OFF_BH + off);
                ldsm4(bl[g], sbase + OFF_BL + off);
            }
#pragma unroll
            for (int im = 0; im < 4; im++)
#pragma unroll
                for (int in = 0; in < 4; in++) {
                    int g = in >> 1, s2 = (in & 1) * 2;
                    mma16816(acc[im][in], ah[im], &bh[g][s2]);
                    mma16816(acc[im][in], ah[im], &bl[g][s2]);
                    mma16816(acc[im][in], al[im], &bh[g][s2]);
                }
        }
        __syncthreads();
    }

    // Epilogue
    const int group = lid >> 2, tid4 = lid & 3;
    const size_t offC = (size_t)zb * sCb + (size_t)zh * sCh_;

    auto emit = [&](int m, int n, float v) {
        v *= scale;
        if (bias) v += bias[n];
        if (MODE == 0) {
            Cf[offC + (size_t)m * ldc + n] = v;
        } else if (MODE == 1) {
            __nv_bfloat16 h = __float2bfloat16(v);
            __nv_bfloat16 l = __float2bfloat16(v - __bfloat162float(h));
            size_t a = offC + (size_t)m * ldc + n;
            Chi[a] = h; Clo[a] = l;
        } else {
            __nv_bfloat16 h = __float2bfloat16(v);
            __nv_bfloat16 l = __float2bfloat16(v - __bfloat162float(h));
            int bb = m >> 12, kv = m & (LKV_ - 1);
            size_t a = ((size_t)(bb * D_ + n)) * LKV_ + kv;
            Chi[a] = h; Clo[a] = l;
        }
    };

#pragma unroll
    for (int im = 0; im < 4; im++)
#pragma unroll
        for (int in = 0; in < 4; in++) {
            int row = m0 + wm * 64 + im * 16 + group;
            int col = n0 + wn * 32 + in * 8 + tid4 * 2;
            emit(row,     col,     acc[im][in][0]);
            emit(row,     col + 1, acc[im][in][1]);
            emit(row + 8, col,     acc[im][in][2]);
            emit(row + 8, col + 1, acc[im][in][3]);
        }
}

// ---------------------------------------------------------------------------
// Softmax over LKV, one block per row; emits P as hi/lo bf16
// ---------------------------------------------------------------------------
__global__ __launch_bounds__(256) void softmax_kernel(
    const float* __restrict__ S, __nv_bfloat16* __restrict__ Phi,
    __nv_bfloat16* __restrict__ Plo)
{
    const size_t base = (size_t)blockIdx.x * LKV_;
    const float* row = S + base;
    const int t = threadIdx.x;
    __shared__ float red[8];

    float x[16];
#pragma unroll
    for (int p = 0; p < 16; p++) x[p] = row[t + p * 256];

    float mx = -1e30f;
#pragma unroll
    for (int p = 0; p < 16; p++) mx = fmaxf(mx, x[p]);
#pragma unroll
    for (int o = 16; o; o >>= 1) mx = fmaxf(mx, __shfl_xor_sync(0xffffffffu, mx, o));
    if ((t & 31) == 0) red[t >> 5] = mx;
    __syncthreads();
    if (t < 32) {
        float v = (t < 8) ? red[t] : -1e30f;
#pragma unroll
        for (int o = 4; o; o >>= 1) v = fmaxf(v, __shfl_xor_sync(0xffffffffu, v, o));
        if (t == 0) red[0] = v;
    }
    __syncthreads();
    mx = red[0];
    __syncthreads();

    float sum = 0.f;
#pragma unroll
    for (int p = 0; p < 16; p++) { x[p] = __expf(x[p] - mx); sum += x[p]; }
#pragma unroll
    for (int o = 16; o; o >>= 1) sum += __shfl_xor_sync(0xffffffffu, sum, o);
    if ((t & 31) == 0) red[t >> 5] = sum;
    __syncthreads();
    if (t < 32) {
        float v = (t < 8) ? red[t] : 0.f;
#pragma unroll
        for (int o = 4; o; o >>= 1) v += __shfl_xor_sync(0xffffffffu, v, o);
        if (t == 0) red[0] = v;
    }
    __syncthreads();
    const float inv = 1.0f / red[0];

#pragma unroll
    for (int p = 0; p < 16; p++) {
        float v = x[p] * inv;
        __nv_bfloat16 h = __float2bfloat16(v);
        __nv_bfloat16 l = __float2bfloat16(v - __bfloat162float(h));
        Phi[base + t + p * 256] = h;
        Plo[base + t + p * 256] = l;
    }
}

// ---------------------------------------------------------------------------
extern "C" void kernel_launch(void* const* d_in, const int* in_sizes, int n_in,
                              void* d_out, int out_size)
{
    const float* x   = (const float*)d_in[0];
    const float* enc = (const float*)d_in[1];
    const float* Wq  = (const float*)d_in[2];
    const float* Wk  = (const float*)d_in[3];
    const float* Wv  = (const float*)d_in[4];
    const float* bq  = (const float*)d_in[5];
    const float* bk  = (const float*)d_in[6];
    const float* bv  = (const float*)d_in[7];
    const float* Wo  = (const float*)d_in[8];
    const float* bo  = (const float*)d_in[9];
    float* out = (float*)d_out;

    __nv_bfloat16 *xhi, *xlo, *ehi, *elo, *wqh, *wql, *wkh, *wkl, *wvh, *wvl, *woh, *wol;
    __nv_bfloat16 *qhi, *qlo, *khi, *klo, *vth, *vtl, *phi, *plo, *cth, *ctl;
    float* S;
    cudaGetSymbolAddress((void**)&xhi, g_xhi);  cudaGetSymbolAddress((void**)&xlo, g_xlo);
    cudaGetSymbolAddress((void**)&ehi, g_ehi);  cudaGetSymbolAddress((void**)&elo, g_elo);
    cudaGetSymbolAddress((void**)&wqh, g_wqhi); cudaGetSymbolAddress((void**)&wql, g_wqlo);
    cudaGetSymbolAddress((void**)&wkh, g_wkhi); cudaGetSymbolAddress((void**)&wkl, g_wklo);
    cudaGetSymbolAddress((void**)&wvh, g_wvhi); cudaGetSymbolAddress((void**)&wvl, g_wvlo);
    cudaGetSymbolAddress((void**)&woh, g_wohi); cudaGetSymbolAddress((void**)&wol, g_wolo);
    cudaGetSymbolAddress((void**)&qhi, g_qhi);  cudaGetSymbolAddress((void**)&qlo, g_qlo);
    cudaGetSymbolAddress((void**)&khi, g_khi);  cudaGetSymbolAddress((void**)&klo, g_klo);
    cudaGetSymbolAddress((void**)&vth, g_vthi); cudaGetSymbolAddress((void**)&vtl, g_vtlo);
    cudaGetSymbolAddress((void**)&phi, g_phi);  cudaGetSymbolAddress((void**)&plo, g_plo);
    cudaGetSymbolAddress((void**)&cth, g_cthi); cudaGetSymbolAddress((void**)&ctl, g_ctlo);
    cudaGetSymbolAddress((void**)&S,   g_s);

    cudaFuncSetAttribute(gemm_kernel<0>, cudaFuncAttributeMaxDynamicSharedMemorySize, SMEM_SZ);
    cudaFuncSetAttribute(gemm_kernel<1>, cudaFuncAttributeMaxDynamicSharedMemorySize, SMEM_SZ);
    cudaFuncSetAttribute(gemm_kernel<2>, cudaFuncAttributeMaxDynamicSharedMemorySize, SMEM_SZ);

    // 1) split fp32 inputs/weights into hi/lo bf16
    split_kernel<<<1024, 256>>>(x,   xhi, xlo, (int)(NX / 4));
    split_kernel<<<1024, 256>>>(enc, ehi, elo, (int)(NE / 4));
    split_kernel<<<256, 256>>>(Wq, wqh, wql, (int)(NW / 4));
    split_kernel<<<256, 256>>>(Wk, wkh, wkl, (int)(NW / 4));
    split_kernel<<<256, 256>>>(Wv, wvh, wvl, (int)(NW / 4));
    split_kernel<<<256, 256>>>(Wo, woh, wol, (int)(NW / 4));

    // 2) projections (NT: A[m,k] * W[n,k])
    gemm_kernel<1><<<dim3(4, 32, 1), 256, SMEM_SZ>>>(
        xhi, xlo, D_, 0, 0, wqh, wql, D_, 0, 0,
        nullptr, qhi, qlo, D_, 0, 0, D_, bq, 1.0f);
    gemm_kernel<1><<<dim3(4, 128, 1), 256, SMEM_SZ>>>(
        ehi, elo, D_, 0, 0, wkh, wkl, D_, 0, 0,
        nullptr, khi, klo, D_, 0, 0, D_, bk, 1.0f);
    gemm_kernel<2><<<dim3(4, 128, 1), 256, SMEM_SZ>>>(
        ehi, elo, D_, 0, 0, wvh, wvl, D_, 0, 0,
        nullptr, vth, vtl, 0, 0, 0, D_, bv, 1.0f);

    // 3) scores: S[z,q,kv] = scale * Q . K
    gemm_kernel<0><<<dim3(32, 8, 16), 256, SMEM_SZ>>>(
        qhi, qlo, D_, (long long)LQ_ * D_, HD_,
        khi, klo, D_, (long long)LKV_ * D_, HD_,
        S, nullptr, nullptr, LKV_, (long long)H_ * LQ_ * LKV_, (long long)LQ_ * LKV_,
        HD_, nullptr, SCALE_);

    // 4) softmax -> P hi/lo
    softmax_kernel<<<B_ * H_ * LQ_, 256>>>(S, phi, plo);

    // 5) PV: ctx[z,q,d] = P . Vt   (NT via transposed V)
    gemm_kernel<1><<<dim3(1, 8, 16), 256, SMEM_SZ>>>(
        phi, plo, LKV_, (long long)H_ * LQ_ * LKV_, (long long)LQ_ * LKV_,
        vth, vtl, LKV_, (long long)D_ * LKV_, (long long)HD_ * LKV_,
        nullptr, cth, ctl, D_, (long long)LQ_ * D_, HD_,
        LKV_, nullptr, 1.0f);

    // 6) output projection -> fp32 out
    gemm_kernel<0><<<dim3(4, 32, 1), 256, SMEM_SZ>>>(
        cth, ctl, D_, 0, 0, woh, wol, D_, 0, 0,
        out, nullptr, nullptr, D_, 0, 0, D_, bo, 1.0f);
}

// round 4
// speedup vs baseline: 3.5885x; 1.3178x over previous
#include <cuda_runtime.h>
#include <cuda_bf16.h>
#include <cstdint>
#include <math.h>

#define B_   4
#define LQ_  1024
#define LKV_ 4096
#define D_   512
#define H_   4
#define HD_  128
#define SCALE_ 0.08838834764831845f  // 1/sqrt(128)

// ---------------------------------------------------------------------------
// Helpers
// ---------------------------------------------------------------------------
__device__ __forceinline__ uint32_t smem_u32(const void* p) {
    uint32_t a;
    asm("{ .reg .u64 t; cvta.to.shared.u64 t, %1; cvt.u32.u64 %0, t; }" : "=r"(a) : "l"(p));
    return a;
}
#define SW64(x) ((x) ^ (((x) >> 3) & 0x30))

#define CP_ASYNC16(sa, g) \
    asm volatile("cp.async.cg.shared.global [%0], [%1], 16;" :: "r"(sa), "l"(g))
#define CP_COMMIT() asm volatile("cp.async.commit_group;" ::: "memory")
#define CP_WAIT(n)  asm volatile("cp.async.wait_group %0;" :: "n"(n) : "memory")

__device__ __forceinline__ void ldsm4(uint32_t* r, uint32_t a) {
    asm volatile("ldmatrix.sync.aligned.m8n8.x4.shared.b16 {%0,%1,%2,%3}, [%4];"
                 : "=r"(r[0]), "=r"(r[1]), "=r"(r[2]), "=r"(r[3]) : "r"(a));
}
__device__ __forceinline__ void mma16816(float* c, const uint32_t* a, const uint32_t* b) {
    asm volatile("mma.sync.aligned.m16n8k16.row.col.f32.bf16.bf16.f32 "
                 "{%0,%1,%2,%3}, {%4,%5,%6,%7}, {%8,%9}, {%0,%1,%2,%3};"
                 : "+f"(c[0]), "+f"(c[1]), "+f"(c[2]), "+f"(c[3])
                 : "r"(a[0]), "r"(a[1]), "r"(a[2]), "r"(a[3]), "r"(b[0]), "r"(b[1]));
}
__device__ __forceinline__ uint32_t pack_bf16(float a, float b) {
    __nv_bfloat162 v(__float2bfloat16(a), __float2bfloat16(b));
    return *(uint32_t*)&v;
}

// ---------------------------------------------------------------------------
// Device scratch (allocation-free)
// ---------------------------------------------------------------------------
#define NX  ((size_t)B_ * LQ_ * D_)
#define NE  ((size_t)B_ * LKV_ * D_)
#define NW  ((size_t)D_ * D_)

__device__ __nv_bfloat16 g_xhi[NX],  g_xlo[NX];
__device__ __nv_bfloat16 g_ehi[NE],  g_elo[NE];
__device__ __nv_bfloat16 g_wqhi[NW], g_wqlo[NW];
__device__ __nv_bfloat16 g_wkhi[NW], g_wklo[NW];
__device__ __nv_bfloat16 g_wvhi[NW], g_wvlo[NW];
__device__ __nv_bfloat16 g_wohi[NW], g_wolo[NW];
__device__ __nv_bfloat16 g_qhi[NX],  g_qlo[NX];
__device__ __nv_bfloat16 g_khi[NE],  g_klo[NE];
__device__ __nv_bfloat16 g_vthi[NE], g_vtlo[NE];   // [b][h*HD+hd][lkv]
__device__ __nv_bfloat16 g_cthi[NX], g_ctlo[NX];

// ---------------------------------------------------------------------------
// fp32 -> (hi, lo) bf16 split
// ---------------------------------------------------------------------------
__global__ __launch_bounds__(256) void split_kernel(
    const float* __restrict__ in, __nv_bfloat16* __restrict__ hi,
    __nv_bfloat16* __restrict__ lo, int n4)
{
    int stride = gridDim.x * blockDim.x;
    for (int i = blockIdx.x * blockDim.x + threadIdx.x; i < n4; i += stride) {
        float4 v = ((const float4*)in)[i];
        float f[4] = {v.x, v.y, v.z, v.w};
        __nv_bfloat16 h[4], l[4];
#pragma unroll
        for (int j = 0; j < 4; j++) {
            h[j] = __float2bfloat16(f[j]);
            l[j] = __float2bfloat16(f[j] - __bfloat162float(h[j]));
        }
        ((__nv_bfloat162*)hi)[i * 2]     = __nv_bfloat162(h[0], h[1]);
        ((__nv_bfloat162*)hi)[i * 2 + 1] = __nv_bfloat162(h[2], h[3]);
        ((__nv_bfloat162*)lo)[i * 2]     = __nv_bfloat162(l[0], l[1]);
        ((__nv_bfloat162*)lo)[i * 2 + 1] = __nv_bfloat162(l[2], l[3]);
    }
}

// ---------------------------------------------------------------------------
// Generic NT GEMM, bf16x3 emulated fp32 (round-3, proven).
// C[m,n] = scale * (sum_k A[m,k]*B[n,k] + bias[n])
// MODE 0: fp32 out; 1: hi/lo bf16 out; 2: hi/lo transposed (V producer).
// ---------------------------------------------------------------------------
#define STG_BYTES 32768
#define OFF_AH 0
#define OFF_AL 8192
#define OFF_BH 16384
#define OFF_BL 24576
#define GEMM_SMEM (2 * STG_BYTES)

template <int MODE>
__global__ __launch_bounds__(256) void gemm_kernel(
    const __nv_bfloat16* __restrict__ Ah, const __nv_bfloat16* __restrict__ Al, int lda,
    const __nv_bfloat16* __restrict__ Bh, const __nv_bfloat16* __restrict__ Bl, int ldb,
    float* __restrict__ Cf, __nv_bfloat16* __restrict__ Chi, __nv_bfloat16* __restrict__ Clo,
    int ldc, int K, const float* __restrict__ bias, float scale)
{
    extern __shared__ char smem[];
    const uint32_t sb = smem_u32(smem);
    const int t = threadIdx.x, wid = t >> 5, lid = t & 31;
    const int wm = wid & 1, wn = wid >> 1;
    const int m0 = blockIdx.y * 128, n0 = blockIdx.x * 128;

    const __nv_bfloat16* Abh = Ah + (size_t)m0 * lda;
    const __nv_bfloat16* Abl = Al + (size_t)m0 * lda;
    const __nv_bfloat16* Bbh = Bh + (size_t)n0 * ldb;
    const __nv_bfloat16* Bbl = Bl + (size_t)n0 * ldb;

    float acc[4][4][4];
#pragma unroll
    for (int i = 0; i < 4; i++)
#pragma unroll
        for (int j = 0; j < 4; j++)
#pragma unroll
            for (int r = 0; r < 4; r++) acc[i][j][r] = 0.f;

    const int nch = K >> 5;

    auto load_stage = [&](int c, int st) {
        const int k0 = c << 5;
        const uint32_t sbase = sb + st * STG_BYTES;
#pragma unroll
        for (int i = 0; i < 2; i++) {
            int idx = t + i * 256;
            int r = idx >> 2, s = idx & 3;
            uint32_t so = SW64(r * 64 + s * 16);
            size_t oa = (size_t)r * lda + k0 + s * 8;
            size_t ob = (size_t)r * ldb + k0 + s * 8;
            CP_ASYNC16(sbase + OFF_AH + so, Abh + oa);
            CP_ASYNC16(sbase + OFF_AL + so, Abl + oa);
            CP_ASYNC16(sbase + OFF_BH + so, Bbh + ob);
            CP_ASYNC16(sbase + OFF_BL + so, Bbl + ob);
        }
        CP_COMMIT();
    };

    load_stage(0, 0);

    for (int c = 0; c < nch; c++) {
        if (c + 1 < nch) { load_stage(c + 1, (c + 1) & 1); CP_WAIT(1); }
        else             { CP_WAIT(0); }
        __syncthreads();

        const uint32_t sbase = sb + (c & 1) * STG_BYTES;
#pragma unroll
        for (int ks = 0; ks < 2; ks++) {
            uint32_t ah[4][4], al[4][4], bh[2][4], bl[2][4];
            const int ar = wm * 64 + (lid & 15);
            const int akb = ks * 32 + ((lid >> 4) << 4);
#pragma unroll
            for (int im = 0; im < 4; im++) {
                uint32_t off = SW64((uint32_t)(ar + im * 16) * 64 + akb);
                ldsm4(ah[im], sbase + OFF_AH + off);
                ldsm4(al[im], sbase + OFF_AL + off);
            }
            const int br = wn * 32 + (lid & 7) + ((lid >> 4) & 1) * 8;
            const int bkb = ks * 32 + ((lid >> 3) & 1) * 16;
#pragma unroll
            for (int g = 0; g < 2; g++) {
                uint32_t off = SW64((uint32_t)(br + g * 16) * 64 + bkb);
                ldsm4(bh[g], sbase + OFF_BH + off);
                ldsm4(bl[g], sbase + OFF_BL + off);
            }
#pragma unroll
            for (int im = 0; im < 4; im++)
#pragma unroll
                for (int in = 0; in < 4; in++) {
                    int g = in >> 1, s2 = (in & 1) * 2;
                    mma16816(acc[im][in], ah[im], &bh[g][s2]);
                    mma16816(acc[im][in], ah[im], &bl[g][s2]);
                    mma16816(acc[im][in], al[im], &bh[g][s2]);
                }
        }
        __syncthreads();
    }

    const int group = lid >> 2, tid4 = lid & 3;

    auto emit = [&](int m, int n, float v) {
        if (bias) v += bias[n];
        v *= scale;
        if (MODE == 0) {
            Cf[(size_t)m * ldc + n] = v;
        } else if (MODE == 1) {
            __nv_bfloat16 h = __float2bfloat16(v);
            __nv_bfloat16 l = __float2bfloat16(v - __bfloat162float(h));
            size_t a = (size_t)m * ldc + n;
            Chi[a] = h; Clo[a] = l;
        } else {
            __nv_bfloat16 h = __float2bfloat16(v);
            __nv_bfloat16 l = __float2bfloat16(v - __bfloat162float(h));
            int bb = m >> 12, kv = m & (LKV_ - 1);
            size_t a = ((size_t)(bb * D_ + n)) * LKV_ + kv;
            Chi[a] = h; Clo[a] = l;
        }
    };

#pragma unroll
    for (int im = 0; im < 4; im++)
#pragma unroll
        for (int in = 0; in < 4; in++) {
            int row = m0 + wm * 64 + im * 16 + group;
            int col = n0 + wn * 32 + in * 8 + tid4 * 2;
            emit(row,     col,     acc[im][in][0]);
            emit(row,     col + 1, acc[im][in][1]);
            emit(row + 8, col,     acc[im][in][2]);
            emit(row + 8, col + 1, acc[im][in][3]);
        }
}

// ---------------------------------------------------------------------------
// Flash attention: per CTA one (b, h, q-tile of 128). Online softmax,
// P stays in registers (C-frag -> A-frag identity), bf16x3 everywhere.
// Q resident in smem; K/Vt double-buffered in KV-tiles of 64.
// Q is pre-scaled by 1/sqrt(HD) at projection time.
// ---------------------------------------------------------------------------
#define F_QH   0
#define F_QL   32768
#define F_ST   65536
#define F_STSZ 65536
#define F_KH   0
#define F_KL   16384
#define F_VH   32768
#define F_VL   49152
#define FLASH_SMEM (F_ST + 2 * F_STSZ)   // 196608

// swizzled offsets: 256B rows (Q, K), 128B rows (Vt)
#define SWQ(r, g) ((uint32_t)(r) * 256 + ((uint32_t)((g) ^ ((r) & 15)) << 4))
#define SWV(r, g) ((uint32_t)(r) * 128 + ((uint32_t)((g) ^ ((r) & 7)) << 4))

__global__ __launch_bounds__(256) void flash_kernel(
    const __nv_bfloat16* __restrict__ qhi, const __nv_bfloat16* __restrict__ qlo,
    const __nv_bfloat16* __restrict__ khi, const __nv_bfloat16* __restrict__ klo,
    const __nv_bfloat16* __restrict__ vthi, const __nv_bfloat16* __restrict__ vtlo,
    __nv_bfloat16* __restrict__ cthi, __nv_bfloat16* __restrict__ ctlo)
{
    extern __shared__ char smem[];
    const uint32_t sb = smem_u32(smem);
    const int t = threadIdx.x, wid = t >> 5, lid = t & 31;
    const int z = blockIdx.y, zb = z >> 2, zh = z & 3;
    const int q0 = blockIdx.x * 128;

    // --- load Q tile (hi/lo), group 0 ---
#pragma unroll
    for (int i = 0; i < 8; i++) {
        int idx = t + i * 256;
        int r = idx >> 4, g = idx & 15;
        size_t go = ((size_t)(zb * LQ_ + q0 + r)) * D_ + zh * HD_ + g * 8;
        uint32_t so = SWQ(r, g);
        CP_ASYNC16(sb + F_QH + so, qhi + go);
        CP_ASYNC16(sb + F_QL + so, qlo + go);
    }
    CP_COMMIT();

    auto load_kv = [&](int kt2, int st) {
        const int kv0 = kt2 * 64;
        const uint32_t stb = sb + F_ST + st * F_STSZ;
#pragma unroll
        for (int i = 0; i < 4; i++) {
            int idx = t + i * 256;
            int r = idx >> 4, g = idx & 15;
            size_t go = ((size_t)(zb * LKV_ + kv0 + r)) * D_ + zh * HD_ + g * 8;
            uint32_t so = SWQ(r, g);
            CP_ASYNC16(stb + F_KH + so, khi + go);
            CP_ASYNC16(stb + F_KL + so, klo + go);
        }
#pragma unroll
        for (int i = 0; i < 4; i++) {
            int idx = t + i * 256;
            int r = idx >> 3, g = idx & 7;
            size_t go = ((size_t)(zb * D_ + zh * HD_ + r)) * LKV_ + kv0 + g * 8;
            uint32_t so = SWV(r, g);
            CP_ASYNC16(stb + F_VH + so, vthi + go);
            CP_ASYNC16(stb + F_VL + so, vtlo + go);
        }
        CP_COMMIT();
    };

    load_kv(0, 0);

    float oacc[16][4];
#pragma unroll
    for (int i = 0; i < 16; i++)
#pragma unroll
        for (int j = 0; j < 4; j++) oacc[i][j] = 0.f;
    float mr0 = -1e30f, mr1 = -1e30f, l0 = 0.f, l1 = 0.f;

    for (int kt = 0; kt < LKV_ / 64; kt++) {
        if (kt + 1 < LKV_ / 64) { load_kv(kt + 1, (kt + 1) & 1); CP_WAIT(1); }
        else                    { CP_WAIT(0); }
        __syncthreads();
        const uint32_t stb = sb + F_ST + (kt & 1) * F_STSZ;

        // ---- S = Q . K^T  (tile 16 x 64 per warp), 3-pass bf16x3 ----
        float sacc[8][4];
#pragma unroll
        for (int i = 0; i < 8; i++)
#pragma unroll
            for (int j = 0; j < 4; j++) sacc[i][j] = 0.f;

#pragma unroll
        for (int ks = 0; ks < 8; ks++) {
            uint32_t aqh[4], aql[4];
            const int ar = wid * 16 + (lid & 15);
            const int ag = ks * 2 + (lid >> 4);
            ldsm4(aqh, sb + F_QH + SWQ(ar, ag));
            ldsm4(aql, sb + F_QL + SWQ(ar, ag));
#pragma unroll
            for (int jn = 0; jn < 4; jn++) {
                uint32_t bh[4], bl[4];
                const int br = jn * 16 + (lid & 7) + ((lid >> 4) & 1) * 8;
                const int bg = ks * 2 + ((lid >> 3) & 1);
                ldsm4(bh, stb + F_KH + SWQ(br, bg));
                ldsm4(bl, stb + F_KL + SWQ(br, bg));
                mma16816(sacc[2 * jn],     aqh, &bh[0]);
                mma16816(sacc[2 * jn],     aqh, &bl[0]);
                mma16816(sacc[2 * jn],     aql, &bh[0]);
                mma16816(sacc[2 * jn + 1], aqh, &bh[2]);
                mma16816(sacc[2 * jn + 1], aqh, &bl[2]);
                mma16816(sacc[2 * jn + 1], aql, &bh[2]);
            }
        }

        // ---- online softmax (rows r=lid>>2 and r+8 of this warp's q-set) ----
        float tm0 = -1e30f, tm1 = -1e30f;
#pragma unroll
        for (int i = 0; i < 8; i++) {
            tm0 = fmaxf(tm0, fmaxf(sacc[i][0], sacc[i][1]));
            tm1 = fmaxf(tm1, fmaxf(sacc[i][2], sacc[i][3]));
        }
        tm0 = fmaxf(tm0, __shfl_xor_sync(0xffffffffu, tm0, 1));
        tm0 = fmaxf(tm0, __shfl_xor_sync(0xffffffffu, tm0, 2));
        tm1 = fmaxf(tm1, __shfl_xor_sync(0xffffffffu, tm1, 1));
        tm1 = fmaxf(tm1, __shfl_xor_sync(0xffffffffu, tm1, 2));

        const float mn0 = fmaxf(mr0, tm0), mn1 = fmaxf(mr1, tm1);
        const float al0 = __expf(mr0 - mn0), al1 = __expf(mr1 - mn1);
        mr0 = mn0; mr1 = mn1;

        uint32_t phi[8][2], plo[8][2];
        float ps0 = 0.f, ps1 = 0.f;
#pragma unroll
        for (int i = 0; i < 8; i++) {
            float p00 = __expf(sacc[i][0] - mn0);
            float p01 = __expf(sacc[i][1] - mn0);
            float p10 = __expf(sacc[i][2] - mn1);
            float p11 = __expf(sacc[i][3] - mn1);
            ps0 += p00 + p01; ps1 += p10 + p11;
            float h00 = __bfloat162float(__float2bfloat16(p00));
            float h01 = __bfloat162float(__float2bfloat16(p01));
            float h10 = __bfloat162float(__float2bfloat16(p10));
            float h11 = __bfloat162float(__float2bfloat16(p11));
            phi[i][0] = pack_bf16(h00, h01);
            phi[i][1] = pack_bf16(h10, h11);
            plo[i][0] = pack_bf16(p00 - h00, p01 - h01);
            plo[i][1] = pack_bf16(p10 - h10, p11 - h11);
        }
        l0 = l0 * al0 + ps0;
        l1 = l1 * al1 + ps1;
#pragma unroll
        for (int i = 0; i < 16; i++) {
            oacc[i][0] *= al0; oacc[i][1] *= al0;
            oacc[i][2] *= al1; oacc[i][3] *= al1;
        }

        // ---- O += P . V   (P in regs as A-frag; B from Vt smem) ----
#pragma unroll
        for (int pk = 0; pk < 4; pk++) {
            uint32_t ah[4] = {phi[2 * pk][0], phi[2 * pk][1], phi[2 * pk + 1][0], phi[2 * pk + 1][1]};
            uint32_t alr[4] = {plo[2 * pk][0], plo[2 * pk][1], plo[2 * pk + 1][0], plo[2 * pk + 1][1]};
#pragma unroll
            for (int jn = 0; jn < 8; jn++) {
                uint32_t bvh[4], bvl[4];
                const int vr = jn * 16 + (lid & 7) + ((lid >> 4) & 1) * 8;
                const int vg = pk * 2 + ((lid >> 3) & 1);
                ldsm4(bvh, stb + F_VH + SWV(vr, vg));
                ldsm4(bvl, stb + F_VL + SWV(vr, vg));
                mma16816(oacc[2 * jn],     ah,  &bvh[0]);
                mma16816(oacc[2 * jn],     ah,  &bvl[0]);
                mma16816(oacc[2 * jn],     alr, &bvh[0]);
                mma16816(oacc[2 * jn + 1], ah,  &bvh[2]);
                mma16816(oacc[2 * jn + 1], ah,  &bvl[2]);
                mma16816(oacc[2 * jn + 1], alr, &bvh[2]);
            }
        }
        __syncthreads();
    }

    // ---- epilogue: O /= l, split hi/lo, store ctx [B, LQ, D] ----
    l0 += __shfl_xor_sync(0xffffffffu, l0, 1);
    l0 += __shfl_xor_sync(0xffffffffu, l0, 2);
    l1 += __shfl_xor_sync(0xffffffffu, l1, 1);
    l1 += __shfl_xor_sync(0xffffffffu, l1, 2);
    const float inv0 = 1.0f / l0, inv1 = 1.0f / l1;

    const int r = lid >> 2, c2 = (lid & 3) * 2;
    const int qg = q0 + wid * 16 + r;
    const size_t row0 = ((size_t)(zb * LQ_) + qg) * D_ + zh * HD_;
    const size_t row1 = row0 + 8 * D_;
#pragma unroll
    for (int jt = 0; jt < 16; jt++) {
        int col = jt * 8 + c2;
        float v00 = oacc[jt][0] * inv0, v01 = oacc[jt][1] * inv0;
        float v10 = oacc[jt][2] * inv1, v11 = oacc[jt][3] * inv1;
        float h00 = __bfloat162float(__float2bfloat16(v00));
        float h01 = __bfloat162float(__float2bfloat16(v01));
        float h10 = __bfloat162float(__float2bfloat16(v10));
        float h11 = __bfloat162float(__float2bfloat16(v11));
        *(uint32_t*)(cthi + row0 + col) = pack_bf16(h00, h01);
        *(uint32_t*)(cthi + row1 + col) = pack_bf16(h10, h11);
        *(uint32_t*)(ctlo + row0 + col) = pack_bf16(v00 - h00, v01 - h01);
        *(uint32_t*)(ctlo + row1 + col) = pack_bf16(v10 - h10, v11 - h11);
    }
}

// ---------------------------------------------------------------------------
extern "C" void kernel_launch(void* const* d_in, const int* in_sizes, int n_in,
                              void* d_out, int out_size)
{
    const float* x   = (const float*)d_in[0];
    const float* enc = (const float*)d_in[1];
    const float* Wq  = (const float*)d_in[2];
    const float* Wk  = (const float*)d_in[3];
    const float* Wv  = (const float*)d_in[4];
    const float* bq  = (const float*)d_in[5];
    const float* bk  = (const float*)d_in[6];
    const float* bv  = (const float*)d_in[7];
    const float* Wo  = (const float*)d_in[8];
    const float* bo  = (const float*)d_in[9];
    float* out = (float*)d_out;

    __nv_bfloat16 *xhi, *xlo, *ehi, *elo, *wqh, *wql, *wkh, *wkl, *wvh, *wvl, *woh, *wol;
    __nv_bfloat16 *qhi, *qlo, *khi, *klo, *vth, *vtl, *cth, *ctl;
    cudaGetSymbolAddress((void**)&xhi, g_xhi);  cudaGetSymbolAddress((void**)&xlo, g_xlo);
    cudaGetSymbolAddress((void**)&ehi, g_ehi);  cudaGetSymbolAddress((void**)&elo, g_elo);
    cudaGetSymbolAddress((void**)&wqh, g_wqhi); cudaGetSymbolAddress((void**)&wql, g_wqlo);
    cudaGetSymbolAddress((void**)&wkh, g_wkhi); cudaGetSymbolAddress((void**)&wkl, g_wklo);
    cudaGetSymbolAddress((void**)&wvh, g_wvhi); cudaGetSymbolAddress((void**)&wvl, g_wvlo);
    cudaGetSymbolAddress((void**)&woh, g_wohi); cudaGetSymbolAddress((void**)&wol, g_wolo);
    cudaGetSymbolAddress((void**)&qhi, g_qhi);  cudaGetSymbolAddress((void**)&qlo, g_qlo);
    cudaGetSymbolAddress((void**)&khi, g_khi);  cudaGetSymbolAddress((void**)&klo, g_klo);
    cudaGetSymbolAddress((void**)&vth, g_vthi); cudaGetSymbolAddress((void**)&vtl, g_vtlo);
    cudaGetSymbolAddress((void**)&cth, g_cthi); cudaGetSymbolAddress((void**)&ctl, g_ctlo);

    cudaFuncSetAttribute(gemm_kernel<0>, cudaFuncAttributeMaxDynamicSharedMemorySize, GEMM_SMEM);
    cudaFuncSetAttribute(gemm_kernel<1>, cudaFuncAttributeMaxDynamicSharedMemorySize, GEMM_SMEM);
    cudaFuncSetAttribute(gemm_kernel<2>, cudaFuncAttributeMaxDynamicSharedMemorySize, GEMM_SMEM);
    cudaFuncSetAttribute(flash_kernel,   cudaFuncAttributeMaxDynamicSharedMemorySize, FLASH_SMEM);

    // 1) splits
    split_kernel<<<1024, 256>>>(x,   xhi, xlo, (int)(NX / 4));
    split_kernel<<<1024, 256>>>(enc, ehi, elo, (int)(NE / 4));
    split_kernel<<<256, 256>>>(Wq, wqh, wql, (int)(NW / 4));
    split_kernel<<<256, 256>>>(Wk, wkh, wkl, (int)(NW / 4));
    split_kernel<<<256, 256>>>(Wv, wvh, wvl, (int)(NW / 4));
    split_kernel<<<256, 256>>>(Wo, woh, wol, (int)(NW / 4));

    // 2) projections (Q pre-scaled by 1/sqrt(HD))
    gemm_kernel<1><<<dim3(4, 32), 256, GEMM_SMEM>>>(
        xhi, xlo, D_, wqh, wql, D_, nullptr, qhi, qlo, D_, D_, bq, SCALE_);
    gemm_kernel<1><<<dim3(4, 128), 256, GEMM_SMEM>>>(
        ehi, elo, D_, wkh, wkl, D_, nullptr, khi, klo, D_, D_, bk, 1.0f);
    gemm_kernel<2><<<dim3(4, 128), 256, GEMM_SMEM>>>(
        ehi, elo, D_, wvh, wvl, D_, nullptr, vth, vtl, D_, D_, bv, 1.0f);

    // 3) fused flash attention -> ctx hi/lo
    flash_kernel<<<dim3(LQ_ / 128, B_ * H_), 256, FLASH_SMEM>>>(
        qhi, qlo, khi, klo, vth, vtl, cth, ctl);

    // 4) output projection -> fp32 out
    gemm_kernel<0><<<dim3(4, 32), 256, GEMM_SMEM>>>(
        cth, ctl, D_, woh, wol, D_, out, nullptr, nullptr, D_, D_, bo, 1.0f);
}

// round 5
// speedup vs baseline: 4.2201x; 1.1760x over previous
#include <cuda_runtime.h>
#include <cuda_bf16.h>
#include <cstdint>
#include <math.h>

#define B_   4
#define LQ_  1024
#define LKV_ 4096
#define D_   512
#define H_   4
#define HD_  128
#define SCALE_ 0.08838834764831845f  // 1/sqrt(128)

// ---------------------------------------------------------------------------
// Helpers
// ---------------------------------------------------------------------------
__device__ __forceinline__ uint32_t smem_u32(const void* p) {
    uint32_t a;
    asm("{ .reg .u64 t; cvta.to.shared.u64 t, %1; cvt.u32.u64 %0, t; }" : "=r"(a) : "l"(p));
    return a;
}
#define SW64(x) ((x) ^ (((x) >> 3) & 0x30))

#define CP_ASYNC16(sa, g) \
    asm volatile("cp.async.cg.shared.global [%0], [%1], 16;" :: "r"(sa), "l"(g))
#define CP_COMMIT() asm volatile("cp.async.commit_group;" ::: "memory")
#define CP_WAIT(n)  asm volatile("cp.async.wait_group %0;" :: "n"(n) : "memory")

__device__ __forceinline__ void ldsm4(uint32_t* r, uint32_t a) {
    asm volatile("ldmatrix.sync.aligned.m8n8.x4.shared.b16 {%0,%1,%2,%3}, [%4];"
                 : "=r"(r[0]), "=r"(r[1]), "=r"(r[2]), "=r"(r[3]) : "r"(a));
}
__device__ __forceinline__ void mma16816(float* c, const uint32_t* a, const uint32_t* b) {
    asm volatile("mma.sync.aligned.m16n8k16.row.col.f32.bf16.bf16.f32 "
                 "{%0,%1,%2,%3}, {%4,%5,%6,%7}, {%8,%9}, {%0,%1,%2,%3};"
                 : "+f"(c[0]), "+f"(c[1]), "+f"(c[2]), "+f"(c[3])
                 : "r"(a[0]), "r"(a[1]), "r"(a[2]), "r"(a[3]), "r"(b[0]), "r"(b[1]));
}
__device__ __forceinline__ void mma_tf32(float* c, const uint32_t* a, uint32_t b0, uint32_t b1) {
    asm volatile("mma.sync.aligned.m16n8k8.row.col.f32.tf32.tf32.f32 "
                 "{%0,%1,%2,%3}, {%4,%5,%6,%7}, {%8,%9}, {%0,%1,%2,%3};"
                 : "+f"(c[0]), "+f"(c[1]), "+f"(c[2]), "+f"(c[3])
                 : "r"(a[0]), "r"(a[1]), "r"(a[2]), "r"(a[3]), "r"(b0), "r"(b1));
}
__device__ __forceinline__ uint32_t pack_bf16(float a, float b) {
    __nv_bfloat162 v(__float2bfloat16(a), __float2bfloat16(b));
    return *(uint32_t*)&v;
}
__device__ __forceinline__ uint32_t tf32_bits(float x) {
    uint32_t u;
    asm("cvt.rna.tf32.f32 %0, %1;" : "=r"(u) : "f"(x));
    return u;
}
__device__ __forceinline__ float tf32r(float x) { return __uint_as_float(tf32_bits(x)); }

// ---------------------------------------------------------------------------
// Device scratch (allocation-free)
// ---------------------------------------------------------------------------
#define NX  ((size_t)B_ * LQ_ * D_)
#define NE  ((size_t)B_ * LKV_ * D_)
#define NW  ((size_t)D_ * D_)

__device__ __nv_bfloat16 g_xhi[NX],  g_xlo[NX];
__device__ __nv_bfloat16 g_ehi[NE],  g_elo[NE];
__device__ __nv_bfloat16 g_wqhi[NW], g_wqlo[NW];
__device__ __nv_bfloat16 g_wkhi[NW], g_wklo[NW];
__device__ __nv_bfloat16 g_wvhi[NW], g_wvlo[NW];
__device__ __nv_bfloat16 g_wohi[NW], g_wolo[NW];
__device__ float g_qf[NX];    // tf32-rounded fp32
__device__ float g_kf[NE];
__device__ float g_vtf[NE];   // transposed [b][h*HD+d][lkv]
__device__ __nv_bfloat16 g_cthi[NX], g_ctlo[NX];

// ---------------------------------------------------------------------------
// fp32 -> (hi, lo) bf16 split
// ---------------------------------------------------------------------------
__global__ __launch_bounds__(256) void split_kernel(
    const float* __restrict__ in, __nv_bfloat16* __restrict__ hi,
    __nv_bfloat16* __restrict__ lo, int n4)
{
    int stride = gridDim.x * blockDim.x;
    for (int i = blockIdx.x * blockDim.x + threadIdx.x; i < n4; i += stride) {
        float4 v = ((const float4*)in)[i];
        float f[4] = {v.x, v.y, v.z, v.w};
        __nv_bfloat16 h[4], l[4];
#pragma unroll
        for (int j = 0; j < 4; j++) {
            h[j] = __float2bfloat16(f[j]);
            l[j] = __float2bfloat16(f[j] - __bfloat162float(h[j]));
        }
        ((__nv_bfloat162*)hi)[i * 2]     = __nv_bfloat162(h[0], h[1]);
        ((__nv_bfloat162*)hi)[i * 2 + 1] = __nv_bfloat162(h[2], h[3]);
        ((__nv_bfloat162*)lo)[i * 2]     = __nv_bfloat162(l[0], l[1]);
        ((__nv_bfloat162*)lo)[i * 2 + 1] = __nv_bfloat162(l[2], l[3]);
    }
}

// ---------------------------------------------------------------------------
// Generic NT GEMM, bf16x3 emulated fp32 (proven round-3 engine).
// MODE 0: fp32 out (final). MODE 3: tf32-rounded fp32 out (q, k).
// MODE 4: tf32-rounded fp32 out, V-transposed layout (vt).
// ---------------------------------------------------------------------------
#define STG_BYTES 32768
#define OFF_AH 0
#define OFF_AL 8192
#define OFF_BH 16384
#define OFF_BL 24576
#define GEMM_SMEM (2 * STG_BYTES)

template <int MODE>
__global__ __launch_bounds__(256) void gemm_kernel(
    const __nv_bfloat16* __restrict__ Ah, const __nv_bfloat16* __restrict__ Al, int lda,
    const __nv_bfloat16* __restrict__ Bh, const __nv_bfloat16* __restrict__ Bl, int ldb,
    float* __restrict__ Cf, int ldc, int K, const float* __restrict__ bias, float scale)
{
    extern __shared__ char smem[];
    const uint32_t sb = smem_u32(smem);
    const int t = threadIdx.x, wid = t >> 5, lid = t & 31;
    const int wm = wid & 1, wn = wid >> 1;
    const int m0 = blockIdx.y * 128, n0 = blockIdx.x * 128;

    const __nv_bfloat16* Abh = Ah + (size_t)m0 * lda;
    const __nv_bfloat16* Abl = Al + (size_t)m0 * lda;
    const __nv_bfloat16* Bbh = Bh + (size_t)n0 * ldb;
    const __nv_bfloat16* Bbl = Bl + (size_t)n0 * ldb;

    float acc[4][4][4];
#pragma unroll
    for (int i = 0; i < 4; i++)
#pragma unroll
        for (int j = 0; j < 4; j++)
#pragma unroll
            for (int r = 0; r < 4; r++) acc[i][j][r] = 0.f;

    const int nch = K >> 5;

    auto load_stage = [&](int c, int st) {
        const int k0 = c << 5;
        const uint32_t sbase = sb + st * STG_BYTES;
#pragma unroll
        for (int i = 0; i < 2; i++) {
            int idx = t + i * 256;
            int r = idx >> 2, s = idx & 3;
            uint32_t so = SW64(r * 64 + s * 16);
            size_t oa = (size_t)r * lda + k0 + s * 8;
            size_t ob = (size_t)r * ldb + k0 + s * 8;
            CP_ASYNC16(sbase + OFF_AH + so, Abh + oa);
            CP_ASYNC16(sbase + OFF_AL + so, Abl + oa);
            CP_ASYNC16(sbase + OFF_BH + so, Bbh + ob);
            CP_ASYNC16(sbase + OFF_BL + so, Bbl + ob);
        }
        CP_COMMIT();
    };

    load_stage(0, 0);

    for (int c = 0; c < nch; c++) {
        if (c + 1 < nch) { load_stage(c + 1, (c + 1) & 1); CP_WAIT(1); }
        else             { CP_WAIT(0); }
        __syncthreads();

        const uint32_t sbase = sb + (c & 1) * STG_BYTES;
#pragma unroll
        for (int ks = 0; ks < 2; ks++) {
            uint32_t ah[4][4], al[4][4], bh[2][4], bl[2][4];
            const int ar = wm * 64 + (lid & 15);
            const int akb = ks * 32 + ((lid >> 4) << 4);
#pragma unroll
            for (int im = 0; im < 4; im++) {
                uint32_t off = SW64((uint32_t)(ar + im * 16) * 64 + akb);
                ldsm4(ah[im], sbase + OFF_AH + off);
                ldsm4(al[im], sbase + OFF_AL + off);
            }
            const int br = wn * 32 + (lid & 7) + ((lid >> 4) & 1) * 8;
            const int bkb = ks * 32 + ((lid >> 3) & 1) * 16;
#pragma unroll
            for (int g = 0; g < 2; g++) {
                uint32_t off = SW64((uint32_t)(br + g * 16) * 64 + bkb);
                ldsm4(bh[g], sbase + OFF_BH + off);
                ldsm4(bl[g], sbase + OFF_BL + off);
            }
#pragma unroll
            for (int im = 0; im < 4; im++)
#pragma unroll
                for (int in = 0; in < 4; in++) {
                    int g = in >> 1, s2 = (in & 1) * 2;
                    mma16816(acc[im][in], ah[im], &bh[g][s2]);
                    mma16816(acc[im][in], ah[im], &bl[g][s2]);
                    mma16816(acc[im][in], al[im], &bh[g][s2]);
                }
        }
        __syncthreads();
    }

    const int group = lid >> 2, tid4 = lid & 3;

    auto emit = [&](int m, int n, float v) {
        if (bias) v += bias[n];
        v *= scale;
        if (MODE == 0) {
            Cf[(size_t)m * ldc + n] = v;
        } else if (MODE == 3) {
            Cf[(size_t)m * ldc + n] = tf32r(v);
        } else {  // MODE 4: vt transposed
            int bb = m >> 12, kv = m & (LKV_ - 1);
            Cf[((size_t)(bb * D_ + n)) * LKV_ + kv] = tf32r(v);
        }
    };

#pragma unroll
    for (int im = 0; im < 4; im++)
#pragma unroll
        for (int in = 0; in < 4; in++) {
            int row = m0 + wm * 64 + im * 16 + group;
            int col = n0 + wn * 32 + in * 8 + tid4 * 2;
            emit(row,     col,     acc[im][in][0]);
            emit(row,     col + 1, acc[im][in][1]);
            emit(row + 8, col,     acc[im][in][2]);
            emit(row + 8, col + 1, acc[im][in][3]);
        }
}

// ---------------------------------------------------------------------------
// Flash attention, single-pass tf32 (m16n8k8). Online softmax; P re-fragmented
// from C-frags to tf32 A-frags via intra-quad shuffles.
// q/k/vt are fp32 pre-rounded to tf32 (rna). Q pre-scaled by 1/sqrt(HD).
// ---------------------------------------------------------------------------
#define F_Q    0
#define F_ST   65536
#define F_STSZ 65536
#define F_K    0
#define F_V    32768
#define FLASH_SMEM (F_ST + 2 * F_STSZ)   // 196608

// fp32 tiles: rows of 512B (Q,K: 128 floats) / 256B (Vt: 64 floats), 16B granules
#define SWF512(r, g) ((uint32_t)(r) * 512 + ((uint32_t)((g) ^ ((r) & 7)) << 4))
#define SWF256(r, g) ((uint32_t)(r) * 256 + ((uint32_t)((g) ^ ((r) & 7)) << 4))

__global__ __launch_bounds__(256) void flash_kernel(
    const float* __restrict__ q, const float* __restrict__ k,
    const float* __restrict__ vt,
    __nv_bfloat16* __restrict__ cthi, __nv_bfloat16* __restrict__ ctlo)
{
    extern __shared__ char smem[];
    const uint32_t sb = smem_u32(smem);
    const int t = threadIdx.x, wid = t >> 5, lid = t & 31;
    const int z = blockIdx.y, zb = z >> 2, zh = z & 3;
    const int q0 = blockIdx.x * 128;

    // --- load Q tile (fp32), commit group 0 ---
#pragma unroll
    for (int i = 0; i < 16; i++) {
        int idx = t + i * 256;
        int r = idx >> 5, g = idx & 31;
        const float* gp = q + ((size_t)(zb * LQ_ + q0 + r)) * D_ + zh * HD_ + g * 4;
        CP_ASYNC16(sb + F_Q + SWF512(r, g), gp);
    }
    CP_COMMIT();

    auto load_kv = [&](int kt2, int st) {
        const int kv0 = kt2 * 64;
        const uint32_t stb = sb + F_ST + st * F_STSZ;
#pragma unroll
        for (int i = 0; i < 8; i++) {
            int idx = t + i * 256;
            int r = idx >> 5, g = idx & 31;
            const float* gp = k + ((size_t)(zb * LKV_ + kv0 + r)) * D_ + zh * HD_ + g * 4;
            CP_ASYNC16(stb + F_K + SWF512(r, g), gp);
        }
#pragma unroll
        for (int i = 0; i < 8; i++) {
            int idx = t + i * 256;
            int r = idx >> 4, g = idx & 15;
            const float* gp = vt + ((size_t)(zb * D_ + zh * HD_ + r)) * LKV_ + kv0 + g * 4;
            CP_ASYNC16(stb + F_V + SWF256(r, g), gp);
        }
        CP_COMMIT();
    };

    load_kv(0, 0);

    float oacc[16][4];
#pragma unroll
    for (int i = 0; i < 16; i++)
#pragma unroll
        for (int j = 0; j < 4; j++) oacc[i][j] = 0.f;
    float mr0 = -1e30f, mr1 = -1e30f, l0 = 0.f, l1 = 0.f;

    for (int kt = 0; kt < LKV_ / 64; kt++) {
        if (kt + 1 < LKV_ / 64) { load_kv(kt + 1, (kt + 1) & 1); CP_WAIT(1); }
        else                    { CP_WAIT(0); }
        __syncthreads();
        const uint32_t stb = sb + F_ST + (kt & 1) * F_STSZ;

        // ---- S = Q . K^T  (16 x 64 per warp, K=128, tf32 k8 steps) ----
        float sacc[8][4];
#pragma unroll
        for (int i = 0; i < 8; i++)
#pragma unroll
            for (int j = 0; j < 4; j++) sacc[i][j] = 0.f;

#pragma unroll
        for (int ks = 0; ks < 16; ks++) {
            uint32_t aq[4];
            ldsm4(aq, sb + F_Q + SWF512(wid * 16 + (lid & 15), ks * 2 + (lid >> 4)));
#pragma unroll
            for (int jn = 0; jn < 4; jn++) {
                uint32_t bk4[4];
                ldsm4(bk4, stb + F_K + SWF512(jn * 16 + (lid & 15), ks * 2 + (lid >> 4)));
                mma_tf32(sacc[2 * jn],     aq, bk4[0], bk4[2]);
                mma_tf32(sacc[2 * jn + 1], aq, bk4[1], bk4[3]);
            }
        }

        // ---- online softmax (rows lid>>2 and +8) ----
        float tm0 = -1e30f, tm1 = -1e30f;
#pragma unroll
        for (int i = 0; i < 8; i++) {
            tm0 = fmaxf(tm0, fmaxf(sacc[i][0], sacc[i][1]));
            tm1 = fmaxf(tm1, fmaxf(sacc[i][2], sacc[i][3]));
        }
        tm0 = fmaxf(tm0, __shfl_xor_sync(0xffffffffu, tm0, 1));
        tm0 = fmaxf(tm0, __shfl_xor_sync(0xffffffffu, tm0, 2));
        tm1 = fmaxf(tm1, __shfl_xor_sync(0xffffffffu, tm1, 1));
        tm1 = fmaxf(tm1, __shfl_xor_sync(0xffffffffu, tm1, 2));

        const float mn0 = fmaxf(mr0, tm0), mn1 = fmaxf(mr1, tm1);
        const float al0 = __expf(mr0 - mn0), al1 = __expf(mr1 - mn1);
        mr0 = mn0; mr1 = mn1;

        float ps0 = 0.f, ps1 = 0.f;
#pragma unroll
        for (int i = 0; i < 8; i++) {
            sacc[i][0] = __expf(sacc[i][0] - mn0);
            sacc[i][1] = __expf(sacc[i][1] - mn0);
            sacc[i][2] = __expf(sacc[i][2] - mn1);
            sacc[i][3] = __expf(sacc[i][3] - mn1);
            ps0 += sacc[i][0] + sacc[i][1];
            ps1 += sacc[i][2] + sacc[i][3];
        }
        l0 = l0 * al0 + ps0;
        l1 = l1 * al1 + ps1;
#pragma unroll
        for (int i = 0; i < 16; i++) {
            oacc[i][0] *= al0; oacc[i][1] *= al0;
            oacc[i][2] *= al1; oacc[i][3] *= al1;
        }

        // ---- O += P . V  (P C-frag -> tf32 A-frag via intra-quad shfl) ----
        const int t4 = lid & 3;
        const int srcLo = (lid & ~3) | (t4 >> 1);
        const int srcHi = srcLo + 2;
        const bool odd = t4 & 1;
#pragma unroll
        for (int ks = 0; ks < 8; ks++) {
            float e00 = __shfl_sync(0xffffffffu, sacc[ks][0], srcLo);
            float e01 = __shfl_sync(0xffffffffu, sacc[ks][1], srcLo);
            float e20 = __shfl_sync(0xffffffffu, sacc[ks][2], srcLo);
            float e21 = __shfl_sync(0xffffffffu, sacc[ks][3], srcLo);
            float f00 = __shfl_sync(0xffffffffu, sacc[ks][0], srcHi);
            float f01 = __shfl_sync(0xffffffffu, sacc[ks][1], srcHi);
            float f20 = __shfl_sync(0xffffffffu, sacc[ks][2], srcHi);
            float f21 = __shfl_sync(0xffffffffu, sacc[ks][3], srcHi);
            uint32_t ap[4];
            ap[0] = tf32_bits(odd ? e01 : e00);
            ap[1] = tf32_bits(odd ? e21 : e20);
            ap[2] = tf32_bits(odd ? f01 : f00);
            ap[3] = tf32_bits(odd ? f21 : f20);
#pragma unroll
            for (int jn = 0; jn < 8; jn++) {
                uint32_t bv[4];
                ldsm4(bv, stb + F_V + SWF256(jn * 16 + (lid & 15), ks * 2 + (lid >> 4)));
                mma_tf32(oacc[2 * jn],     ap, bv[0], bv[2]);
                mma_tf32(oacc[2 * jn + 1], ap, bv[1], bv[3]);
            }
        }
        __syncthreads();
    }

    // ---- epilogue: O /= l, split hi/lo, store ctx [B, LQ, D] ----
    l0 += __shfl_xor_sync(0xffffffffu, l0, 1);
    l0 += __shfl_xor_sync(0xffffffffu, l0, 2);
    l1 += __shfl_xor_sync(0xffffffffu, l1, 1);
    l1 += __shfl_xor_sync(0xffffffffu, l1, 2);
    const float inv0 = 1.0f / l0, inv1 = 1.0f / l1;

    const int r = lid >> 2, c2 = (lid & 3) * 2;
    const int qg = q0 + wid * 16 + r;
    const size_t row0 = ((size_t)(zb * LQ_) + qg) * D_ + zh * HD_;
    const size_t row1 = row0 + 8 * D_;
#pragma unroll
    for (int jt = 0; jt < 16; jt++) {
        int col = jt * 8 + c2;
        float v00 = oacc[jt][0] * inv0, v01 = oacc[jt][1] * inv0;
        float v10 = oacc[jt][2] * inv1, v11 = oacc[jt][3] * inv1;
        float h00 = __bfloat162float(__float2bfloat16(v00));
        float h01 = __bfloat162float(__float2bfloat16(v01));
        float h10 = __bfloat162float(__float2bfloat16(v10));
        float h11 = __bfloat162float(__float2bfloat16(v11));
        *(uint32_t*)(cthi + row0 + col) = pack_bf16(h00, h01);
        *(uint32_t*)(cthi + row1 + col) = pack_bf16(h10, h11);
        *(uint32_t*)(ctlo + row0 + col) = pack_bf16(v00 - h00, v01 - h01);
        *(uint32_t*)(ctlo + row1 + col) = pack_bf16(v10 - h10, v11 - h11);
    }
}

// ---------------------------------------------------------------------------
extern "C" void kernel_launch(void* const* d_in, const int* in_sizes, int n_in,
                              void* d_out, int out_size)
{
    const float* x   = (const float*)d_in[0];
    const float* enc = (const float*)d_in[1];
    const float* Wq  = (const float*)d_in[2];
    const float* Wk  = (const float*)d_in[3];
    const float* Wv  = (const float*)d_in[4];
    const float* bq  = (const float*)d_in[5];
    const float* bk  = (const float*)d_in[6];
    const float* bv  = (const float*)d_in[7];
    const float* Wo  = (const float*)d_in[8];
    const float* bo  = (const float*)d_in[9];
    float* out = (float*)d_out;

    __nv_bfloat16 *xhi, *xlo, *ehi, *elo, *wqh, *wql, *wkh, *wkl, *wvh, *wvl, *woh, *wol;
    __nv_bfloat16 *cth, *ctl;
    float *qf, *kf, *vtf;
    cudaGetSymbolAddress((void**)&xhi, g_xhi);  cudaGetSymbolAddress((void**)&xlo, g_xlo);
    cudaGetSymbolAddress((void**)&ehi, g_ehi);  cudaGetSymbolAddress((void**)&elo, g_elo);
    cudaGetSymbolAddress((void**)&wqh, g_wqhi); cudaGetSymbolAddress((void**)&wql, g_wqlo);
    cudaGetSymbolAddress((void**)&wkh, g_wkhi); cudaGetSymbolAddress((void**)&wkl, g_wklo);
    cudaGetSymbolAddress((void**)&wvh, g_wvhi); cudaGetSymbolAddress((void**)&wvl, g_wvlo);
    cudaGetSymbolAddress((void**)&woh, g_wohi); cudaGetSymbolAddress((void**)&wol, g_wolo);
    cudaGetSymbolAddress((void**)&qf,  g_qf);   cudaGetSymbolAddress((void**)&kf,  g_kf);
    cudaGetSymbolAddress((void**)&vtf, g_vtf);
    cudaGetSymbolAddress((void**)&cth, g_cthi); cudaGetSymbolAddress((void**)&ctl, g_ctlo);

    cudaFuncSetAttribute(gemm_kernel<0>, cudaFuncAttributeMaxDynamicSharedMemorySize, GEMM_SMEM);
    cudaFuncSetAttribute(gemm_kernel<3>, cudaFuncAttributeMaxDynamicSharedMemorySize, GEMM_SMEM);
    cudaFuncSetAttribute(gemm_kernel<4>, cudaFuncAttributeMaxDynamicSharedMemorySize, GEMM_SMEM);
    cudaFuncSetAttribute(flash_kernel,   cudaFuncAttributeMaxDynamicSharedMemorySize, FLASH_SMEM);

    // 1) splits (bf16x3 inputs for projections)
    split_kernel<<<1024, 256>>>(x,   xhi, xlo, (int)(NX / 4));
    split_kernel<<<1024, 256>>>(enc, ehi, elo, (int)(NE / 4));
    split_kernel<<<256, 256>>>(Wq, wqh, wql, (int)(NW / 4));
    split_kernel<<<256, 256>>>(Wk, wkh, wkl, (int)(NW / 4));
    split_kernel<<<256, 256>>>(Wv, wvh, wvl, (int)(NW / 4));
    split_kernel<<<256, 256>>>(Wo, woh, wol, (int)(NW / 4));

    // 2) projections, bf16x3 accurate; outputs tf32-rounded fp32.
    //    Q pre-scaled by 1/sqrt(HD).
    gemm_kernel<3><<<dim3(4, 32), 256, GEMM_SMEM>>>(
        xhi, xlo, D_, wqh, wql, D_, qf, D_, D_, bq, SCALE_);
    gemm_kernel<3><<<dim3(4, 128), 256, GEMM_SMEM>>>(
        ehi, elo, D_, wkh, wkl, D_, kf, D_, D_, bk, 1.0f);
    gemm_kernel<4><<<dim3(4, 128), 256, GEMM_SMEM>>>(
        ehi, elo, D_, wvh, wvl, D_, vtf, D_, D_, bv, 1.0f);

    // 3) fused flash attention (tf32 single-pass) -> ctx hi/lo
    flash_kernel<<<dim3(LQ_ / 128, B_ * H_), 256, FLASH_SMEM>>>(
        qf, kf, vtf, cth, ctl);

    // 4) output projection (bf16x3) -> fp32 out
    gemm_kernel<0><<<dim3(4, 32), 256, GEMM_SMEM>>>(
        cth, ctl, D_, woh, wol, D_, out, D_, D_, bo, 1.0f);
}

// round 6
// speedup vs baseline: 5.3074x; 1.2576x over previous
#include <cuda_runtime.h>
#include <cuda_bf16.h>
#include <cuda_fp16.h>
#include <cstdint>
#include <math.h>

#define B_   4
#define LQ_  1024
#define LKV_ 4096
#define D_   512
#define H_   4
#define HD_  128
#define SCALE_ 0.08838834764831845f  // 1/sqrt(128)

// ---------------------------------------------------------------------------
// Helpers
// ---------------------------------------------------------------------------
__device__ __forceinline__ uint32_t smem_u32(const void* p) {
    uint32_t a;
    asm("{ .reg .u64 t; cvta.to.shared.u64 t, %1; cvt.u32.u64 %0, t; }" : "=r"(a) : "l"(p));
    return a;
}
#define SW64(x) ((x) ^ (((x) >> 3) & 0x30))

#define CP_ASYNC16(sa, g) \
    asm volatile("cp.async.cg.shared.global [%0], [%1], 16;" :: "r"(sa), "l"(g))
#define CP_COMMIT() asm volatile("cp.async.commit_group;" ::: "memory")
#define CP_WAIT(n)  asm volatile("cp.async.wait_group %0;" :: "n"(n) : "memory")

__device__ __forceinline__ void ldsm4(uint32_t* r, uint32_t a) {
    asm volatile("ldmatrix.sync.aligned.m8n8.x4.shared.b16 {%0,%1,%2,%3}, [%4];"
                 : "=r"(r[0]), "=r"(r[1]), "=r"(r[2]), "=r"(r[3]) : "r"(a));
}
__device__ __forceinline__ void mma16816(float* c, const uint32_t* a, const uint32_t* b) {
    asm volatile("mma.sync.aligned.m16n8k16.row.col.f32.bf16.bf16.f32 "
                 "{%0,%1,%2,%3}, {%4,%5,%6,%7}, {%8,%9}, {%0,%1,%2,%3};"
                 : "+f"(c[0]), "+f"(c[1]), "+f"(c[2]), "+f"(c[3])
                 : "r"(a[0]), "r"(a[1]), "r"(a[2]), "r"(a[3]), "r"(b[0]), "r"(b[1]));
}
__device__ __forceinline__ void mma_f16(float* c, const uint32_t* a, const uint32_t* b) {
    asm volatile("mma.sync.aligned.m16n8k16.row.col.f32.f16.f16.f32 "
                 "{%0,%1,%2,%3}, {%4,%5,%6,%7}, {%8,%9}, {%0,%1,%2,%3};"
                 : "+f"(c[0]), "+f"(c[1]), "+f"(c[2]), "+f"(c[3])
                 : "r"(a[0]), "r"(a[1]), "r"(a[2]), "r"(a[3]), "r"(b[0]), "r"(b[1]));
}
__device__ __forceinline__ uint32_t pack_bf16(float a, float b) {
    __nv_bfloat162 v(__float2bfloat16(a), __float2bfloat16(b));
    return *(uint32_t*)&v;
}
__device__ __forceinline__ uint32_t pack_h2(float a, float b) {
    __half2 v = __floats2half2_rn(a, b);   // a -> lo (.x), b -> hi (.y)
    return *(uint32_t*)&v;
}

// ---------------------------------------------------------------------------
// Device scratch (allocation-free)
// ---------------------------------------------------------------------------
#define NX  ((size_t)B_ * LQ_ * D_)
#define NE  ((size_t)B_ * LKV_ * D_)
#define NW  ((size_t)D_ * D_)

__device__ __nv_bfloat16 g_xhi[NX],  g_xlo[NX];
__device__ __nv_bfloat16 g_ehi[NE],  g_elo[NE];
__device__ __nv_bfloat16 g_wqhi[NW], g_wqlo[NW];
__device__ __nv_bfloat16 g_wkhi[NW], g_wklo[NW];
__device__ __nv_bfloat16 g_wvhi[NW], g_wvlo[NW];
__device__ __nv_bfloat16 g_wohi[NW], g_wolo[NW];
__device__ __half g_qh[NX];
__device__ __half g_kh[NE];
__device__ __half g_vth[NE];   // transposed [b][h*HD+d][lkv]
__device__ __nv_bfloat16 g_cthi[NX], g_ctlo[NX];

// ---------------------------------------------------------------------------
// fp32 -> (hi, lo) bf16 split
// ---------------------------------------------------------------------------
__global__ __launch_bounds__(256) void split_kernel(
    const float* __restrict__ in, __nv_bfloat16* __restrict__ hi,
    __nv_bfloat16* __restrict__ lo, int n4)
{
    int stride = gridDim.x * blockDim.x;
    for (int i = blockIdx.x * blockDim.x + threadIdx.x; i < n4; i += stride) {
        float4 v = ((const float4*)in)[i];
        float f[4] = {v.x, v.y, v.z, v.w};
        __nv_bfloat16 h[4], l[4];
#pragma unroll
        for (int j = 0; j < 4; j++) {
            h[j] = __float2bfloat16(f[j]);
            l[j] = __float2bfloat16(f[j] - __bfloat162float(h[j]));
        }
        ((__nv_bfloat162*)hi)[i * 2]     = __nv_bfloat162(h[0], h[1]);
        ((__nv_bfloat162*)hi)[i * 2 + 1] = __nv_bfloat162(h[2], h[3]);
        ((__nv_bfloat162*)lo)[i * 2]     = __nv_bfloat162(l[0], l[1]);
        ((__nv_bfloat162*)lo)[i * 2 + 1] = __nv_bfloat162(l[2], l[3]);
    }
}

// ---------------------------------------------------------------------------
// Generic NT GEMM, bf16x3 emulated fp32 (proven engine).
// MODE 0: fp32 out (final). MODE 3: fp16 out (q, k). MODE 4: fp16 transposed (vt).
// ---------------------------------------------------------------------------
#define STG_BYTES 32768
#define OFF_AH 0
#define OFF_AL 8192
#define OFF_BH 16384
#define OFF_BL 24576
#define GEMM_SMEM (2 * STG_BYTES)

template <int MODE>
__global__ __launch_bounds__(256) void gemm_kernel(
    const __nv_bfloat16* __restrict__ Ah, const __nv_bfloat16* __restrict__ Al, int lda,
    const __nv_bfloat16* __restrict__ Bh, const __nv_bfloat16* __restrict__ Bl, int ldb,
    float* __restrict__ Cf, __half* __restrict__ Ch,
    int ldc, int K, const float* __restrict__ bias, float scale)
{
    extern __shared__ char smem[];
    const uint32_t sb = smem_u32(smem);
    const int t = threadIdx.x, wid = t >> 5, lid = t & 31;
    const int wm = wid & 1, wn = wid >> 1;
    const int m0 = blockIdx.y * 128, n0 = blockIdx.x * 128;

    const __nv_bfloat16* Abh = Ah + (size_t)m0 * lda;
    const __nv_bfloat16* Abl = Al + (size_t)m0 * lda;
    const __nv_bfloat16* Bbh = Bh + (size_t)n0 * ldb;
    const __nv_bfloat16* Bbl = Bl + (size_t)n0 * ldb;

    float acc[4][4][4];
#pragma unroll
    for (int i = 0; i < 4; i++)
#pragma unroll
        for (int j = 0; j < 4; j++)
#pragma unroll
            for (int r = 0; r < 4; r++) acc[i][j][r] = 0.f;

    const int nch = K >> 5;

    auto load_stage = [&](int c, int st) {
        const int k0 = c << 5;
        const uint32_t sbase = sb + st * STG_BYTES;
#pragma unroll
        for (int i = 0; i < 2; i++) {
            int idx = t + i * 256;
            int r = idx >> 2, s = idx & 3;
            uint32_t so = SW64(r * 64 + s * 16);
            size_t oa = (size_t)r * lda + k0 + s * 8;
            size_t ob = (size_t)r * ldb + k0 + s * 8;
            CP_ASYNC16(sbase + OFF_AH + so, Abh + oa);
            CP_ASYNC16(sbase + OFF_AL + so, Abl + oa);
            CP_ASYNC16(sbase + OFF_BH + so, Bbh + ob);
            CP_ASYNC16(sbase + OFF_BL + so, Bbl + ob);
        }
        CP_COMMIT();
    };

    load_stage(0, 0);

    for (int c = 0; c < nch; c++) {
        if (c + 1 < nch) { load_stage(c + 1, (c + 1) & 1); CP_WAIT(1); }
        else             { CP_WAIT(0); }
        __syncthreads();

        const uint32_t sbase = sb + (c & 1) * STG_BYTES;
#pragma unroll
        for (int ks = 0; ks < 2; ks++) {
            uint32_t ah[4][4], al[4][4], bh[2][4], bl[2][4];
            const int ar = wm * 64 + (lid & 15);
            const int akb = ks * 32 + ((lid >> 4) << 4);
#pragma unroll
            for (int im = 0; im < 4; im++) {
                uint32_t off = SW64((uint32_t)(ar + im * 16) * 64 + akb);
                ldsm4(ah[im], sbase + OFF_AH + off);
                ldsm4(al[im], sbase + OFF_AL + off);
            }
            const int br = wn * 32 + (lid & 7) + ((lid >> 4) & 1) * 8;
            const int bkb = ks * 32 + ((lid >> 3) & 1) * 16;
#pragma unroll
            for (int g = 0; g < 2; g++) {
                uint32_t off = SW64((uint32_t)(br + g * 16) * 64 + bkb);
                ldsm4(bh[g], sbase + OFF_BH + off);
                ldsm4(bl[g], sbase + OFF_BL + off);
            }
#pragma unroll
            for (int im = 0; im < 4; im++)
#pragma unroll
                for (int in = 0; in < 4; in++) {
                    int g = in >> 1, s2 = (in & 1) * 2;
                    mma16816(acc[im][in], ah[im], &bh[g][s2]);
                    mma16816(acc[im][in], ah[im], &bl[g][s2]);
                    mma16816(acc[im][in], al[im], &bh[g][s2]);
                }
        }
        __syncthreads();
    }

    const int group = lid >> 2, tid4 = lid & 3;

    auto emit = [&](int m, int n, float v) {
        if (bias) v += bias[n];
        v *= scale;
        if (MODE == 0) {
            Cf[(size_t)m * ldc + n] = v;
        } else if (MODE == 3) {
            Ch[(size_t)m * ldc + n] = __float2half_rn(v);
        } else {  // MODE 4: vt transposed
            int bb = m >> 12, kv = m & (LKV_ - 1);
            Ch[((size_t)(bb * D_ + n)) * LKV_ + kv] = __float2half_rn(v);
        }
    };

#pragma unroll
    for (int im = 0; im < 4; im++)
#pragma unroll
        for (int in = 0; in < 4; in++) {
            int row = m0 + wm * 64 + im * 16 + group;
            int col = n0 + wn * 32 + in * 8 + tid4 * 2;
            emit(row,     col,     acc[im][in][0]);
            emit(row,     col + 1, acc[im][in][1]);
            emit(row + 8, col,     acc[im][in][2]);
            emit(row + 8, col + 1, acc[im][in][3]);
        }
}

// ---------------------------------------------------------------------------
// Flash attention, single-pass fp16 (m16n8k16). Online softmax; P C-frags are
// reused directly as fp16 A-frags (layout identity, no shuffles).
// q/k/vt are fp16; Q pre-scaled by 1/sqrt(HD).
// ---------------------------------------------------------------------------
#define F_Q    0
#define F_ST   32768
#define F_STSZ 32768
#define F_K    0
#define F_V    16384
#define FLASH_SMEM (F_ST + 2 * F_STSZ)   // 98304

// fp16 tiles: 256B rows (Q, K: 128 halves), 128B rows (Vt: 64 halves), 16B granules
#define SWQ(r, g) ((uint32_t)(r) * 256 + ((uint32_t)((g) ^ ((r) & 15)) << 4))
#define SWV(r, g) ((uint32_t)(r) * 128 + ((uint32_t)((g) ^ ((r) & 7)) << 4))

__global__ __launch_bounds__(256) void flash_kernel(
    const __half* __restrict__ q, const __half* __restrict__ k,
    const __half* __restrict__ vt,
    __nv_bfloat16* __restrict__ cthi, __nv_bfloat16* __restrict__ ctlo)
{
    extern __shared__ char smem[];
    const uint32_t sb = smem_u32(smem);
    const int t = threadIdx.x, wid = t >> 5, lid = t & 31;
    const int z = blockIdx.y, zb = z >> 2, zh = z & 3;
    const int q0 = blockIdx.x * 128;

    // --- load Q tile (fp16) ---
#pragma unroll
    for (int i = 0; i < 8; i++) {
        int idx = t + i * 256;
        int r = idx >> 4, g = idx & 15;
        const __half* gp = q + ((size_t)(zb * LQ_ + q0 + r)) * D_ + zh * HD_ + g * 8;
        CP_ASYNC16(sb + F_Q + SWQ(r, g), gp);
    }
    CP_COMMIT();

    auto load_kv = [&](int kt2, int st) {
        const int kv0 = kt2 * 64;
        const uint32_t stb = sb + F_ST + st * F_STSZ;
#pragma unroll
        for (int i = 0; i < 4; i++) {
            int idx = t + i * 256;
            int r = idx >> 4, g = idx & 15;
            const __half* gp = k + ((size_t)(zb * LKV_ + kv0 + r)) * D_ + zh * HD_ + g * 8;
            CP_ASYNC16(stb + F_K + SWQ(r, g), gp);
        }
#pragma unroll
        for (int i = 0; i < 4; i++) {
            int idx = t + i * 256;
            int r = idx >> 3, g = idx & 7;
            const __half* gp = vt + ((size_t)(zb * D_ + zh * HD_ + r)) * LKV_ + kv0 + g * 8;
            CP_ASYNC16(stb + F_V + SWV(r, g), gp);
        }
        CP_COMMIT();
    };

    load_kv(0, 0);

    float oacc[16][4];
#pragma unroll
    for (int i = 0; i < 16; i++)
#pragma unroll
        for (int j = 0; j < 4; j++) oacc[i][j] = 0.f;
    float mr0 = -1e30f, mr1 = -1e30f, l0 = 0.f, l1 = 0.f;

    for (int kt = 0; kt < LKV_ / 64; kt++) {
        if (kt + 1 < LKV_ / 64) { load_kv(kt + 1, (kt + 1) & 1); CP_WAIT(1); }
        else                    { CP_WAIT(0); }
        __syncthreads();
        const uint32_t stb = sb + F_ST + (kt & 1) * F_STSZ;

        // ---- S = Q . K^T  (16 x 64 per warp, K=128, fp16 k16 steps) ----
        float sacc[8][4];
#pragma unroll
        for (int i = 0; i < 8; i++)
#pragma unroll
            for (int j = 0; j < 4; j++) sacc[i][j] = 0.f;

#pragma unroll
        for (int ks = 0; ks < 8; ks++) {
            uint32_t aq[4];
            const int ar = wid * 16 + (lid & 15);
            const int ag = ks * 2 + (lid >> 4);
            ldsm4(aq, sb + F_Q + SWQ(ar, ag));
#pragma unroll
            for (int jn = 0; jn < 4; jn++) {
                uint32_t bk4[4];
                const int br = jn * 16 + (lid & 7) + ((lid >> 4) & 1) * 8;
                const int bg = ks * 2 + ((lid >> 3) & 1);
                ldsm4(bk4, stb + F_K + SWQ(br, bg));
                mma_f16(sacc[2 * jn],     aq, &bk4[0]);
                mma_f16(sacc[2 * jn + 1], aq, &bk4[2]);
            }
        }

        // ---- online softmax (rows lid>>2 and +8) ----
        float tm0 = -1e30f, tm1 = -1e30f;
#pragma unroll
        for (int i = 0; i < 8; i++) {
            tm0 = fmaxf(tm0, fmaxf(sacc[i][0], sacc[i][1]));
            tm1 = fmaxf(tm1, fmaxf(sacc[i][2], sacc[i][3]));
        }
        tm0 = fmaxf(tm0, __shfl_xor_sync(0xffffffffu, tm0, 1));
        tm0 = fmaxf(tm0, __shfl_xor_sync(0xffffffffu, tm0, 2));
        tm1 = fmaxf(tm1, __shfl_xor_sync(0xffffffffu, tm1, 1));
        tm1 = fmaxf(tm1, __shfl_xor_sync(0xffffffffu, tm1, 2));

        const float mn0 = fmaxf(mr0, tm0), mn1 = fmaxf(mr1, tm1);
        const float al0 = __expf(mr0 - mn0), al1 = __expf(mr1 - mn1);
        mr0 = mn0; mr1 = mn1;

        uint32_t phi[8][2];
        float ps0 = 0.f, ps1 = 0.f;
#pragma unroll
        for (int i = 0; i < 8; i++) {
            float p00 = __expf(sacc[i][0] - mn0);
            float p01 = __expf(sacc[i][1] - mn0);
            float p10 = __expf(sacc[i][2] - mn1);
            float p11 = __expf(sacc[i][3] - mn1);
            ps0 += p00 + p01; ps1 += p10 + p11;
            phi[i][0] = pack_h2(p00, p01);
            phi[i][1] = pack_h2(p10, p11);
        }
        l0 = l0 * al0 + ps0;
        l1 = l1 * al1 + ps1;
#pragma unroll
        for (int i = 0; i < 16; i++) {
            oacc[i][0] *= al0; oacc[i][1] *= al0;
            oacc[i][2] *= al1; oacc[i][3] *= al1;
        }

        // ---- O += P . V  (P C-frag reused as fp16 A-frag) ----
#pragma unroll
        for (int pk = 0; pk < 4; pk++) {
            uint32_t ap[4] = {phi[2 * pk][0], phi[2 * pk][1],
                              phi[2 * pk + 1][0], phi[2 * pk + 1][1]};
#pragma unroll
            for (int jn = 0; jn < 8; jn++) {
                uint32_t bv[4];
                const int vr = jn * 16 + (lid & 7) + ((lid >> 4) & 1) * 8;
                const int vg = pk * 2 + ((lid >> 3) & 1);
                ldsm4(bv, stb + F_V + SWV(vr, vg));
                mma_f16(oacc[2 * jn],     ap, &bv[0]);
                mma_f16(oacc[2 * jn + 1], ap, &bv[2]);
            }
        }
        __syncthreads();
    }

    // ---- epilogue: O /= l, split hi/lo, store ctx [B, LQ, D] ----
    l0 += __shfl_xor_sync(0xffffffffu, l0, 1);
    l0 += __shfl_xor_sync(0xffffffffu, l0, 2);
    l1 += __shfl_xor_sync(0xffffffffu, l1, 1);
    l1 += __shfl_xor_sync(0xffffffffu, l1, 2);
    const float inv0 = 1.0f / l0, inv1 = 1.0f / l1;

    const int r = lid >> 2, c2 = (lid & 3) * 2;
    const int qg = q0 + wid * 16 + r;
    const size_t row0 = ((size_t)(zb * LQ_) + qg) * D_ + zh * HD_;
    const size_t row1 = row0 + 8 * D_;
#pragma unroll
    for (int jt = 0; jt < 16; jt++) {
        int col = jt * 8 + c2;
        float v00 = oacc[jt][0] * inv0, v01 = oacc[jt][1] * inv0;
        float v10 = oacc[jt][2] * inv1, v11 = oacc[jt][3] * inv1;
        float h00 = __bfloat162float(__float2bfloat16(v00));
        float h01 = __bfloat162float(__float2bfloat16(v01));
        float h10 = __bfloat162float(__float2bfloat16(v10));
        float h11 = __bfloat162float(__float2bfloat16(v11));
        *(uint32_t*)(cthi + row0 + col) = pack_bf16(h00, h01);
        *(uint32_t*)(cthi + row1 + col) = pack_bf16(h10, h11);
        *(uint32_t*)(ctlo + row0 + col) = pack_bf16(v00 - h00, v01 - h01);
        *(uint32_t*)(ctlo + row1 + col) = pack_bf16(v10 - h10, v11 - h11);
    }
}

// ---------------------------------------------------------------------------
extern "C" void kernel_launch(void* const* d_in, const int* in_sizes, int n_in,
                              void* d_out, int out_size)
{
    const float* x   = (const float*)d_in[0];
    const float* enc = (const float*)d_in[1];
    const float* Wq  = (const float*)d_in[2];
    const float* Wk  = (const float*)d_in[3];
    const float* Wv  = (const float*)d_in[4];
    const float* bq  = (const float*)d_in[5];
    const float* bk  = (const float*)d_in[6];
    const float* bv  = (const float*)d_in[7];
    const float* Wo  = (const float*)d_in[8];
    const float* bo  = (const float*)d_in[9];
    float* out = (float*)d_out;

    __nv_bfloat16 *xhi, *xlo, *ehi, *elo, *wqh, *wql, *wkh, *wkl, *wvh, *wvl, *woh, *wol;
    __nv_bfloat16 *cth, *ctl;
    __half *qh, *kh, *vth;
    cudaGetSymbolAddress((void**)&xhi, g_xhi);  cudaGetSymbolAddress((void**)&xlo, g_xlo);
    cudaGetSymbolAddress((void**)&ehi, g_ehi);  cudaGetSymbolAddress((void**)&elo, g_elo);
    cudaGetSymbolAddress((void**)&wqh, g_wqhi); cudaGetSymbolAddress((void**)&wql, g_wqlo);
    cudaGetSymbolAddress((void**)&wkh, g_wkhi); cudaGetSymbolAddress((void**)&wkl, g_wklo);
    cudaGetSymbolAddress((void**)&wvh, g_wvhi); cudaGetSymbolAddress((void**)&wvl, g_wvlo);
    cudaGetSymbolAddress((void**)&woh, g_wohi); cudaGetSymbolAddress((void**)&wol, g_wolo);
    cudaGetSymbolAddress((void**)&qh,  g_qh);   cudaGetSymbolAddress((void**)&kh,  g_kh);
    cudaGetSymbolAddress((void**)&vth, g_vth);
    cudaGetSymbolAddress((void**)&cth, g_cthi); cudaGetSymbolAddress((void**)&ctl, g_ctlo);

    cudaFuncSetAttribute(gemm_kernel<0>, cudaFuncAttributeMaxDynamicSharedMemorySize, GEMM_SMEM);
    cudaFuncSetAttribute(gemm_kernel<3>, cudaFuncAttributeMaxDynamicSharedMemorySize, GEMM_SMEM);
    cudaFuncSetAttribute(gemm_kernel<4>, cudaFuncAttributeMaxDynamicSharedMemorySize, GEMM_SMEM);
    cudaFuncSetAttribute(flash_kernel,   cudaFuncAttributeMaxDynamicSharedMemorySize, FLASH_SMEM);

    // 1) splits (bf16x3 inputs for projections)
    split_kernel<<<1024, 256>>>(x,   xhi, xlo, (int)(NX / 4));
    split_kernel<<<1024, 256>>>(enc, ehi, elo, (int)(NE / 4));
    split_kernel<<<256, 256>>>(Wq, wqh, wql, (int)(NW / 4));
    split_kernel<<<256, 256>>>(Wk, wkh, wkl, (int)(NW / 4));
    split_kernel<<<256, 256>>>(Wv, wvh, wvl, (int)(NW / 4));
    split_kernel<<<256, 256>>>(Wo, woh, wol, (int)(NW / 4));

    // 2) projections, bf16x3 accurate; outputs fp16. Q pre-scaled by 1/sqrt(HD).
    gemm_kernel<3><<<dim3(4, 32), 256, GEMM_SMEM>>>(
        xhi, xlo, D_, wqh, wql, D_, nullptr, qh, D_, D_, bq, SCALE_);
    gemm_kernel<3><<<dim3(4, 128), 256, GEMM_SMEM>>>(
        ehi, elo, D_, wkh, wkl, D_, nullptr, kh, D_, D_, bk, 1.0f);
    gemm_kernel<4><<<dim3(4, 128), 256, GEMM_SMEM>>>(
        ehi, elo, D_, wvh, wvl, D_, nullptr, vth, D_, D_, bv, 1.0f);

    // 3) fused flash attention (fp16 single-pass) -> ctx hi/lo
    flash_kernel<<<dim3(LQ_ / 128, B_ * H_), 256, FLASH_SMEM>>>(
        qh, kh, vth, cth, ctl);

    // 4) output projection (bf16x3) -> fp32 out
    gemm_kernel<0><<<dim3(4, 32), 256, GEMM_SMEM>>>(
        cth, ctl, D_, woh, wol, D_, out, nullptr, D_, D_, bo, 1.0f);
}

// round 7
// speedup vs baseline: 6.2874x; 1.1846x over previous
#include <cuda_runtime.h>
#include <cuda_bf16.h>
#include <cuda_fp16.h>
#include <cstdint>
#include <math.h>

#define B_   4
#define LQ_  1024
#define LKV_ 4096
#define D_   512
#define H_   4
#define HD_  128
#define SCALE_ 0.08838834764831845f  // 1/sqrt(128)

// ---------------------------------------------------------------------------
// Helpers
// ---------------------------------------------------------------------------
__device__ __forceinline__ uint32_t smem_u32(const void* p) {
    uint32_t a;
    asm("{ .reg .u64 t; cvta.to.shared.u64 t, %1; cvt.u32.u64 %0, t; }" : "=r"(a) : "l"(p));
    return a;
}
#define SW64(x) ((x) ^ (((x) >> 3) & 0x30))

#define CP_ASYNC16(sa, g) \
    asm volatile("cp.async.cg.shared.global [%0], [%1], 16;" :: "r"(sa), "l"(g))
#define CP_COMMIT() asm volatile("cp.async.commit_group;" ::: "memory")
#define CP_WAIT(n)  asm volatile("cp.async.wait_group %0;" :: "n"(n) : "memory")

__device__ __forceinline__ void ldsm4(uint32_t* r, uint32_t a) {
    asm volatile("ldmatrix.sync.aligned.m8n8.x4.shared.b16 {%0,%1,%2,%3}, [%4];"
                 : "=r"(r[0]), "=r"(r[1]), "=r"(r[2]), "=r"(r[3]) : "r"(a));
}
__device__ __forceinline__ void mma_f16(float* c, const uint32_t* a, const uint32_t* b) {
    asm volatile("mma.sync.aligned.m16n8k16.row.col.f32.f16.f16.f32 "
                 "{%0,%1,%2,%3}, {%4,%5,%6,%7}, {%8,%9}, {%0,%1,%2,%3};"
                 : "+f"(c[0]), "+f"(c[1]), "+f"(c[2]), "+f"(c[3])
                 : "r"(a[0]), "r"(a[1]), "r"(a[2]), "r"(a[3]), "r"(b[0]), "r"(b[1]));
}
__device__ __forceinline__ uint32_t pack_h2(float a, float b) {
    __half2 v = __floats2half2_rn(a, b);
    return *(uint32_t*)&v;
}

// ---------------------------------------------------------------------------
// Device scratch (allocation-free)
// ---------------------------------------------------------------------------
#define NX  ((size_t)B_ * LQ_ * D_)
#define NE  ((size_t)B_ * LKV_ * D_)
#define NW  ((size_t)D_ * D_)

__device__ __half g_xh[NX];
__device__ __half g_eh[NE];
__device__ __half g_wqhi[NW], g_wqlo[NW];
__device__ __half g_wkhi[NW], g_wklo[NW];
__device__ __half g_wvhi[NW], g_wvlo[NW];
__device__ __half g_wohi[NW], g_wolo[NW];
__device__ __half g_qh[NX];
__device__ __half g_kh[NE];
__device__ __half g_vth[NE];   // transposed [b][h*HD+d][lkv]
__device__ __half g_ct[NX];

// ---------------------------------------------------------------------------
// fp32 -> fp16 convert (inputs) and fp32 -> fp16 hi/lo split (weights)
// ---------------------------------------------------------------------------
__global__ __launch_bounds__(256) void convert_kernel(
    const float* __restrict__ in, __half* __restrict__ outp, int n4)
{
    int stride = gridDim.x * blockDim.x;
    for (int i = blockIdx.x * blockDim.x + threadIdx.x; i < n4; i += stride) {
        float4 v = ((const float4*)in)[i];
        ((uint2*)outp)[i] = make_uint2(pack_h2(v.x, v.y), pack_h2(v.z, v.w));
    }
}

__global__ __launch_bounds__(256) void wsplit_kernel(
    const float* __restrict__ in, __half* __restrict__ hi,
    __half* __restrict__ lo, int n4)
{
    int stride = gridDim.x * blockDim.x;
    for (int i = blockIdx.x * blockDim.x + threadIdx.x; i < n4; i += stride) {
        float4 v = ((const float4*)in)[i];
        float f[4] = {v.x, v.y, v.z, v.w};
        float h[4], l[4];
#pragma unroll
        for (int j = 0; j < 4; j++) {
            h[j] = __half2float(__float2half_rn(f[j]));
            l[j] = f[j] - h[j];
        }
        ((uint2*)hi)[i] = make_uint2(pack_h2(h[0], h[1]), pack_h2(h[2], h[3]));
        ((uint2*)lo)[i] = make_uint2(pack_h2(l[0], l[1]), pack_h2(l[2], l[3]));
    }
}

// ---------------------------------------------------------------------------
// Generic NT GEMM, 2-pass fp16: C = scale * (A_fp16 . (Bhi + Blo)^T + bias)
// A fp16 (single), B fp16 hi/lo. CTA tile 128x128, warp tile 64x32, K-chunk 32.
// MODE 0: fp32 out (final). MODE 3: fp16 out (q, k). MODE 4: fp16 transposed (vt).
// ---------------------------------------------------------------------------
#define STG_BYTES 24576   // A 8K + BH 8K + BL 8K
#define OFF_A  0
#define OFF_BH 8192
#define OFF_BL 16384
#define GEMM_SMEM (2 * STG_BYTES)   // 49152

template <int MODE>
__global__ __launch_bounds__(256) void gemm_kernel(
    const __half* __restrict__ A, int lda,
    const __half* __restrict__ Bh, const __half* __restrict__ Bl, int ldb,
    float* __restrict__ Cf, __half* __restrict__ Ch,
    int ldc, int K, const float* __restrict__ bias, float scale)
{
    extern __shared__ char smem[];
    const uint32_t sb = smem_u32(smem);
    const int t = threadIdx.x, wid = t >> 5, lid = t & 31;
    const int wm = wid & 1, wn = wid >> 1;
    const int m0 = blockIdx.y * 128, n0 = blockIdx.x * 128;

    const __half* Ab  = A  + (size_t)m0 * lda;
    const __half* Bbh = Bh + (size_t)n0 * ldb;
    const __half* Bbl = Bl + (size_t)n0 * ldb;

    float acc[4][4][4];
#pragma unroll
    for (int i = 0; i < 4; i++)
#pragma unroll
        for (int j = 0; j < 4; j++)
#pragma unroll
            for (int r = 0; r < 4; r++) acc[i][j][r] = 0.f;

    const int nch = K >> 5;

    auto load_stage = [&](int c, int st) {
        const int k0 = c << 5;
        const uint32_t sbase = sb + st * STG_BYTES;
#pragma unroll
        for (int i = 0; i < 2; i++) {
            int idx = t + i * 256;
            int r = idx >> 2, s = idx & 3;
            uint32_t so = SW64(r * 64 + s * 16);
            size_t oa = (size_t)r * lda + k0 + s * 8;
            size_t ob = (size_t)r * ldb + k0 + s * 8;
            CP_ASYNC16(sbase + OFF_A + so, Ab + oa);
            CP_ASYNC16(sbase + OFF_BH + so, Bbh + ob);
            CP_ASYNC16(sbase + OFF_BL + so, Bbl + ob);
        }
        CP_COMMIT();
    };

    load_stage(0, 0);

    for (int c = 0; c < nch; c++) {
        if (c + 1 < nch) { load_stage(c + 1, (c + 1) & 1); CP_WAIT(1); }
        else             { CP_WAIT(0); }
        __syncthreads();

        const uint32_t sbase = sb + (c & 1) * STG_BYTES;
#pragma unroll
        for (int ks = 0; ks < 2; ks++) {
            uint32_t ah[4][4], bh[2][4], bl[2][4];
            const int ar = wm * 64 + (lid & 15);
            const int akb = ks * 32 + ((lid >> 4) << 4);
#pragma unroll
            for (int im = 0; im < 4; im++)
                ldsm4(ah[im], sbase + OFF_A + SW64((uint32_t)(ar + im * 16) * 64 + akb));
            const int br = wn * 32 + (lid & 7) + ((lid >> 4) & 1) * 8;
            const int bkb = ks * 32 + ((lid >> 3) & 1) * 16;
#pragma unroll
            for (int g = 0; g < 2; g++) {
                uint32_t off = SW64((uint32_t)(br + g * 16) * 64 + bkb);
                ldsm4(bh[g], sbase + OFF_BH + off);
                ldsm4(bl[g], sbase + OFF_BL + off);
            }
#pragma unroll
            for (int im = 0; im < 4; im++)
#pragma unroll
                for (int in = 0; in < 4; in++) {
                    int g = in >> 1, s2 = (in & 1) * 2;
                    mma_f16(acc[im][in], ah[im], &bh[g][s2]);
                    mma_f16(acc[im][in], ah[im], &bl[g][s2]);
                }
        }
        __syncthreads();
    }

    const int group = lid >> 2, tid4 = lid & 3;

    auto emit = [&](int m, int n, float v) {
        if (bias) v += bias[n];
        v *= scale;
        if (MODE == 0) {
            Cf[(size_t)m * ldc + n] = v;
        } else if (MODE == 3) {
            Ch[(size_t)m * ldc + n] = __float2half_rn(v);
        } else {  // MODE 4: vt transposed
            int bb = m >> 12, kv = m & (LKV_ - 1);
            Ch[((size_t)(bb * D_ + n)) * LKV_ + kv] = __float2half_rn(v);
        }
    };

#pragma unroll
    for (int im = 0; im < 4; im++)
#pragma unroll
        for (int in = 0; in < 4; in++) {
            int row = m0 + wm * 64 + im * 16 + group;
            int col = n0 + wn * 32 + in * 8 + tid4 * 2;
            emit(row,     col,     acc[im][in][0]);
            emit(row,     col + 1, acc[im][in][1]);
            emit(row + 8, col,     acc[im][in][2]);
            emit(row + 8, col + 1, acc[im][in][3]);
        }
}

// ---------------------------------------------------------------------------
// Flash attention, single-pass fp16 (m16n8k16). Online softmax; P C-frags
// reused directly as fp16 A-frags. ctx emitted as plain fp16.
// ---------------------------------------------------------------------------
#define F_Q    0
#define F_ST   32768
#define F_STSZ 32768
#define F_K    0
#define F_V    16384
#define FLASH_SMEM (F_ST + 2 * F_STSZ)   // 98304

#define SWQ(r, g) ((uint32_t)(r) * 256 + ((uint32_t)((g) ^ ((r) & 15)) << 4))
#define SWV(r, g) ((uint32_t)(r) * 128 + ((uint32_t)((g) ^ ((r) & 7)) << 4))

__global__ __launch_bounds__(256) void flash_kernel(
    const __half* __restrict__ q, const __half* __restrict__ k,
    const __half* __restrict__ vt, __half* __restrict__ ct)
{
    extern __shared__ char smem[];
    const uint32_t sb = smem_u32(smem);
    const int t = threadIdx.x, wid = t >> 5, lid = t & 31;
    const int z = blockIdx.y, zb = z >> 2, zh = z & 3;
    const int q0 = blockIdx.x * 128;

#pragma unroll
    for (int i = 0; i < 8; i++) {
        int idx = t + i * 256;
        int r = idx >> 4, g = idx & 15;
        const __half* gp = q + ((size_t)(zb * LQ_ + q0 + r)) * D_ + zh * HD_ + g * 8;
        CP_ASYNC16(sb + F_Q + SWQ(r, g), gp);
    }
    CP_COMMIT();

    auto load_kv = [&](int kt2, int st) {
        const int kv0 = kt2 * 64;
        const uint32_t stb = sb + F_ST + st * F_STSZ;
#pragma unroll
        for (int i = 0; i < 4; i++) {
            int idx = t + i * 256;
            int r = idx >> 4, g = idx & 15;
            const __half* gp = k + ((size_t)(zb * LKV_ + kv0 + r)) * D_ + zh * HD_ + g * 8;
            CP_ASYNC16(stb + F_K + SWQ(r, g), gp);
        }
#pragma unroll
        for (int i = 0; i < 4; i++) {
            int idx = t + i * 256;
            int r = idx >> 3, g = idx & 7;
            const __half* gp = vt + ((size_t)(zb * D_ + zh * HD_ + r)) * LKV_ + kv0 + g * 8;
            CP_ASYNC16(stb + F_V + SWV(r, g), gp);
        }
        CP_COMMIT();
    };

    load_kv(0, 0);

    float oacc[16][4];
#pragma unroll
    for (int i = 0; i < 16; i++)
#pragma unroll
        for (int j = 0; j < 4; j++) oacc[i][j] = 0.f;
    float mr0 = -1e30f, mr1 = -1e30f, l0 = 0.f, l1 = 0.f;

    for (int kt = 0; kt < LKV_ / 64; kt++) {
        if (kt + 1 < LKV_ / 64) { load_kv(kt + 1, (kt + 1) & 1); CP_WAIT(1); }
        else                    { CP_WAIT(0); }
        __syncthreads();
        const uint32_t stb = sb + F_ST + (kt & 1) * F_STSZ;

        float sacc[8][4];
#pragma unroll
        for (int i = 0; i < 8; i++)
#pragma unroll
            for (int j = 0; j < 4; j++) sacc[i][j] = 0.f;

#pragma unroll
        for (int ks = 0; ks < 8; ks++) {
            uint32_t aq[4];
            const int ar = wid * 16 + (lid & 15);
            const int ag = ks * 2 + (lid >> 4);
            ldsm4(aq, sb + F_Q + SWQ(ar, ag));
#pragma unroll
            for (int jn = 0; jn < 4; jn++) {
                uint32_t bk4[4];
                const int br = jn * 16 + (lid & 7) + ((lid >> 4) & 1) * 8;
                const int bg = ks * 2 + ((lid >> 3) & 1);
                ldsm4(bk4, stb + F_K + SWQ(br, bg));
                mma_f16(sacc[2 * jn],     aq, &bk4[0]);
                mma_f16(sacc[2 * jn + 1], aq, &bk4[2]);
            }
        }

        float tm0 = -1e30f, tm1 = -1e30f;
#pragma unroll
        for (int i = 0; i < 8; i++) {
            tm0 = fmaxf(tm0, fmaxf(sacc[i][0], sacc[i][1]));
            tm1 = fmaxf(tm1, fmaxf(sacc[i][2], sacc[i][3]));
        }
        tm0 = fmaxf(tm0, __shfl_xor_sync(0xffffffffu, tm0, 1));
        tm0 = fmaxf(tm0, __shfl_xor_sync(0xffffffffu, tm0, 2));
        tm1 = fmaxf(tm1, __shfl_xor_sync(0xffffffffu, tm1, 1));
        tm1 = fmaxf(tm1, __shfl_xor_sync(0xffffffffu, tm1, 2));

        const float mn0 = fmaxf(mr0, tm0), mn1 = fmaxf(mr1, tm1);
        const float al0 = __expf(mr0 - mn0), al1 = __expf(mr1 - mn1);
        mr0 = mn0; mr1 = mn1;

        uint32_t phi[8][2];
        float ps0 = 0.f, ps1 = 0.f;
#pragma unroll
        for (int i = 0; i < 8; i++) {
            float p00 = __expf(sacc[i][0] - mn0);
            float p01 = __expf(sacc[i][1] - mn0);
            float p10 = __expf(sacc[i][2] - mn1);
            float p11 = __expf(sacc[i][3] - mn1);
            ps0 += p00 + p01; ps1 += p10 + p11;
            phi[i][0] = pack_h2(p00, p01);
            phi[i][1] = pack_h2(p10, p11);
        }
        l0 = l0 * al0 + ps0;
        l1 = l1 * al1 + ps1;
#pragma unroll
        for (int i = 0; i < 16; i++) {
            oacc[i][0] *= al0; oacc[i][1] *= al0;
            oacc[i][2] *= al1; oacc[i][3] *= al1;
        }

#pragma unroll
        for (int pk = 0; pk < 4; pk++) {
            uint32_t ap[4] = {phi[2 * pk][0], phi[2 * pk][1],
                              phi[2 * pk + 1][0], phi[2 * pk + 1][1]};
#pragma unroll
            for (int jn = 0; jn < 8; jn++) {
                uint32_t bv[4];
                const int vr = jn * 16 + (lid & 7) + ((lid >> 4) & 1) * 8;
                const int vg = pk * 2 + ((lid >> 3) & 1);
                ldsm4(bv, stb + F_V + SWV(vr, vg));
                mma_f16(oacc[2 * jn],     ap, &bv[0]);
                mma_f16(oacc[2 * jn + 1], ap, &bv[2]);
            }
        }
        __syncthreads();
    }

    l0 += __shfl_xor_sync(0xffffffffu, l0, 1);
    l0 += __shfl_xor_sync(0xffffffffu, l0, 2);
    l1 += __shfl_xor_sync(0xffffffffu, l1, 1);
    l1 += __shfl_xor_sync(0xffffffffu, l1, 2);
    const float inv0 = 1.0f / l0, inv1 = 1.0f / l1;

    const int r = lid >> 2, c2 = (lid & 3) * 2;
    const int qg = q0 + wid * 16 + r;
    const size_t row0 = ((size_t)(zb * LQ_) + qg) * D_ + zh * HD_;
    const size_t row1 = row0 + 8 * D_;
#pragma unroll
    for (int jt = 0; jt < 16; jt++) {
        int col = jt * 8 + c2;
        *(uint32_t*)(ct + row0 + col) = pack_h2(oacc[jt][0] * inv0, oacc[jt][1] * inv0);
        *(uint32_t*)(ct + row1 + col) = pack_h2(oacc[jt][2] * inv1, oacc[jt][3] * inv1);
    }
}

// ---------------------------------------------------------------------------
extern "C" void kernel_launch(void* const* d_in, const int* in_sizes, int n_in,
                              void* d_out, int out_size)
{
    const float* x   = (const float*)d_in[0];
    const float* enc = (const float*)d_in[1];
    const float* Wq  = (const float*)d_in[2];
    const float* Wk  = (const float*)d_in[3];
    const float* Wv  = (const float*)d_in[4];
    const float* bq  = (const float*)d_in[5];
    const float* bk  = (const float*)d_in[6];
    const float* bv  = (const float*)d_in[7];
    const float* Wo  = (const float*)d_in[8];
    const float* bo  = (const float*)d_in[9];
    float* out = (float*)d_out;

    __half *xh, *eh, *wqh, *wql, *wkh, *wkl, *wvh, *wvl, *woh, *wol;
    __half *qh, *kh, *vth, *ct;
    cudaGetSymbolAddress((void**)&xh,  g_xh);
    cudaGetSymbolAddress((void**)&eh,  g_eh);
    cudaGetSymbolAddress((void**)&wqh, g_wqhi); cudaGetSymbolAddress((void**)&wql, g_wqlo);
    cudaGetSymbolAddress((void**)&wkh, g_wkhi); cudaGetSymbolAddress((void**)&wkl, g_wklo);
    cudaGetSymbolAddress((void**)&wvh, g_wvhi); cudaGetSymbolAddress((void**)&wvl, g_wvlo);
    cudaGetSymbolAddress((void**)&woh, g_wohi); cudaGetSymbolAddress((void**)&wol, g_wolo);
    cudaGetSymbolAddress((void**)&qh,  g_qh);   cudaGetSymbolAddress((void**)&kh,  g_kh);
    cudaGetSymbolAddress((void**)&vth, g_vth);  cudaGetSymbolAddress((void**)&ct,  g_ct);

    cudaFuncSetAttribute(gemm_kernel<0>, cudaFuncAttributeMaxDynamicSharedMemorySize, GEMM_SMEM);
    cudaFuncSetAttribute(gemm_kernel<3>, cudaFuncAttributeMaxDynamicSharedMemorySize, GEMM_SMEM);
    cudaFuncSetAttribute(gemm_kernel<4>, cudaFuncAttributeMaxDynamicSharedMemorySize, GEMM_SMEM);
    cudaFuncSetAttribute(flash_kernel,   cudaFuncAttributeMaxDynamicSharedMemorySize, FLASH_SMEM);

    // 1) converts (inputs) + hi/lo weight splits
    convert_kernel<<<1024, 256>>>(x,   xh, (int)(NX / 4));
    convert_kernel<<<1024, 256>>>(enc, eh, (int)(NE / 4));
    wsplit_kernel<<<256, 256>>>(Wq, wqh, wql, (int)(NW / 4));
    wsplit_kernel<<<256, 256>>>(Wk, wkh, wkl, (int)(NW / 4));
    wsplit_kernel<<<256, 256>>>(Wv, wvh, wvl, (int)(NW / 4));
    wsplit_kernel<<<256, 256>>>(Wo, woh, wol, (int)(NW / 4));

    // 2) projections (2-pass fp16). Q pre-scaled by 1/sqrt(HD).
    gemm_kernel<3><<<dim3(4, 32), 256, GEMM_SMEM>>>(
        xh, D_, wqh, wql, D_, nullptr, qh, D_, D_, bq, SCALE_);
    gemm_kernel<3><<<dim3(4, 128), 256, GEMM_SMEM>>>(
        eh, D_, wkh, wkl, D_, nullptr, kh, D_, D_, bk, 1.0f);
    gemm_kernel<4><<<dim3(4, 128), 256, GEMM_SMEM>>>(
        eh, D_, wvh, wvl, D_, nullptr, vth, D_, D_, bv, 1.0f);

    // 3) fused flash attention (fp16 single-pass) -> ctx fp16
    flash_kernel<<<dim3(LQ_ / 128, B_ * H_), 256, FLASH_SMEM>>>(qh, kh, vth, ct);

    // 4) output projection (2-pass fp16) -> fp32 out
    gemm_kernel<0><<<dim3(4, 32), 256, GEMM_SMEM>>>(
        ct, D_, woh, wol, D_, out, nullptr, D_, D_, bo, 1.0f);
}

// round 8
// speedup vs baseline: 7.8722x; 1.2521x over previous
#include <cuda_runtime.h>
#include <cuda_bf16.h>
#include <cuda_fp16.h>
#include <cstdint>
#include <math.h>

#define B_   4
#define LQ_  1024
#define LKV_ 4096
#define D_   512
#define H_   4
#define HD_  128
#define SCALE_ 0.08838834764831845f      // 1/sqrt(128)
#define LOG2E_ 1.4426950408889634f
#define QSCALE_ (SCALE_ * LOG2E_)        // logits emitted in log2 domain

// ---------------------------------------------------------------------------
// Helpers
// ---------------------------------------------------------------------------
__device__ __forceinline__ uint32_t smem_u32(const void* p) {
    uint32_t a;
    asm("{ .reg .u64 t; cvta.to.shared.u64 t, %1; cvt.u32.u64 %0, t; }" : "=r"(a) : "l"(p));
    return a;
}
#define SW64(x) ((x) ^ (((x) >> 3) & 0x30))

#define CP_ASYNC16(sa, g) \
    asm volatile("cp.async.cg.shared.global [%0], [%1], 16;" :: "r"(sa), "l"(g))
#define CP_COMMIT() asm volatile("cp.async.commit_group;" ::: "memory")
#define CP_WAIT(n)  asm volatile("cp.async.wait_group %0;" :: "n"(n) : "memory")

__device__ __forceinline__ void ldsm4(uint32_t* r, uint32_t a) {
    asm volatile("ldmatrix.sync.aligned.m8n8.x4.shared.b16 {%0,%1,%2,%3}, [%4];"
                 : "=r"(r[0]), "=r"(r[1]), "=r"(r[2]), "=r"(r[3]) : "r"(a));
}
__device__ __forceinline__ void mma_f16(float* c, const uint32_t* a, const uint32_t* b) {
    asm volatile("mma.sync.aligned.m16n8k16.row.col.f32.f16.f16.f32 "
                 "{%0,%1,%2,%3}, {%4,%5,%6,%7}, {%8,%9}, {%0,%1,%2,%3};"
                 : "+f"(c[0]), "+f"(c[1]), "+f"(c[2]), "+f"(c[3])
                 : "r"(a[0]), "r"(a[1]), "r"(a[2]), "r"(a[3]), "r"(b[0]), "r"(b[1]));
}
__device__ __forceinline__ uint32_t pack_h2(float a, float b) {
    __half2 v = __floats2half2_rn(a, b);
    return *(uint32_t*)&v;
}

// ---------------------------------------------------------------------------
// Device scratch (allocation-free)
// ---------------------------------------------------------------------------
#define NX  ((size_t)B_ * LQ_ * D_)
#define NE  ((size_t)B_ * LKV_ * D_)
#define NW  ((size_t)D_ * D_)

__device__ __half g_xh[NX];
__device__ __half g_eh[NE];
__device__ __half g_wqhi[NW], g_wqlo[NW];
__device__ __half g_wk[NW];            // 1-pass: hi only
__device__ __half g_wv[NW];
__device__ __half g_wohi[NW], g_wolo[NW];
__device__ __half g_qh[NX];
__device__ __half g_kh[NE];
__device__ __half g_vth[NE];           // transposed [b][h*HD+d][lkv]
__device__ __half g_ct[NX];

// ---------------------------------------------------------------------------
// fp32 -> fp16 convert, and fp32 -> fp16 hi/lo split (weights)
// ---------------------------------------------------------------------------
__global__ __launch_bounds__(256) void convert_kernel(
    const float* __restrict__ in, __half* __restrict__ outp, int n4)
{
    int stride = gridDim.x * blockDim.x;
    for (int i = blockIdx.x * blockDim.x + threadIdx.x; i < n4; i += stride) {
        float4 v = ((const float4*)in)[i];
        ((uint2*)outp)[i] = make_uint2(pack_h2(v.x, v.y), pack_h2(v.z, v.w));
    }
}

__global__ __launch_bounds__(256) void wsplit_kernel(
    const float* __restrict__ in, __half* __restrict__ hi,
    __half* __restrict__ lo, int n4)
{
    int stride = gridDim.x * blockDim.x;
    for (int i = blockIdx.x * blockDim.x + threadIdx.x; i < n4; i += stride) {
        float4 v = ((const float4*)in)[i];
        float f[4] = {v.x, v.y, v.z, v.w};
        float h[4], l[4];
#pragma unroll
        for (int j = 0; j < 4; j++) {
            h[j] = __half2float(__float2half_rn(f[j]));
            l[j] = f[j] - h[j];
        }
        ((uint2*)hi)[i] = make_uint2(pack_h2(h[0], h[1]), pack_h2(h[2], h[3]));
        ((uint2*)lo)[i] = make_uint2(pack_h2(l[0], l[1]), pack_h2(l[2], l[3]));
    }
}

// ---------------------------------------------------------------------------
// Generic NT GEMM, fp16 tensor-core. PASSES=2: B hi/lo (emulated-accurate);
// PASSES=1: B single. CTA tile 128x128, warp tile 64x32, K-chunk 32, 2-stage.
// MODE 0: fp32 out (final). MODE 3: fp16 out (q, k). MODE 4: fp16 transposed (vt).
// ---------------------------------------------------------------------------
template <int PASSES> struct StageCfg {
    static const int bytes = (PASSES == 2) ? 24576 : 16384;
};
#define OFF_A  0
#define OFF_BH 8192
#define OFF_BL 16384
#define GEMM_SMEM2 49152
#define GEMM_SMEM1 32768

template <int MODE, int PASSES>
__global__ __launch_bounds__(256) void gemm_kernel(
    const __half* __restrict__ A, int lda,
    const __half* __restrict__ Bh, const __half* __restrict__ Bl, int ldb,
    float* __restrict__ Cf, __half* __restrict__ Ch,
    int ldc, int K, const float* __restrict__ bias, float scale)
{
    extern __shared__ char smem[];
    const uint32_t sb = smem_u32(smem);
    const int t = threadIdx.x, wid = t >> 5, lid = t & 31;
    const int wm = wid & 1, wn = wid >> 1;
    const int m0 = blockIdx.y * 128, n0 = blockIdx.x * 128;
    const int STG = StageCfg<PASSES>::bytes;

    const __half* Ab  = A  + (size_t)m0 * lda;
    const __half* Bbh = Bh + (size_t)n0 * ldb;
    const __half* Bbl = (PASSES == 2) ? (Bl + (size_t)n0 * ldb) : nullptr;

    float acc[4][4][4];
#pragma unroll
    for (int i = 0; i < 4; i++)
#pragma unroll
        for (int j = 0; j < 4; j++)
#pragma unroll
            for (int r = 0; r < 4; r++) acc[i][j][r] = 0.f;

    const int nch = K >> 5;

    auto load_stage = [&](int c, int st) {
        const int k0 = c << 5;
        const uint32_t sbase = sb + st * STG;
#pragma unroll
        for (int i = 0; i < 2; i++) {
            int idx = t + i * 256;
            int r = idx >> 2, s = idx & 3;
            uint32_t so = SW64(r * 64 + s * 16);
            size_t oa = (size_t)r * lda + k0 + s * 8;
            size_t ob = (size_t)r * ldb + k0 + s * 8;
            CP_ASYNC16(sbase + OFF_A + so, Ab + oa);
            CP_ASYNC16(sbase + OFF_BH + so, Bbh + ob);
            if (PASSES == 2) CP_ASYNC16(sbase + OFF_BL + so, Bbl + ob);
        }
        CP_COMMIT();
    };

    load_stage(0, 0);

    for (int c = 0; c < nch; c++) {
        if (c + 1 < nch) { load_stage(c + 1, (c + 1) & 1); CP_WAIT(1); }
        else             { CP_WAIT(0); }
        __syncthreads();

        const uint32_t sbase = sb + (c & 1) * STG;
#pragma unroll
        for (int ks = 0; ks < 2; ks++) {
            uint32_t ah[4][4], bh[2][4], bl[2][4];
            const int ar = wm * 64 + (lid & 15);
            const int akb = ks * 32 + ((lid >> 4) << 4);
#pragma unroll
            for (int im = 0; im < 4; im++)
                ldsm4(ah[im], sbase + OFF_A + SW64((uint32_t)(ar + im * 16) * 64 + akb));
            const int br = wn * 32 + (lid & 7) + ((lid >> 4) & 1) * 8;
            const int bkb = ks * 32 + ((lid >> 3) & 1) * 16;
#pragma unroll
            for (int g = 0; g < 2; g++) {
                uint32_t off = SW64((uint32_t)(br + g * 16) * 64 + bkb);
                ldsm4(bh[g], sbase + OFF_BH + off);
                if (PASSES == 2) ldsm4(bl[g], sbase + OFF_BL + off);
            }
#pragma unroll
            for (int im = 0; im < 4; im++)
#pragma unroll
                for (int in = 0; in < 4; in++) {
                    int g = in >> 1, s2 = (in & 1) * 2;
                    mma_f16(acc[im][in], ah[im], &bh[g][s2]);
                    if (PASSES == 2) mma_f16(acc[im][in], ah[im], &bl[g][s2]);
                }
        }
        __syncthreads();
    }

    const int group = lid >> 2, tid4 = lid & 3;

    auto emit = [&](int m, int n, float v) {
        if (bias) v += bias[n];
        v *= scale;
        if (MODE == 0) {
            Cf[(size_t)m * ldc + n] = v;
        } else if (MODE == 3) {
            Ch[(size_t)m * ldc + n] = __float2half_rn(v);
        } else {  // MODE 4: vt transposed
            int bb = m >> 12, kv = m & (LKV_ - 1);
            Ch[((size_t)(bb * D_ + n)) * LKV_ + kv] = __float2half_rn(v);
        }
    };

#pragma unroll
    for (int im = 0; im < 4; im++)
#pragma unroll
        for (int in = 0; in < 4; in++) {
            int row = m0 + wm * 64 + im * 16 + group;
            int col = n0 + wn * 32 + in * 8 + tid4 * 2;
            emit(row,     col,     acc[im][in][0]);
            emit(row,     col + 1, acc[im][in][1]);
            emit(row + 8, col,     acc[im][in][2]);
            emit(row + 8, col + 1, acc[im][in][3]);
        }
}

// ---------------------------------------------------------------------------
// Flash attention, single-pass fp16 (m16n8k16). Logits arrive in log2 domain
// (Q pre-scaled by log2e/sqrt(HD)); softmax uses exp2f. P C-frags reused as
// fp16 A-frags. ctx emitted as plain fp16.
// ---------------------------------------------------------------------------
#define F_Q    0
#define F_ST   32768
#define F_STSZ 32768
#define F_K    0
#define F_V    16384
#define FLASH_SMEM (F_ST + 2 * F_STSZ)   // 98304

#define SWQ(r, g) ((uint32_t)(r) * 256 + ((uint32_t)((g) ^ ((r) & 15)) << 4))
#define SWV(r, g) ((uint32_t)(r) * 128 + ((uint32_t)((g) ^ ((r) & 7)) << 4))

__global__ __launch_bounds__(256) void flash_kernel(
    const __half* __restrict__ q, const __half* __restrict__ k,
    const __half* __restrict__ vt, __half* __restrict__ ct)
{
    extern __shared__ char smem[];
    const uint32_t sb = smem_u32(smem);
    const int t = threadIdx.x, wid = t >> 5, lid = t & 31;
    const int z = blockIdx.y, zb = z >> 2, zh = z & 3;
    const int q0 = blockIdx.x * 128;

#pragma unroll
    for (int i = 0; i < 8; i++) {
        int idx = t + i * 256;
        int r = idx >> 4, g = idx & 15;
        const __half* gp = q + ((size_t)(zb * LQ_ + q0 + r)) * D_ + zh * HD_ + g * 8;
        CP_ASYNC16(sb + F_Q + SWQ(r, g), gp);
    }
    CP_COMMIT();

    auto load_kv = [&](int kt2, int st) {
        const int kv0 = kt2 * 64;
        const uint32_t stb = sb + F_ST + st * F_STSZ;
#pragma unroll
        for (int i = 0; i < 4; i++) {
            int idx = t + i * 256;
            int r = idx >> 4, g = idx & 15;
            const __half* gp = k + ((size_t)(zb * LKV_ + kv0 + r)) * D_ + zh * HD_ + g * 8;
            CP_ASYNC16(stb + F_K + SWQ(r, g), gp);
        }
#pragma unroll
        for (int i = 0; i < 4; i++) {
            int idx = t + i * 256;
            int r = idx >> 3, g = idx & 7;
            const __half* gp = vt + ((size_t)(zb * D_ + zh * HD_ + r)) * LKV_ + kv0 + g * 8;
            CP_ASYNC16(stb + F_V + SWV(r, g), gp);
        }
        CP_COMMIT();
    };

    load_kv(0, 0);

    float oacc[16][4];
#pragma unroll
    for (int i = 0; i < 16; i++)
#pragma unroll
        for (int j = 0; j < 4; j++) oacc[i][j] = 0.f;
    float mr0 = -1e30f, mr1 = -1e30f, l0 = 0.f, l1 = 0.f;

    for (int kt = 0; kt < LKV_ / 64; kt++) {
        if (kt + 1 < LKV_ / 64) { load_kv(kt + 1, (kt + 1) & 1); CP_WAIT(1); }
        else                    { CP_WAIT(0); }
        __syncthreads();
        const uint32_t stb = sb + F_ST + (kt & 1) * F_STSZ;

        float sacc[8][4];
#pragma unroll
        for (int i = 0; i < 8; i++)
#pragma unroll
            for (int j = 0; j < 4; j++) sacc[i][j] = 0.f;

#pragma unroll
        for (int ks = 0; ks < 8; ks++) {
            uint32_t aq[4];
            const int ar = wid * 16 + (lid & 15);
            const int ag = ks * 2 + (lid >> 4);
            ldsm4(aq, sb + F_Q + SWQ(ar, ag));
#pragma unroll
            for (int jn = 0; jn < 4; jn++) {
                uint32_t bk4[4];
                const int br = jn * 16 + (lid & 7) + ((lid >> 4) & 1) * 8;
                const int bg = ks * 2 + ((lid >> 3) & 1);
                ldsm4(bk4, stb + F_K + SWQ(br, bg));
                mma_f16(sacc[2 * jn],     aq, &bk4[0]);
                mma_f16(sacc[2 * jn + 1], aq, &bk4[2]);
            }
        }

        float tm0 = -1e30f, tm1 = -1e30f;
#pragma unroll
        for (int i = 0; i < 8; i++) {
            tm0 = fmaxf(tm0, fmaxf(sacc[i][0], sacc[i][1]));
            tm1 = fmaxf(tm1, fmaxf(sacc[i][2], sacc[i][3]));
        }
        tm0 = fmaxf(tm0, __shfl_xor_sync(0xffffffffu, tm0, 1));
        tm0 = fmaxf(tm0, __shfl_xor_sync(0xffffffffu, tm0, 2));
        tm1 = fmaxf(tm1, __shfl_xor_sync(0xffffffffu, tm1, 1));
        tm1 = fmaxf(tm1, __shfl_xor_sync(0xffffffffu, tm1, 2));

        const float mn0 = fmaxf(mr0, tm0), mn1 = fmaxf(mr1, tm1);
        const float al0 = exp2f(mr0 - mn0), al1 = exp2f(mr1 - mn1);
        mr0 = mn0; mr1 = mn1;

        uint32_t phi[8][2];
        float ps0 = 0.f, ps1 = 0.f;
#pragma unroll
        for (int i = 0; i < 8; i++) {
            float p00 = exp2f(sacc[i][0] - mn0);
            float p01 = exp2f(sacc[i][1] - mn0);
            float p10 = exp2f(sacc[i][2] - mn1);
            float p11 = exp2f(sacc[i][3] - mn1);
            ps0 += p00 + p01; ps1 += p10 + p11;
            phi[i][0] = pack_h2(p00, p01);
            phi[i][1] = pack_h2(p10, p11);
        }
        l0 = l0 * al0 + ps0;
        l1 = l1 * al1 + ps1;
#pragma unroll
        for (int i = 0; i < 16; i++) {
            oacc[i][0] *= al0; oacc[i][1] *= al0;
            oacc[i][2] *= al1; oacc[i][3] *= al1;
        }

#pragma unroll
        for (int pk = 0; pk < 4; pk++) {
            uint32_t ap[4] = {phi[2 * pk][0], phi[2 * pk][1],
                              phi[2 * pk + 1][0], phi[2 * pk + 1][1]};
#pragma unroll
            for (int jn = 0; jn < 8; jn++) {
                uint32_t bv[4];
                const int vr = jn * 16 + (lid & 7) + ((lid >> 4) & 1) * 8;
                const int vg = pk * 2 + ((lid >> 3) & 1);
                ldsm4(bv, stb + F_V + SWV(vr, vg));
                mma_f16(oacc[2 * jn],     ap, &bv[0]);
                mma_f16(oacc[2 * jn + 1], ap, &bv[2]);
            }
        }
        __syncthreads();
    }

    l0 += __shfl_xor_sync(0xffffffffu, l0, 1);
    l0 += __shfl_xor_sync(0xffffffffu, l0, 2);
    l1 += __shfl_xor_sync(0xffffffffu, l1, 1);
    l1 += __shfl_xor_sync(0xffffffffu, l1, 2);
    const float inv0 = 1.0f / l0, inv1 = 1.0f / l1;

    const int r = lid >> 2, c2 = (lid & 3) * 2;
    const int qg = q0 + wid * 16 + r;
    const size_t row0 = ((size_t)(zb * LQ_) + qg) * D_ + zh * HD_;
    const size_t row1 = row0 + 8 * D_;
#pragma unroll
    for (int jt = 0; jt < 16; jt++) {
        int col = jt * 8 + c2;
        *(uint32_t*)(ct + row0 + col) = pack_h2(oacc[jt][0] * inv0, oacc[jt][1] * inv0);
        *(uint32_t*)(ct + row1 + col) = pack_h2(oacc[jt][2] * inv1, oacc[jt][3] * inv1);
    }
}

// ---------------------------------------------------------------------------
extern "C" void kernel_launch(void* const* d_in, const int* in_sizes, int n_in,
                              void* d_out, int out_size)
{
    const float* x   = (const float*)d_in[0];
    const float* enc = (const float*)d_in[1];
    const float* Wq  = (const float*)d_in[2];
    const float* Wk  = (const float*)d_in[3];
    const float* Wv  = (const float*)d_in[4];
    const float* bq  = (const float*)d_in[5];
    const float* bk  = (const float*)d_in[6];
    const float* bv  = (const float*)d_in[7];
    const float* Wo  = (const float*)d_in[8];
    const float* bo  = (const float*)d_in[9];
    float* out = (float*)d_out;

    __half *xh, *eh, *wqh, *wql, *wk, *wv, *woh, *wol;
    __half *qh, *kh, *vth, *ct;
    cudaGetSymbolAddress((void**)&xh,  g_xh);
    cudaGetSymbolAddress((void**)&eh,  g_eh);
    cudaGetSymbolAddress((void**)&wqh, g_wqhi); cudaGetSymbolAddress((void**)&wql, g_wqlo);
    cudaGetSymbolAddress((void**)&wk,  g_wk);
    cudaGetSymbolAddress((void**)&wv,  g_wv);
    cudaGetSymbolAddress((void**)&woh, g_wohi); cudaGetSymbolAddress((void**)&wol, g_wolo);
    cudaGetSymbolAddress((void**)&qh,  g_qh);   cudaGetSymbolAddress((void**)&kh,  g_kh);
    cudaGetSymbolAddress((void**)&vth, g_vth);  cudaGetSymbolAddress((void**)&ct,  g_ct);

    cudaFuncSetAttribute((const void*)gemm_kernel<0, 2>, cudaFuncAttributeMaxDynamicSharedMemorySize, GEMM_SMEM2);
    cudaFuncSetAttribute((const void*)gemm_kernel<3, 2>, cudaFuncAttributeMaxDynamicSharedMemorySize, GEMM_SMEM2);
    cudaFuncSetAttribute((const void*)gemm_kernel<3, 1>, cudaFuncAttributeMaxDynamicSharedMemorySize, GEMM_SMEM1);
    cudaFuncSetAttribute((const void*)gemm_kernel<4, 1>, cudaFuncAttributeMaxDynamicSharedMemorySize, GEMM_SMEM1);
    cudaFuncSetAttribute((const void*)flash_kernel, cudaFuncAttributeMaxDynamicSharedMemorySize, FLASH_SMEM);

    // 1) converts + weight prep
    convert_kernel<<<1024, 256>>>(x,   xh, (int)(NX / 4));
    convert_kernel<<<1024, 256>>>(enc, eh, (int)(NE / 4));
    wsplit_kernel<<<256, 256>>>(Wq, wqh, wql, (int)(NW / 4));
    convert_kernel<<<256, 256>>>(Wk, wk, (int)(NW / 4));
    convert_kernel<<<256, 256>>>(Wv, wv, (int)(NW / 4));
    wsplit_kernel<<<256, 256>>>(Wo, woh, wol, (int)(NW / 4));

    // 2) projections. Q: 2-pass, pre-scaled by log2e/sqrt(HD). K/V: 1-pass.
    gemm_kernel<3, 2><<<dim3(4, 32), 256, GEMM_SMEM2>>>(
        xh, D_, wqh, wql, D_, nullptr, qh, D_, D_, bq, QSCALE_);
    gemm_kernel<3, 1><<<dim3(4, 128), 256, GEMM_SMEM1>>>(
        eh, D_, wk, nullptr, D_, nullptr, kh, D_, D_, bk, 1.0f);
    gemm_kernel<4, 1><<<dim3(4, 128), 256, GEMM_SMEM1>>>(
        eh, D_, wv, nullptr, D_, nullptr, vth, D_, D_, bv, 1.0f);

    // 3) fused flash attention (fp16, exp2 softmax) -> ctx fp16
    flash_kernel<<<dim3(LQ_ / 128, B_ * H_), 256, FLASH_SMEM>>>(qh, kh, vth, ct);

    // 4) output projection (2-pass fp16) -> fp32 out
    gemm_kernel<0, 2><<<dim3(4, 32), 256, GEMM_SMEM2>>>(
        ct, D_, woh, wol, D_, out, nullptr, D_, D_, bo, 1.0f);
}

// round 9
// speedup vs baseline: 8.3247x; 1.0575x over previous
#include <cuda_runtime.h>
#include <cuda_bf16.h>
#include <cuda_fp16.h>
#include <cstdint>
#include <math.h>

#define B_   4
#define LQ_  1024
#define LKV_ 4096
#define D_   512
#define H_   4
#define HD_  128
#define SCALE_ 0.08838834764831845f      // 1/sqrt(128)
#define LOG2E_ 1.4426950408889634f
#define QSCALE_ (SCALE_ * LOG2E_)        // logits emitted in log2 domain

// ---------------------------------------------------------------------------
// Helpers
// ---------------------------------------------------------------------------
__device__ __forceinline__ uint32_t smem_u32(const void* p) {
    uint32_t a;
    asm("{ .reg .u64 t; cvta.to.shared.u64 t, %1; cvt.u32.u64 %0, t; }" : "=r"(a) : "l"(p));
    return a;
}
#define SW64(x) ((x) ^ (((x) >> 3) & 0x30))

#define CP_ASYNC16(sa, g) \
    asm volatile("cp.async.cg.shared.global [%0], [%1], 16;" :: "r"(sa), "l"(g))
#define CP_COMMIT() asm volatile("cp.async.commit_group;" ::: "memory")
#define CP_WAIT(n)  asm volatile("cp.async.wait_group %0;" :: "n"(n) : "memory")

__device__ __forceinline__ void ldsm4(uint32_t* r, uint32_t a) {
    asm volatile("ldmatrix.sync.aligned.m8n8.x4.shared.b16 {%0,%1,%2,%3}, [%4];"
                 : "=r"(r[0]), "=r"(r[1]), "=r"(r[2]), "=r"(r[3]) : "r"(a));
}
__device__ __forceinline__ void mma_f16(float* c, const uint32_t* a, const uint32_t* b) {
    asm volatile("mma.sync.aligned.m16n8k16.row.col.f32.f16.f16.f32 "
                 "{%0,%1,%2,%3}, {%4,%5,%6,%7}, {%8,%9}, {%0,%1,%2,%3};"
                 : "+f"(c[0]), "+f"(c[1]), "+f"(c[2]), "+f"(c[3])
                 : "r"(a[0]), "r"(a[1]), "r"(a[2]), "r"(a[3]), "r"(b[0]), "r"(b[1]));
}
__device__ __forceinline__ uint32_t pack_h2(float a, float b) {
    __half2 v = __floats2half2_rn(a, b);
    return *(uint32_t*)&v;
}

// ---------------------------------------------------------------------------
// Device scratch (allocation-free)
// ---------------------------------------------------------------------------
#define NX  ((size_t)B_ * LQ_ * D_)
#define NE  ((size_t)B_ * LKV_ * D_)
#define NW  ((size_t)D_ * D_)

__device__ __half g_xh[NX];
__device__ __half g_eh[NE];
__device__ __half g_wqhi[NW], g_wqlo[NW];
__device__ __half g_wk[NW];
__device__ __half g_wv[NW];
__device__ __half g_wohi[NW], g_wolo[NW];
__device__ __half g_qh[NX];
__device__ __half g_kh[NE];
__device__ __half g_vth[NE];           // transposed [b][h*HD+d][lkv]
__device__ __half g_ct[NX];

// ---------------------------------------------------------------------------
// Fused prep kernels
// ---------------------------------------------------------------------------
// inputs: y=0 -> x (NX), y=1 -> enc (NE)
__global__ __launch_bounds__(256) void iconv_kernel(
    const float* __restrict__ x, const float* __restrict__ enc,
    __half* __restrict__ xh, __half* __restrict__ eh)
{
    const int which = blockIdx.y;
    const float* in = which ? enc : x;
    __half* outp = which ? eh : xh;
    const int n4 = which ? (int)(NE / 4) : (int)(NX / 4);
    int stride = gridDim.x * blockDim.x;
    for (int i = blockIdx.x * blockDim.x + threadIdx.x; i < n4; i += stride) {
        float4 v = ((const float4*)in)[i];
        ((uint2*)outp)[i] = make_uint2(pack_h2(v.x, v.y), pack_h2(v.z, v.w));
    }
}

// weights: y=0 Wq->split(wqh,wql); y=1 Wk->wk; y=2 Wv->wv; y=3 Wo->split(woh,wol)
__global__ __launch_bounds__(256) void wprep_kernel(
    const float* __restrict__ Wq, const float* __restrict__ Wk,
    const float* __restrict__ Wv, const float* __restrict__ Wo,
    __half* __restrict__ wqh, __half* __restrict__ wql,
    __half* __restrict__ wk, __half* __restrict__ wv,
    __half* __restrict__ woh, __half* __restrict__ wol)
{
    const int which = blockIdx.y;
    const int n4 = (int)(NW / 4);
    const int stride = gridDim.x * blockDim.x;
    const float* in = (which == 0) ? Wq : (which == 1) ? Wk : (which == 2) ? Wv : Wo;
    if (which == 1 || which == 2) {
        __half* outp = (which == 1) ? wk : wv;
        for (int i = blockIdx.x * blockDim.x + threadIdx.x; i < n4; i += stride) {
            float4 v = ((const float4*)in)[i];
            ((uint2*)outp)[i] = make_uint2(pack_h2(v.x, v.y), pack_h2(v.z, v.w));
        }
    } else {
        __half* hi = (which == 0) ? wqh : woh;
        __half* lo = (which == 0) ? wql : wol;
        for (int i = blockIdx.x * blockDim.x + threadIdx.x; i < n4; i += stride) {
            float4 v = ((const float4*)in)[i];
            float f[4] = {v.x, v.y, v.z, v.w};
            float h[4], l[4];
#pragma unroll
            for (int j = 0; j < 4; j++) {
                h[j] = __half2float(__float2half_rn(f[j]));
                l[j] = f[j] - h[j];
            }
            ((uint2*)hi)[i] = make_uint2(pack_h2(h[0], h[1]), pack_h2(h[2], h[3]));
            ((uint2*)lo)[i] = make_uint2(pack_h2(l[0], l[1]), pack_h2(l[2], l[3]));
        }
    }
}

// ---------------------------------------------------------------------------
// Generic NT GEMM, fp16 tensor-core. PASSES=2: B hi/lo; PASSES=1: B single.
// CTA tile 128x128, warp tile 64x32, K-chunk 32, 2-stage cp.async.
// MODE 0: fp32 out. MODE 3: fp16 out (q, k). MODE 4: fp16 transposed (vt).
// ---------------------------------------------------------------------------
template <int PASSES> struct StageCfg {
    static const int bytes = (PASSES == 2) ? 24576 : 16384;
};
#define OFF_A  0
#define OFF_BH 8192
#define OFF_BL 16384
#define GEMM_SMEM2 49152
#define GEMM_SMEM1 32768

template <int MODE, int PASSES>
__global__ __launch_bounds__(256) void gemm_kernel(
    const __half* __restrict__ A, int lda,
    const __half* __restrict__ Bh, const __half* __restrict__ Bl, int ldb,
    float* __restrict__ Cf, __half* __restrict__ Ch,
    int ldc, int K, const float* __restrict__ bias, float scale)
{
    extern __shared__ char smem[];
    const uint32_t sb = smem_u32(smem);
    const int t = threadIdx.x, wid = t >> 5, lid = t & 31;
    const int wm = wid & 1, wn = wid >> 1;
    const int m0 = blockIdx.y * 128, n0 = blockIdx.x * 128;
    const int STG = StageCfg<PASSES>::bytes;

    const __half* Ab  = A  + (size_t)m0 * lda;
    const __half* Bbh = Bh + (size_t)n0 * ldb;
    const __half* Bbl = (PASSES == 2) ? (Bl + (size_t)n0 * ldb) : nullptr;

    float acc[4][4][4];
#pragma unroll
    for (int i = 0; i < 4; i++)
#pragma unroll
        for (int j = 0; j < 4; j++)
#pragma unroll
            for (int r = 0; r < 4; r++) acc[i][j][r] = 0.f;

    const int nch = K >> 5;

    auto load_stage = [&](int c, int st) {
        const int k0 = c << 5;
        const uint32_t sbase = sb + st * STG;
#pragma unroll
        for (int i = 0; i < 2; i++) {
            int idx = t + i * 256;
            int r = idx >> 2, s = idx & 3;
            uint32_t so = SW64(r * 64 + s * 16);
            size_t oa = (size_t)r * lda + k0 + s * 8;
            size_t ob = (size_t)r * ldb + k0 + s * 8;
            CP_ASYNC16(sbase + OFF_A + so, Ab + oa);
            CP_ASYNC16(sbase + OFF_BH + so, Bbh + ob);
            if (PASSES == 2) CP_ASYNC16(sbase + OFF_BL + so, Bbl + ob);
        }
        CP_COMMIT();
    };

    load_stage(0, 0);

    for (int c = 0; c < nch; c++) {
        if (c + 1 < nch) { load_stage(c + 1, (c + 1) & 1); CP_WAIT(1); }
        else             { CP_WAIT(0); }
        __syncthreads();

        const uint32_t sbase = sb + (c & 1) * STG;
#pragma unroll
        for (int ks = 0; ks < 2; ks++) {
            uint32_t ah[4][4], bh[2][4], bl[2][4];
            const int ar = wm * 64 + (lid & 15);
            const int akb = ks * 32 + ((lid >> 4) << 4);
#pragma unroll
            for (int im = 0; im < 4; im++)
                ldsm4(ah[im], sbase + OFF_A + SW64((uint32_t)(ar + im * 16) * 64 + akb));
            const int br = wn * 32 + (lid & 7) + ((lid >> 4) & 1) * 8;
            const int bkb = ks * 32 + ((lid >> 3) & 1) * 16;
#pragma unroll
            for (int g = 0; g < 2; g++) {
                uint32_t off = SW64((uint32_t)(br + g * 16) * 64 + bkb);
                ldsm4(bh[g], sbase + OFF_BH + off);
                if (PASSES == 2) ldsm4(bl[g], sbase + OFF_BL + off);
            }
#pragma unroll
            for (int im = 0; im < 4; im++)
#pragma unroll
                for (int in = 0; in < 4; in++) {
                    int g = in >> 1, s2 = (in & 1) * 2;
                    mma_f16(acc[im][in], ah[im], &bh[g][s2]);
                    if (PASSES == 2) mma_f16(acc[im][in], ah[im], &bl[g][s2]);
                }
        }
        __syncthreads();
    }

    const int group = lid >> 2, tid4 = lid & 3;

    auto emit = [&](int m, int n, float v) {
        if (bias) v += bias[n];
        v *= scale;
        if (MODE == 0) {
            Cf[(size_t)m * ldc + n] = v;
        } else if (MODE == 3) {
            Ch[(size_t)m * ldc + n] = __float2half_rn(v);
        } else {  // MODE 4: vt transposed
            int bb = m >> 12, kv = m & (LKV_ - 1);
            Ch[((size_t)(bb * D_ + n)) * LKV_ + kv] = __float2half_rn(v);
        }
    };

#pragma unroll
    for (int im = 0; im < 4; im++)
#pragma unroll
        for (int in = 0; in < 4; in++) {
            int row = m0 + wm * 64 + im * 16 + group;
            int col = n0 + wn * 32 + in * 8 + tid4 * 2;
            emit(row,     col,     acc[im][in][0]);
            emit(row,     col + 1, acc[im][in][1]);
            emit(row + 8, col,     acc[im][in][2]);
            emit(row + 8, col + 1, acc[im][in][3]);
        }
}

// ---------------------------------------------------------------------------
// Flash attention, fp16 single-pass, exp2 softmax.
// Q-tile 64, 128 threads (4 warps, 16 q-rows each) -> 256 CTAs, 2 CTAs/SM.
// ---------------------------------------------------------------------------
#define F_Q    0
#define F_ST   16384
#define F_STSZ 32768
#define F_K    0
#define F_V    16384
#define FLASH_SMEM (F_ST + 2 * F_STSZ)   // 81920

#define SWQ(r, g) ((uint32_t)(r) * 256 + ((uint32_t)((g) ^ ((r) & 15)) << 4))
#define SWV(r, g) ((uint32_t)(r) * 128 + ((uint32_t)((g) ^ ((r) & 7)) << 4))

__global__ __launch_bounds__(128, 2) void flash_kernel(
    const __half* __restrict__ q, const __half* __restrict__ k,
    const __half* __restrict__ vt, __half* __restrict__ ct)
{
    extern __shared__ char smem[];
    const uint32_t sb = smem_u32(smem);
    const int t = threadIdx.x, wid = t >> 5, lid = t & 31;
    const int z = blockIdx.y, zb = z >> 2, zh = z & 3;
    const int q0 = blockIdx.x * 64;

    // --- load Q tile (64 x 128 fp16) ---
#pragma unroll
    for (int i = 0; i < 8; i++) {
        int idx = t + i * 128;
        int r = idx >> 4, g = idx & 15;
        const __half* gp = q + ((size_t)(zb * LQ_ + q0 + r)) * D_ + zh * HD_ + g * 8;
        CP_ASYNC16(sb + F_Q + SWQ(r, g), gp);
    }
    CP_COMMIT();

    auto load_kv = [&](int kt2, int st) {
        const int kv0 = kt2 * 64;
        const uint32_t stb = sb + F_ST + st * F_STSZ;
#pragma unroll
        for (int i = 0; i < 8; i++) {
            int idx = t + i * 128;
            int r = idx >> 4, g = idx & 15;
            const __half* gp = k + ((size_t)(zb * LKV_ + kv0 + r)) * D_ + zh * HD_ + g * 8;
            CP_ASYNC16(stb + F_K + SWQ(r, g), gp);
        }
#pragma unroll
        for (int i = 0; i < 8; i++) {
            int idx = t + i * 128;
            int r = idx >> 3, g = idx & 7;
            const __half* gp = vt + ((size_t)(zb * D_ + zh * HD_ + r)) * LKV_ + kv0 + g * 8;
            CP_ASYNC16(stb + F_V + SWV(r, g), gp);
        }
        CP_COMMIT();
    };

    load_kv(0, 0);

    float oacc[16][4];
#pragma unroll
    for (int i = 0; i < 16; i++)
#pragma unroll
        for (int j = 0; j < 4; j++) oacc[i][j] = 0.f;
    float mr0 = -1e30f, mr1 = -1e30f, l0 = 0.f, l1 = 0.f;

    for (int kt = 0; kt < LKV_ / 64; kt++) {
        if (kt + 1 < LKV_ / 64) { load_kv(kt + 1, (kt + 1) & 1); CP_WAIT(1); }
        else                    { CP_WAIT(0); }
        __syncthreads();
        const uint32_t stb = sb + F_ST + (kt & 1) * F_STSZ;

        // ---- S = Q . K^T  (16 x 64 per warp, K=128) ----
        float sacc[8][4];
#pragma unroll
        for (int i = 0; i < 8; i++)
#pragma unroll
            for (int j = 0; j < 4; j++) sacc[i][j] = 0.f;

#pragma unroll
        for (int ks = 0; ks < 8; ks++) {
            uint32_t aq[4];
            const int ar = wid * 16 + (lid & 15);
            const int ag = ks * 2 + (lid >> 4);
            ldsm4(aq, sb + F_Q + SWQ(ar, ag));
#pragma unroll
            for (int jn = 0; jn < 4; jn++) {
                uint32_t bk4[4];
                const int br = jn * 16 + (lid & 7) + ((lid >> 4) & 1) * 8;
                const int bg = ks * 2 + ((lid >> 3) & 1);
                ldsm4(bk4, stb + F_K + SWQ(br, bg));
                mma_f16(sacc[2 * jn],     aq, &bk4[0]);
                mma_f16(sacc[2 * jn + 1], aq, &bk4[2]);
            }
        }

        // ---- online softmax (log2 domain) ----
        float tm0 = -1e30f, tm1 = -1e30f;
#pragma unroll
        for (int i = 0; i < 8; i++) {
            tm0 = fmaxf(tm0, fmaxf(sacc[i][0], sacc[i][1]));
            tm1 = fmaxf(tm1, fmaxf(sacc[i][2], sacc[i][3]));
        }
        tm0 = fmaxf(tm0, __shfl_xor_sync(0xffffffffu, tm0, 1));
        tm0 = fmaxf(tm0, __shfl_xor_sync(0xffffffffu, tm0, 2));
        tm1 = fmaxf(tm1, __shfl_xor_sync(0xffffffffu, tm1, 1));
        tm1 = fmaxf(tm1, __shfl_xor_sync(0xffffffffu, tm1, 2));

        const float mn0 = fmaxf(mr0, tm0), mn1 = fmaxf(mr1, tm1);
        const float al0 = exp2f(mr0 - mn0), al1 = exp2f(mr1 - mn1);
        mr0 = mn0; mr1 = mn1;

        uint32_t phi[8][2];
        float ps0 = 0.f, ps1 = 0.f;
#pragma unroll
        for (int i = 0; i < 8; i++) {
            float p00 = exp2f(sacc[i][0] - mn0);
            float p01 = exp2f(sacc[i][1] - mn0);
            float p10 = exp2f(sacc[i][2] - mn1);
            float p11 = exp2f(sacc[i][3] - mn1);
            ps0 += p00 + p01; ps1 += p10 + p11;
            phi[i][0] = pack_h2(p00, p01);
            phi[i][1] = pack_h2(p10, p11);
        }
        l0 = l0 * al0 + ps0;
        l1 = l1 * al1 + ps1;
        if (al0 != 1.f || al1 != 1.f) {
#pragma unroll
            for (int i = 0; i < 16; i++) {
                oacc[i][0] *= al0; oacc[i][1] *= al0;
                oacc[i][2] *= al1; oacc[i][3] *= al1;
            }
        }

        // ---- O += P . V  (P C-frag reused as fp16 A-frag) ----
#pragma unroll
        for (int pk = 0; pk < 4; pk++) {
            uint32_t ap[4] = {phi[2 * pk][0], phi[2 * pk][1],
                              phi[2 * pk + 1][0], phi[2 * pk + 1][1]};
#pragma unroll
            for (int jn = 0; jn < 8; jn++) {
                uint32_t bv[4];
                const int vr = jn * 16 + (lid & 7) + ((lid >> 4) & 1) * 8;
                const int vg = pk * 2 + ((lid >> 3) & 1);
                ldsm4(bv, stb + F_V + SWV(vr, vg));
                mma_f16(oacc[2 * jn],     ap, &bv[0]);
                mma_f16(oacc[2 * jn + 1], ap, &bv[2]);
            }
        }
        __syncthreads();
    }

    l0 += __shfl_xor_sync(0xffffffffu, l0, 1);
    l0 += __shfl_xor_sync(0xffffffffu, l0, 2);
    l1 += __shfl_xor_sync(0xffffffffu, l1, 1);
    l1 += __shfl_xor_sync(0xffffffffu, l1, 2);
    const float inv0 = 1.0f / l0, inv1 = 1.0f / l1;

    const int r = lid >> 2, c2 = (lid & 3) * 2;
    const int qg = q0 + wid * 16 + r;
    const size_t row0 = ((size_t)(zb * LQ_) + qg) * D_ + zh * HD_;
    const size_t row1 = row0 + 8 * D_;
#pragma unroll
    for (int jt = 0; jt < 16; jt++) {
        int col = jt * 8 + c2;
        *(uint32_t*)(ct + row0 + col) = pack_h2(oacc[jt][0] * inv0, oacc[jt][1] * inv0);
        *(uint32_t*)(ct + row1 + col) = pack_h2(oacc[jt][2] * inv1, oacc[jt][3] * inv1);
    }
}

// ---------------------------------------------------------------------------
extern "C" void kernel_launch(void* const* d_in, const int* in_sizes, int n_in,
                              void* d_out, int out_size)
{
    const float* x   = (const float*)d_in[0];
    const float* enc = (const float*)d_in[1];
    const float* Wq  = (const float*)d_in[2];
    const float* Wk  = (const float*)d_in[3];
    const float* Wv  = (const float*)d_in[4];
    const float* bq  = (const float*)d_in[5];
    const float* bk  = (const float*)d_in[6];
    const float* bv  = (const float*)d_in[7];
    const float* Wo  = (const float*)d_in[8];
    const float* bo  = (const float*)d_in[9];
    float* out = (float*)d_out;

    __half *xh, *eh, *wqh, *wql, *wk, *wv, *woh, *wol;
    __half *qh, *kh, *vth, *ct;
    cudaGetSymbolAddress((void**)&xh,  g_xh);
    cudaGetSymbolAddress((void**)&eh,  g_eh);
    cudaGetSymbolAddress((void**)&wqh, g_wqhi); cudaGetSymbolAddress((void**)&wql, g_wqlo);
    cudaGetSymbolAddress((void**)&wk,  g_wk);
    cudaGetSymbolAddress((void**)&wv,  g_wv);
    cudaGetSymbolAddress((void**)&woh, g_wohi); cudaGetSymbolAddress((void**)&wol, g_wolo);
    cudaGetSymbolAddress((void**)&qh,  g_qh);   cudaGetSymbolAddress((void**)&kh,  g_kh);
    cudaGetSymbolAddress((void**)&vth, g_vth);  cudaGetSymbolAddress((void**)&ct,  g_ct);

    cudaFuncSetAttribute((const void*)gemm_kernel<0, 2>, cudaFuncAttributeMaxDynamicSharedMemorySize, GEMM_SMEM2);
    cudaFuncSetAttribute((const void*)gemm_kernel<3, 2>, cudaFuncAttributeMaxDynamicSharedMemorySize, GEMM_SMEM2);
    cudaFuncSetAttribute((const void*)gemm_kernel<3, 1>, cudaFuncAttributeMaxDynamicSharedMemorySize, GEMM_SMEM1);
    cudaFuncSetAttribute((const void*)gemm_kernel<4, 1>, cudaFuncAttributeMaxDynamicSharedMemorySize, GEMM_SMEM1);
    cudaFuncSetAttribute((const void*)flash_kernel, cudaFuncAttributeMaxDynamicSharedMemorySize, FLASH_SMEM);

    // 1) fused prep: inputs (2D grid) + weights (2D grid)
    iconv_kernel<<<dim3(1024, 2), 256>>>(x, enc, xh, eh);
    wprep_kernel<<<dim3(128, 4), 256>>>(Wq, Wk, Wv, Wo, wqh, wql, wk, wv, woh, wol);

    // 2) projections. Q: 2-pass, pre-scaled by log2e/sqrt(HD). K/V: 1-pass.
    gemm_kernel<3, 2><<<dim3(4, 32), 256, GEMM_SMEM2>>>(
        xh, D_, wqh, wql, D_, nullptr, qh, D_, D_, bq, QSCALE_);
    gemm_kernel<3, 1><<<dim3(4, 128), 256, GEMM_SMEM1>>>(
        eh, D_, wk, nullptr, D_, nullptr, kh, D_, D_, bk, 1.0f);
    gemm_kernel<4, 1><<<dim3(4, 128), 256, GEMM_SMEM1>>>(
        eh, D_, wv, nullptr, D_, nullptr, vth, D_, D_, bv, 1.0f);

    // 3) fused flash attention (fp16, exp2) -> ctx fp16; 256 CTAs fill chip
    flash_kernel<<<dim3(LQ_ / 64, B_ * H_), 128, FLASH_SMEM>>>(qh, kh, vth, ct);

    // 4) output projection (2-pass fp16) -> fp32 out
    gemm_kernel<0, 2><<<dim3(4, 32), 256, GEMM_SMEM2>>>(
        ct, D_, woh, wol, D_, out, nullptr, D_, D_, bo, 1.0f);
}

// round 10
// speedup vs baseline: 8.4782x; 1.0184x over previous
#include <cuda_runtime.h>
#include <cuda_bf16.h>
#include <cuda_fp16.h>
#include <cstdint>
#include <math.h>

#define B_   4
#define LQ_  1024
#define LKV_ 4096
#define D_   512
#define H_   4
#define HD_  128
#define SCALE_ 0.08838834764831845f      // 1/sqrt(128)
#define LOG2E_ 1.4426950408889634f
#define QSCALE_ (SCALE_ * LOG2E_)        // logits emitted in log2 domain

// ---------------------------------------------------------------------------
// Helpers
// ---------------------------------------------------------------------------
__device__ __forceinline__ uint32_t smem_u32(const void* p) {
    uint32_t a;
    asm("{ .reg .u64 t; cvta.to.shared.u64 t, %1; cvt.u32.u64 %0, t; }" : "=r"(a) : "l"(p));
    return a;
}
#define SW64(x) ((x) ^ (((x) >> 3) & 0x30))

#define CP_ASYNC16(sa, g) \
    asm volatile("cp.async.cg.shared.global [%0], [%1], 16;" :: "r"(sa), "l"(g))
#define CP_COMMIT() asm volatile("cp.async.commit_group;" ::: "memory")
#define CP_WAIT(n)  asm volatile("cp.async.wait_group %0;" :: "n"(n) : "memory")

__device__ __forceinline__ void ldsm4(uint32_t* r, uint32_t a) {
    asm volatile("ldmatrix.sync.aligned.m8n8.x4.shared.b16 {%0,%1,%2,%3}, [%4];"
                 : "=r"(r[0]), "=r"(r[1]), "=r"(r[2]), "=r"(r[3]) : "r"(a));
}
__device__ __forceinline__ void mma_f16(float* c, const uint32_t* a, const uint32_t* b) {
    asm volatile("mma.sync.aligned.m16n8k16.row.col.f32.f16.f16.f32 "
                 "{%0,%1,%2,%3}, {%4,%5,%6,%7}, {%8,%9}, {%0,%1,%2,%3};"
                 : "+f"(c[0]), "+f"(c[1]), "+f"(c[2]), "+f"(c[3])
                 : "r"(a[0]), "r"(a[1]), "r"(a[2]), "r"(a[3]), "r"(b[0]), "r"(b[1]));
}
__device__ __forceinline__ uint32_t pack_h2(float a, float b) {
    __half2 v = __floats2half2_rn(a, b);
    return *(uint32_t*)&v;
}

// ---------------------------------------------------------------------------
// Device scratch (allocation-free)
// ---------------------------------------------------------------------------
#define NX  ((size_t)B_ * LQ_ * D_)
#define NE  ((size_t)B_ * LKV_ * D_)
#define NW  ((size_t)D_ * D_)

__device__ __half g_xh[NX];
__device__ __half g_eh[NE];
__device__ __half g_wqhi[NW], g_wqlo[NW];
__device__ __half g_wk[NW];
__device__ __half g_wv[NW];
__device__ __half g_wohi[NW], g_wolo[NW];
__device__ __half g_qh[NX];
__device__ __half g_kh[NE];
__device__ __half g_vth[NE];           // transposed [b][h*HD+d][lkv]
__device__ __half g_ct[NX];

// ---------------------------------------------------------------------------
// Fused prep kernels
// ---------------------------------------------------------------------------
__global__ __launch_bounds__(256) void iconv_kernel(
    const float* __restrict__ x, const float* __restrict__ enc,
    __half* __restrict__ xh, __half* __restrict__ eh)
{
    const int which = blockIdx.y;
    const float* in = which ? enc : x;
    __half* outp = which ? eh : xh;
    const int n4 = which ? (int)(NE / 4) : (int)(NX / 4);
    int stride = gridDim.x * blockDim.x;
    for (int i = blockIdx.x * blockDim.x + threadIdx.x; i < n4; i += stride) {
        float4 v = ((const float4*)in)[i];
        ((uint2*)outp)[i] = make_uint2(pack_h2(v.x, v.y), pack_h2(v.z, v.w));
    }
}

__global__ __launch_bounds__(256) void wprep_kernel(
    const float* __restrict__ Wq, const float* __restrict__ Wk,
    const float* __restrict__ Wv, const float* __restrict__ Wo,
    __half* __restrict__ wqh, __half* __restrict__ wql,
    __half* __restrict__ wk, __half* __restrict__ wv,
    __half* __restrict__ woh, __half* __restrict__ wol)
{
    const int which = blockIdx.y;
    const int n4 = (int)(NW / 4);
    const int stride = gridDim.x * blockDim.x;
    const float* in = (which == 0) ? Wq : (which == 1) ? Wk : (which == 2) ? Wv : Wo;
    if (which == 1 || which == 2) {
        __half* outp = (which == 1) ? wk : wv;
        for (int i = blockIdx.x * blockDim.x + threadIdx.x; i < n4; i += stride) {
            float4 v = ((const float4*)in)[i];
            ((uint2*)outp)[i] = make_uint2(pack_h2(v.x, v.y), pack_h2(v.z, v.w));
        }
    } else {
        __half* hi = (which == 0) ? wqh : woh;
        __half* lo = (which == 0) ? wql : wol;
        for (int i = blockIdx.x * blockDim.x + threadIdx.x; i < n4; i += stride) {
            float4 v = ((const float4*)in)[i];
            float f[4] = {v.x, v.y, v.z, v.w};
            float h[4], l[4];
#pragma unroll
            for (int j = 0; j < 4; j++) {
                h[j] = __half2float(__float2half_rn(f[j]));
                l[j] = f[j] - h[j];
            }
            ((uint2*)hi)[i] = make_uint2(pack_h2(h[0], h[1]), pack_h2(h[2], h[3]));
            ((uint2*)lo)[i] = make_uint2(pack_h2(l[0], l[1]), pack_h2(l[2], l[3]));
        }
    }
}

// ---------------------------------------------------------------------------
// Generic NT GEMM, fp16 tensor-core. 4-stage cp.async ring, prefetch depth 2,
// single barrier per chunk (stage distance proof: write (c+2)&3 vs laggard
// read (c-1)&3 are always distinct mod 4).
// PASSES=2: B hi/lo; PASSES=1: B single.
// MODE 0: fp32 out. MODE 3: fp16 out (q, k). MODE 4: fp16 transposed (vt).
// ---------------------------------------------------------------------------
template <int PASSES> struct StageCfg {
    static const int bytes = (PASSES == 2) ? 24576 : 16384;
};
#define OFF_A  0
#define OFF_BH 8192
#define OFF_BL 16384
#define GEMM_SMEM2 98304   // 4 stages x 24576
#define GEMM_SMEM1 65536   // 4 stages x 16384

template <int MODE, int PASSES>
__global__ __launch_bounds__(256) void gemm_kernel(
    const __half* __restrict__ A, int lda,
    const __half* __restrict__ Bh, const __half* __restrict__ Bl, int ldb,
    float* __restrict__ Cf, __half* __restrict__ Ch,
    int ldc, int K, const float* __restrict__ bias, float scale)
{
    extern __shared__ char smem[];
    const uint32_t sb = smem_u32(smem);
    const int t = threadIdx.x, wid = t >> 5, lid = t & 31;
    const int wm = wid & 1, wn = wid >> 1;
    const int m0 = blockIdx.y * 128, n0 = blockIdx.x * 128;
    const int STG = StageCfg<PASSES>::bytes;

    const __half* Ab  = A  + (size_t)m0 * lda;
    const __half* Bbh = Bh + (size_t)n0 * ldb;
    const __half* Bbl = (PASSES == 2) ? (Bl + (size_t)n0 * ldb) : nullptr;

    float acc[4][4][4];
#pragma unroll
    for (int i = 0; i < 4; i++)
#pragma unroll
        for (int j = 0; j < 4; j++)
#pragma unroll
            for (int r = 0; r < 4; r++) acc[i][j][r] = 0.f;

    const int nch = K >> 5;

    auto load_stage = [&](int c) {
        const int k0 = c << 5;
        const uint32_t sbase = sb + (c & 3) * STG;
#pragma unroll
        for (int i = 0; i < 2; i++) {
            int idx = t + i * 256;
            int r = idx >> 2, s = idx & 3;
            uint32_t so = SW64(r * 64 + s * 16);
            size_t oa = (size_t)r * lda + k0 + s * 8;
            size_t ob = (size_t)r * ldb + k0 + s * 8;
            CP_ASYNC16(sbase + OFF_A + so, Ab + oa);
            CP_ASYNC16(sbase + OFF_BH + so, Bbh + ob);
            if (PASSES == 2) CP_ASYNC16(sbase + OFF_BL + so, Bbl + ob);
        }
        CP_COMMIT();
    };

    load_stage(0);
    if (nch > 1) load_stage(1);

    for (int c = 0; c < nch; c++) {
        if (c + 2 < nch) { load_stage(c + 2); CP_WAIT(2); }
        else if (c + 1 < nch) { CP_WAIT(1); }
        else { CP_WAIT(0); }
        __syncthreads();

        const uint32_t sbase = sb + (c & 3) * STG;
#pragma unroll
        for (int ks = 0; ks < 2; ks++) {
            uint32_t ah[4][4], bh[2][4], bl[2][4];
            const int ar = wm * 64 + (lid & 15);
            const int akb = ks * 32 + ((lid >> 4) << 4);
#pragma unroll
            for (int im = 0; im < 4; im++)
                ldsm4(ah[im], sbase + OFF_A + SW64((uint32_t)(ar + im * 16) * 64 + akb));
            const int br = wn * 32 + (lid & 7) + ((lid >> 4) & 1) * 8;
            const int bkb = ks * 32 + ((lid >> 3) & 1) * 16;
#pragma unroll
            for (int g = 0; g < 2; g++) {
                uint32_t off = SW64((uint32_t)(br + g * 16) * 64 + bkb);
                ldsm4(bh[g], sbase + OFF_BH + off);
                if (PASSES == 2) ldsm4(bl[g], sbase + OFF_BL + off);
            }
#pragma unroll
            for (int im = 0; im < 4; im++)
#pragma unroll
                for (int in = 0; in < 4; in++) {
                    int g = in >> 1, s2 = (in & 1) * 2;
                    mma_f16(acc[im][in], ah[im], &bh[g][s2]);
                    if (PASSES == 2) mma_f16(acc[im][in], ah[im], &bl[g][s2]);
                }
        }
        // no trailing barrier: 4-stage ring makes WAR impossible
    }

    const int group = lid >> 2, tid4 = lid & 3;

    auto emit = [&](int m, int n, float v) {
        if (bias) v += bias[n];
        v *= scale;
        if (MODE == 0) {
            Cf[(size_t)m * ldc + n] = v;
        } else if (MODE == 3) {
            Ch[(size_t)m * ldc + n] = __float2half_rn(v);
        } else {  // MODE 4: vt transposed
            int bb = m >> 12, kv = m & (LKV_ - 1);
            Ch[((size_t)(bb * D_ + n)) * LKV_ + kv] = __float2half_rn(v);
        }
    };

#pragma unroll
    for (int im = 0; im < 4; im++)
#pragma unroll
        for (int in = 0; in < 4; in++) {
            int row = m0 + wm * 64 + im * 16 + group;
            int col = n0 + wn * 32 + in * 8 + tid4 * 2;
            emit(row,     col,     acc[im][in][0]);
            emit(row,     col + 1, acc[im][in][1]);
            emit(row + 8, col,     acc[im][in][2]);
            emit(row + 8, col + 1, acc[im][in][3]);
        }
}

// ---------------------------------------------------------------------------
// Flash attention, fp16 single-pass, exp2 softmax. Q-tile 64, 128 threads,
// 3-stage KV ring -> single barrier per iteration (write (kt+1)%3 vs laggard
// read (kt-1)%3 distinct mod 3).
// ---------------------------------------------------------------------------
#define F_Q    0
#define F_ST   16384
#define F_STSZ 32768
#define F_K    0
#define F_V    16384
#define FLASH_SMEM (F_ST + 3 * F_STSZ)   // 114688

#define SWQ(r, g) ((uint32_t)(r) * 256 + ((uint32_t)((g) ^ ((r) & 15)) << 4))
#define SWV(r, g) ((uint32_t)(r) * 128 + ((uint32_t)((g) ^ ((r) & 7)) << 4))

__global__ __launch_bounds__(128, 2) void flash_kernel(
    const __half* __restrict__ q, const __half* __restrict__ k,
    const __half* __restrict__ vt, __half* __restrict__ ct)
{
    extern __shared__ char smem[];
    const uint32_t sb = smem_u32(smem);
    const int t = threadIdx.x, wid = t >> 5, lid = t & 31;
    const int z = blockIdx.y, zb = z >> 2, zh = z & 3;
    const int q0 = blockIdx.x * 64;

    // --- load Q tile (64 x 128 fp16) ---
#pragma unroll
    for (int i = 0; i < 8; i++) {
        int idx = t + i * 128;
        int r = idx >> 4, g = idx & 15;
        const __half* gp = q + ((size_t)(zb * LQ_ + q0 + r)) * D_ + zh * HD_ + g * 8;
        CP_ASYNC16(sb + F_Q + SWQ(r, g), gp);
    }
    CP_COMMIT();

    auto load_kv = [&](int kt2) {
        const int kv0 = kt2 * 64;
        const uint32_t stb = sb + F_ST + (kt2 % 3) * F_STSZ;
#pragma unroll
        for (int i = 0; i < 8; i++) {
            int idx = t + i * 128;
            int r = idx >> 4, g = idx & 15;
            const __half* gp = k + ((size_t)(zb * LKV_ + kv0 + r)) * D_ + zh * HD_ + g * 8;
            CP_ASYNC16(stb + F_K + SWQ(r, g), gp);
        }
#pragma unroll
        for (int i = 0; i < 8; i++) {
            int idx = t + i * 128;
            int r = idx >> 3, g = idx & 7;
            const __half* gp = vt + ((size_t)(zb * D_ + zh * HD_ + r)) * LKV_ + kv0 + g * 8;
            CP_ASYNC16(stb + F_V + SWV(r, g), gp);
        }
        CP_COMMIT();
    };

    load_kv(0);

    float oacc[16][4];
#pragma unroll
    for (int i = 0; i < 16; i++)
#pragma unroll
        for (int j = 0; j < 4; j++) oacc[i][j] = 0.f;
    float mr0 = -1e30f, mr1 = -1e30f, l0 = 0.f, l1 = 0.f;

    for (int kt = 0; kt < LKV_ / 64; kt++) {
        if (kt + 1 < LKV_ / 64) { load_kv(kt + 1); CP_WAIT(1); }
        else                    { CP_WAIT(0); }
        __syncthreads();
        const uint32_t stb = sb + F_ST + (kt % 3) * F_STSZ;

        // ---- S = Q . K^T  (16 x 64 per warp, K=128) ----
        float sacc[8][4];
#pragma unroll
        for (int i = 0; i < 8; i++)
#pragma unroll
            for (int j = 0; j < 4; j++) sacc[i][j] = 0.f;

#pragma unroll
        for (int ks = 0; ks < 8; ks++) {
            uint32_t aq[4];
            const int ar = wid * 16 + (lid & 15);
            const int ag = ks * 2 + (lid >> 4);
            ldsm4(aq, sb + F_Q + SWQ(ar, ag));
#pragma unroll
            for (int jn = 0; jn < 4; jn++) {
                uint32_t bk4[4];
                const int br = jn * 16 + (lid & 7) + ((lid >> 4) & 1) * 8;
                const int bg = ks * 2 + ((lid >> 3) & 1);
                ldsm4(bk4, stb + F_K + SWQ(br, bg));
                mma_f16(sacc[2 * jn],     aq, &bk4[0]);
                mma_f16(sacc[2 * jn + 1], aq, &bk4[2]);
            }
        }

        // ---- online softmax (log2 domain) ----
        float tm0 = -1e30f, tm1 = -1e30f;
#pragma unroll
        for (int i = 0; i < 8; i++) {
            tm0 = fmaxf(tm0, fmaxf(sacc[i][0], sacc[i][1]));
            tm1 = fmaxf(tm1, fmaxf(sacc[i][2], sacc[i][3]));
        }
        tm0 = fmaxf(tm0, __shfl_xor_sync(0xffffffffu, tm0, 1));
        tm0 = fmaxf(tm0, __shfl_xor_sync(0xffffffffu, tm0, 2));
        tm1 = fmaxf(tm1, __shfl_xor_sync(0xffffffffu, tm1, 1));
        tm1 = fmaxf(tm1, __shfl_xor_sync(0xffffffffu, tm1, 2));

        const float mn0 = fmaxf(mr0, tm0), mn1 = fmaxf(mr1, tm1);
        const float al0 = exp2f(mr0 - mn0), al1 = exp2f(mr1 - mn1);
        mr0 = mn0; mr1 = mn1;

        uint32_t phi[8][2];
        float ps0 = 0.f, ps1 = 0.f;
#pragma unroll
        for (int i = 0; i < 8; i++) {
            float p00 = exp2f(sacc[i][0] - mn0);
            float p01 = exp2f(sacc[i][1] - mn0);
            float p10 = exp2f(sacc[i][2] - mn1);
            float p11 = exp2f(sacc[i][3] - mn1);
            ps0 += p00 + p01; ps1 += p10 + p11;
            phi[i][0] = pack_h2(p00, p01);
            phi[i][1] = pack_h2(p10, p11);
        }
        l0 = l0 * al0 + ps0;
        l1 = l1 * al1 + ps1;
        if (al0 != 1.f || al1 != 1.f) {
#pragma unroll
            for (int i = 0; i < 16; i++) {
                oacc[i][0] *= al0; oacc[i][1] *= al0;
                oacc[i][2] *= al1; oacc[i][3] *= al1;
            }
        }

        // ---- O += P . V  (P C-frag reused as fp16 A-frag) ----
#pragma unroll
        for (int pk = 0; pk < 4; pk++) {
            uint32_t ap[4] = {phi[2 * pk][0], phi[2 * pk][1],
                              phi[2 * pk + 1][0], phi[2 * pk + 1][1]};
#pragma unroll
            for (int jn = 0; jn < 8; jn++) {
                uint32_t bv[4];
                const int vr = jn * 16 + (lid & 7) + ((lid >> 4) & 1) * 8;
                const int vg = pk * 2 + ((lid >> 3) & 1);
                ldsm4(bv, stb + F_V + SWV(vr, vg));
                mma_f16(oacc[2 * jn],     ap, &bv[0]);
                mma_f16(oacc[2 * jn + 1], ap, &bv[2]);
            }
        }
        // no trailing barrier: 3-stage ring makes WAR impossible
    }

    l0 += __shfl_xor_sync(0xffffffffu, l0, 1);
    l0 += __shfl_xor_sync(0xffffffffu, l0, 2);
    l1 += __shfl_xor_sync(0xffffffffu, l1, 1);
    l1 += __shfl_xor_sync(0xffffffffu, l1, 2);
    const float inv0 = 1.0f / l0, inv1 = 1.0f / l1;

    const int r = lid >> 2, c2 = (lid & 3) * 2;
    const int qg = q0 + wid * 16 + r;
    const size_t row0 = ((size_t)(zb * LQ_) + qg) * D_ + zh * HD_;
    const size_t row1 = row0 + 8 * D_;
#pragma unroll
    for (int jt = 0; jt < 16; jt++) {
        int col = jt * 8 + c2;
        *(uint32_t*)(ct + row0 + col) = pack_h2(oacc[jt][0] * inv0, oacc[jt][1] * inv0);
        *(uint32_t*)(ct + row1 + col) = pack_h2(oacc[jt][2] * inv1, oacc[jt][3] * inv1);
    }
}

// ---------------------------------------------------------------------------
extern "C" void kernel_launch(void* const* d_in, const int* in_sizes, int n_in,
                              void* d_out, int out_size)
{
    const float* x   = (const float*)d_in[0];
    const float* enc = (const float*)d_in[1];
    const float* Wq  = (const float*)d_in[2];
    const float* Wk  = (const float*)d_in[3];
    const float* Wv  = (const float*)d_in[4];
    const float* bq  = (const float*)d_in[5];
    const float* bk  = (const float*)d_in[6];
    const float* bv  = (const float*)d_in[7];
    const float* Wo  = (const float*)d_in[8];
    const float* bo  = (const float*)d_in[9];
    float* out = (float*)d_out;

    __half *xh, *eh, *wqh, *wql, *wk, *wv, *woh, *wol;
    __half *qh, *kh, *vth, *ct;
    cudaGetSymbolAddress((void**)&xh,  g_xh);
    cudaGetSymbolAddress((void**)&eh,  g_eh);
    cudaGetSymbolAddress((void**)&wqh, g_wqhi); cudaGetSymbolAddress((void**)&wql, g_wqlo);
    cudaGetSymbolAddress((void**)&wk,  g_wk);
    cudaGetSymbolAddress((void**)&wv,  g_wv);
    cudaGetSymbolAddress((void**)&woh, g_wohi); cudaGetSymbolAddress((void**)&wol, g_wolo);
    cudaGetSymbolAddress((void**)&qh,  g_qh);   cudaGetSymbolAddress((void**)&kh,  g_kh);
    cudaGetSymbolAddress((void**)&vth, g_vth);  cudaGetSymbolAddress((void**)&ct,  g_ct);

    cudaFuncSetAttribute((const void*)gemm_kernel<0, 2>, cudaFuncAttributeMaxDynamicSharedMemorySize, GEMM_SMEM2);
    cudaFuncSetAttribute((const void*)gemm_kernel<3, 2>, cudaFuncAttributeMaxDynamicSharedMemorySize, GEMM_SMEM2);
    cudaFuncSetAttribute((const void*)gemm_kernel<3, 1>, cudaFuncAttributeMaxDynamicSharedMemorySize, GEMM_SMEM1);
    cudaFuncSetAttribute((const void*)gemm_kernel<4, 1>, cudaFuncAttributeMaxDynamicSharedMemorySize, GEMM_SMEM1);
    cudaFuncSetAttribute((const void*)flash_kernel, cudaFuncAttributeMaxDynamicSharedMemorySize, FLASH_SMEM);

    // 1) fused prep
    iconv_kernel<<<dim3(1024, 2), 256>>>(x, enc, xh, eh);
    wprep_kernel<<<dim3(128, 4), 256>>>(Wq, Wk, Wv, Wo, wqh, wql, wk, wv, woh, wol);

    // 2) projections. Q: 2-pass, pre-scaled by log2e/sqrt(HD). K/V: 1-pass.
    gemm_kernel<3, 2><<<dim3(4, 32), 256, GEMM_SMEM2>>>(
        xh, D_, wqh, wql, D_, nullptr, qh, D_, D_, bq, QSCALE_);
    gemm_kernel<3, 1><<<dim3(4, 128), 256, GEMM_SMEM1>>>(
        eh, D_, wk, nullptr, D_, nullptr, kh, D_, D_, bk, 1.0f);
    gemm_kernel<4, 1><<<dim3(4, 128), 256, GEMM_SMEM1>>>(
        eh, D_, wv, nullptr, D_, nullptr, vth, D_, D_, bv, 1.0f);

    // 3) fused flash attention (fp16, exp2) -> ctx fp16
    flash_kernel<<<dim3(LQ_ / 64, B_ * H_), 128, FLASH_SMEM>>>(qh, kh, vth, ct);

    // 4) output projection (2-pass fp16) -> fp32 out
    gemm_kernel<0, 2><<<dim3(4, 32), 256, GEMM_SMEM2>>>(
        ct, D_, woh, wol, D_, out, nullptr, D_, D_, bo, 1.0f);
}

// round 11
// speedup vs baseline: 8.8698x; 1.0462x over previous
#include <cuda_runtime.h>
#include <cuda_bf16.h>
#include <cuda_fp16.h>
#include <cstdint>
#include <math.h>

#define B_   4
#define LQ_  1024
#define LKV_ 4096
#define D_   512
#define H_   4
#define HD_  128
#define SCALE_ 0.08838834764831845f      // 1/sqrt(128)
#define LOG2E_ 1.4426950408889634f
#define QSCALE_ (SCALE_ * LOG2E_)        // logits emitted in log2 domain

// ---------------------------------------------------------------------------
// Helpers
// ---------------------------------------------------------------------------
__device__ __forceinline__ uint32_t smem_u32(const void* p) {
    uint32_t a;
    asm("{ .reg .u64 t; cvta.to.shared.u64 t, %1; cvt.u32.u64 %0, t; }" : "=r"(a) : "l"(p));
    return a;
}

#define CP_ASYNC16(sa, g) \
    asm volatile("cp.async.cg.shared.global [%0], [%1], 16;" :: "r"(sa), "l"(g))
#define CP_COMMIT() asm volatile("cp.async.commit_group;" ::: "memory")
#define CP_WAIT(n)  asm volatile("cp.async.wait_group %0;" :: "n"(n) : "memory")

__device__ __forceinline__ void ldsm4(uint32_t* r, uint32_t a) {
    asm volatile("ldmatrix.sync.aligned.m8n8.x4.shared.b16 {%0,%1,%2,%3}, [%4];"
                 : "=r"(r[0]), "=r"(r[1]), "=r"(r[2]), "=r"(r[3]) : "r"(a));
}
__device__ __forceinline__ void mma_f16(float* c, const uint32_t* a, const uint32_t* b) {
    asm volatile("mma.sync.aligned.m16n8k16.row.col.f32.f16.f16.f32 "
                 "{%0,%1,%2,%3}, {%4,%5,%6,%7}, {%8,%9}, {%0,%1,%2,%3};"
                 : "+f"(c[0]), "+f"(c[1]), "+f"(c[2]), "+f"(c[3])
                 : "r"(a[0]), "r"(a[1]), "r"(a[2]), "r"(a[3]), "r"(b[0]), "r"(b[1]));
}
__device__ __forceinline__ uint32_t pack_h2(float a, float b) {
    __half2 v = __floats2half2_rn(a, b);
    return *(uint32_t*)&v;
}

// 128B-row swizzle (8 granules of 16B per row), conflict-free for ldsm
#define SWR(r, g) ((uint32_t)(r) * 128 + ((uint32_t)((g) ^ ((r) & 7)) << 4))
// 256B-row swizzle (flash Q/K tiles)
#define SWQ(r, g) ((uint32_t)(r) * 256 + ((uint32_t)((g) ^ ((r) & 15)) << 4))

// ---------------------------------------------------------------------------
// Device scratch (allocation-free)
// ---------------------------------------------------------------------------
#define NX  ((size_t)B_ * LQ_ * D_)
#define NE  ((size_t)B_ * LKV_ * D_)
#define NW  ((size_t)D_ * D_)

__device__ __half g_xh[NX];
__device__ __half g_eh[NE];
__device__ __half g_wqhi[NW], g_wqlo[NW];
__device__ __half g_wk[NW];
__device__ __half g_wv[NW];
__device__ __half g_wohi[NW], g_wolo[NW];
__device__ __half g_qh[NX];
__device__ __half g_kh[NE];
__device__ __half g_vth[NE];           // transposed [b][h*HD+d][lkv]
__device__ __half g_ct[NX];

// ---------------------------------------------------------------------------
// Single prep kernel: y selects task
// ---------------------------------------------------------------------------
__global__ __launch_bounds__(256) void prep_kernel(
    const float* __restrict__ x, const float* __restrict__ enc,
    const float* __restrict__ Wq, const float* __restrict__ Wk,
    const float* __restrict__ Wv, const float* __restrict__ Wo,
    __half* __restrict__ xh, __half* __restrict__ eh,
    __half* __restrict__ wqh, __half* __restrict__ wql,
    __half* __restrict__ wk, __half* __restrict__ wv,
    __half* __restrict__ woh, __half* __restrict__ wol)
{
    const int which = blockIdx.y;
    const int stride = gridDim.x * blockDim.x;
    const int tid0 = blockIdx.x * blockDim.x + threadIdx.x;
    if (which <= 1 || which == 3 || which == 4) {
        const float* in = (which == 0) ? x : (which == 1) ? enc : (which == 3) ? Wk : Wv;
        __half* outp    = (which == 0) ? xh : (which == 1) ? eh : (which == 3) ? wk : wv;
        const int n4    = (which == 0) ? (int)(NX / 4) : (which == 1) ? (int)(NE / 4) : (int)(NW / 4);
        for (int i = tid0; i < n4; i += stride) {
            float4 v = ((const float4*)in)[i];
            ((uint2*)outp)[i] = make_uint2(pack_h2(v.x, v.y), pack_h2(v.z, v.w));
        }
    } else {
        const float* in = (which == 2) ? Wq : Wo;
        __half* hi = (which == 2) ? wqh : woh;
        __half* lo = (which == 2) ? wql : wol;
        const int n4 = (int)(NW / 4);
        for (int i = tid0; i < n4; i += stride) {
            float4 v = ((const float4*)in)[i];
            float f[4] = {v.x, v.y, v.z, v.w};
            float h[4], l[4];
#pragma unroll
            for (int j = 0; j < 4; j++) {
                h[j] = __half2float(__float2half_rn(f[j]));
                l[j] = f[j] - h[j];
            }
            ((uint2*)hi)[i] = make_uint2(pack_h2(h[0], h[1]), pack_h2(h[2], h[3]));
            ((uint2*)lo)[i] = make_uint2(pack_h2(l[0], l[1]), pack_h2(l[2], l[3]));
        }
    }
}

// ---------------------------------------------------------------------------
// Generic NT GEMM, fp16, K-chunk 64 (128 MMAs between barriers for 2-pass,
// 64 for 1-pass). CTA tile 128x128, warp tile 64x32.
// PASSES=1: 3-stage ring, depth-1 prefetch, no trailing barrier (flash pattern).
// PASSES=2: 2-stage double buffer, leading+trailing barriers.
// MODE 0: fp32 out. MODE 3: fp16 out. MODE 5: merged KV (z: 0=K fp16, 1=V transposed).
// ---------------------------------------------------------------------------
#define OFF_A  0
#define OFF_BH 16384
#define OFF_BL 32768
#define GEMM_SMEM 98304   // P1: 3 x 32768; P2: 2 x 49152

template <int MODE, int PASSES>
__global__ __launch_bounds__(256) void gemm_kernel(
    const __half* __restrict__ A, int lda,
    const __half* __restrict__ Bh, const __half* __restrict__ Bl,
    const __half* __restrict__ Bh2, int ldb,
    float* __restrict__ Cf, __half* __restrict__ Ch, __half* __restrict__ Ch2,
    int ldc, int K, const float* __restrict__ bias, const float* __restrict__ bias2,
    float scale)
{
    extern __shared__ char smem[];
    const uint32_t sb = smem_u32(smem);
    const int t = threadIdx.x, wid = t >> 5, lid = t & 31;
    const int wm = wid & 1, wn = wid >> 1;
    const int m0 = blockIdx.y * 128, n0 = blockIdx.x * 128;
    const int STG = (PASSES == 2) ? 49152 : 32768;
    const int NSTAGE = (PASSES == 2) ? 2 : 3;

    const int zz = (MODE == 5) ? blockIdx.z : 0;
    const __half* Bsel = (MODE == 5 && zz) ? Bh2 : Bh;
    const float* bsel  = (MODE == 5 && zz) ? bias2 : bias;

    const __half* Ab  = A + (size_t)m0 * lda;
    const __half* Bbh = Bsel + (size_t)n0 * ldb;
    const __half* Bbl = (PASSES == 2) ? (Bl + (size_t)n0 * ldb) : nullptr;

    float acc[4][4][4];
#pragma unroll
    for (int i = 0; i < 4; i++)
#pragma unroll
        for (int j = 0; j < 4; j++)
#pragma unroll
            for (int r = 0; r < 4; r++) acc[i][j][r] = 0.f;

    const int nch = K >> 6;   // chunks of 64

    auto load_stage = [&](int c) {
        const int k0 = c << 6;
        const uint32_t sbase = sb + (c % NSTAGE) * STG;
#pragma unroll
        for (int i = 0; i < 4; i++) {
            int idx = t + i * 256;
            int r = idx >> 3, s = idx & 7;
            uint32_t so = SWR(r, s);
            size_t oa = (size_t)r * lda + k0 + s * 8;
            size_t ob = (size_t)r * ldb + k0 + s * 8;
            CP_ASYNC16(sbase + OFF_A + so, Ab + oa);
            CP_ASYNC16(sbase + OFF_BH + so, Bbh + ob);
            if (PASSES == 2) CP_ASYNC16(sbase + OFF_BL + so, Bbl + ob);
        }
        CP_COMMIT();
    };

    load_stage(0);

    for (int c = 0; c < nch; c++) {
        if (c + 1 < nch) { load_stage(c + 1); CP_WAIT(1); }
        else             { CP_WAIT(0); }
        __syncthreads();

        const uint32_t sbase = sb + (c % NSTAGE) * STG;
#pragma unroll
        for (int ks = 0; ks < 4; ks++) {
            uint32_t ah[4][4], bh[2][4], bl[2][4];
            const int ar = wm * 64 + (lid & 15);
            const int ag = ks * 2 + (lid >> 4);
#pragma unroll
            for (int im = 0; im < 4; im++)
                ldsm4(ah[im], sbase + OFF_A + SWR(ar + im * 16, ag));
            const int br = wn * 32 + (lid & 7) + ((lid >> 4) & 1) * 8;
            const int bg = ks * 2 + ((lid >> 3) & 1);
#pragma unroll
            for (int g = 0; g < 2; g++) {
                uint32_t off = SWR(br + g * 16, bg);
                ldsm4(bh[g], sbase + OFF_BH + off);
                if (PASSES == 2) ldsm4(bl[g], sbase + OFF_BL + off);
            }
#pragma unroll
            for (int im = 0; im < 4; im++)
#pragma unroll
                for (int in = 0; in < 4; in++) {
                    int g = in >> 1, s2 = (in & 1) * 2;
                    mma_f16(acc[im][in], ah[im], &bh[g][s2]);
                    if (PASSES == 2) mma_f16(acc[im][in], ah[im], &bl[g][s2]);
                }
        }
        if (PASSES == 2) __syncthreads();   // 2-stage WAR guard; 3-stage ring needs none
    }

    const int group = lid >> 2, tid4 = lid & 3;

    auto emit = [&](int m, int n, float v) {
        if (bsel) v += bsel[n];
        v *= scale;
        if (MODE == 0) {
            Cf[(size_t)m * ldc + n] = v;
        } else if (MODE == 3) {
            Ch[(size_t)m * ldc + n] = __float2half_rn(v);
        } else {  // MODE 5
            if (zz == 0) {
                Ch[(size_t)m * ldc + n] = __float2half_rn(v);
            } else {
                int bb = m >> 12, kv = m & (LKV_ - 1);
                Ch2[((size_t)(bb * D_ + n)) * LKV_ + kv] = __float2half_rn(v);
            }
        }
    };

#pragma unroll
    for (int im = 0; im < 4; im++)
#pragma unroll
        for (int in = 0; in < 4; in++) {
            int row = m0 + wm * 64 + im * 16 + group;
            int col = n0 + wn * 32 + in * 8 + tid4 * 2;
            emit(row,     col,     acc[im][in][0]);
            emit(row,     col + 1, acc[im][in][1]);
            emit(row + 8, col,     acc[im][in][2]);
            emit(row + 8, col + 1, acc[im][in][3]);
        }
}

// ---------------------------------------------------------------------------
// Flash attention, fp16 single-pass, exp2 softmax. Q-tile 64, 128 threads,
// 3-stage KV ring, single barrier per iteration. (unchanged from R10)
// ---------------------------------------------------------------------------
#define F_Q    0
#define F_ST   16384
#define F_STSZ 32768
#define F_K    0
#define F_V    16384
#define FLASH_SMEM (F_ST + 3 * F_STSZ)   // 114688

__global__ __launch_bounds__(128, 2) void flash_kernel(
    const __half* __restrict__ q, const __half* __restrict__ k,
    const __half* __restrict__ vt, __half* __restrict__ ct)
{
    extern __shared__ char smem[];
    const uint32_t sb = smem_u32(smem);
    const int t = threadIdx.x, wid = t >> 5, lid = t & 31;
    const int z = blockIdx.y, zb = z >> 2, zh = z & 3;
    const int q0 = blockIdx.x * 64;

#pragma unroll
    for (int i = 0; i < 8; i++) {
        int idx = t + i * 128;
        int r = idx >> 4, g = idx & 15;
        const __half* gp = q + ((size_t)(zb * LQ_ + q0 + r)) * D_ + zh * HD_ + g * 8;
        CP_ASYNC16(sb + F_Q + SWQ(r, g), gp);
    }
    CP_COMMIT();

    auto load_kv = [&](int kt2) {
        const int kv0 = kt2 * 64;
        const uint32_t stb = sb + F_ST + (kt2 % 3) * F_STSZ;
#pragma unroll
        for (int i = 0; i < 8; i++) {
            int idx = t + i * 128;
            int r = idx >> 4, g = idx & 15;
            const __half* gp = k + ((size_t)(zb * LKV_ + kv0 + r)) * D_ + zh * HD_ + g * 8;
            CP_ASYNC16(stb + F_K + SWQ(r, g), gp);
        }
#pragma unroll
        for (int i = 0; i < 8; i++) {
            int idx = t + i * 128;
            int r = idx >> 3, g = idx & 7;
            const __half* gp = vt + ((size_t)(zb * D_ + zh * HD_ + r)) * LKV_ + kv0 + g * 8;
            CP_ASYNC16(stb + F_V + SWR(r, g), gp);
        }
        CP_COMMIT();
    };

    load_kv(0);

    float oacc[16][4];
#pragma unroll
    for (int i = 0; i < 16; i++)
#pragma unroll
        for (int j = 0; j < 4; j++) oacc[i][j] = 0.f;
    float mr0 = -1e30f, mr1 = -1e30f, l0 = 0.f, l1 = 0.f;

    for (int kt = 0; kt < LKV_ / 64; kt++) {
        if (kt + 1 < LKV_ / 64) { load_kv(kt + 1); CP_WAIT(1); }
        else                    { CP_WAIT(0); }
        __syncthreads();
        const uint32_t stb = sb + F_ST + (kt % 3) * F_STSZ;

        float sacc[8][4];
#pragma unroll
        for (int i = 0; i < 8; i++)
#pragma unroll
            for (int j = 0; j < 4; j++) sacc[i][j] = 0.f;

#pragma unroll
        for (int ks = 0; ks < 8; ks++) {
            uint32_t aq[4];
            const int ar = wid * 16 + (lid & 15);
            const int ag = ks * 2 + (lid >> 4);
            ldsm4(aq, sb + F_Q + SWQ(ar, ag));
#pragma unroll
            for (int jn = 0; jn < 4; jn++) {
                uint32_t bk4[4];
                const int br = jn * 16 + (lid & 7) + ((lid >> 4) & 1) * 8;
                const int bg = ks * 2 + ((lid >> 3) & 1);
                ldsm4(bk4, stb + F_K + SWQ(br, bg));
                mma_f16(sacc[2 * jn],     aq, &bk4[0]);
                mma_f16(sacc[2 * jn + 1], aq, &bk4[2]);
            }
        }

        float tm0 = -1e30f, tm1 = -1e30f;
#pragma unroll
        for (int i = 0; i < 8; i++) {
            tm0 = fmaxf(tm0, fmaxf(sacc[i][0], sacc[i][1]));
            tm1 = fmaxf(tm1, fmaxf(sacc[i][2], sacc[i][3]));
        }
        tm0 = fmaxf(tm0, __shfl_xor_sync(0xffffffffu, tm0, 1));
        tm0 = fmaxf(tm0, __shfl_xor_sync(0xffffffffu, tm0, 2));
        tm1 = fmaxf(tm1, __shfl_xor_sync(0xffffffffu, tm1, 1));
        tm1 = fmaxf(tm1, __shfl_xor_sync(0xffffffffu, tm1, 2));

        const float mn0 = fmaxf(mr0, tm0), mn1 = fmaxf(mr1, tm1);
        const float al0 = exp2f(mr0 - mn0), al1 = exp2f(mr1 - mn1);
        mr0 = mn0; mr1 = mn1;

        uint32_t phi[8][2];
        float ps0 = 0.f, ps1 = 0.f;
#pragma unroll
        for (int i = 0; i < 8; i++) {
            float p00 = exp2f(sacc[i][0] - mn0);
            float p01 = exp2f(sacc[i][1] - mn0);
            float p10 = exp2f(sacc[i][2] - mn1);
            float p11 = exp2f(sacc[i][3] - mn1);
            ps0 += p00 + p01; ps1 += p10 + p11;
            phi[i][0] = pack_h2(p00, p01);
            phi[i][1] = pack_h2(p10, p11);
        }
        l0 = l0 * al0 + ps0;
        l1 = l1 * al1 + ps1;
        if (al0 != 1.f || al1 != 1.f) {
#pragma unroll
            for (int i = 0; i < 16; i++) {
                oacc[i][0] *= al0; oacc[i][1] *= al0;
                oacc[i][2] *= al1; oacc[i][3] *= al1;
            }
        }

#pragma unroll
        for (int pk = 0; pk < 4; pk++) {
            uint32_t ap[4] = {phi[2 * pk][0], phi[2 * pk][1],
                              phi[2 * pk + 1][0], phi[2 * pk + 1][1]};
#pragma unroll
            for (int jn = 0; jn < 8; jn++) {
                uint32_t bv[4];
                const int vr = jn * 16 + (lid & 7) + ((lid >> 4) & 1) * 8;
                const int vg = pk * 2 + ((lid >> 3) & 1);
                ldsm4(bv, stb + F_V + SWR(vr, vg));
                mma_f16(oacc[2 * jn],     ap, &bv[0]);
                mma_f16(oacc[2 * jn + 1], ap, &bv[2]);
            }
        }
    }

    l0 += __shfl_xor_sync(0xffffffffu, l0, 1);
    l0 += __shfl_xor_sync(0xffffffffu, l0, 2);
    l1 += __shfl_xor_sync(0xffffffffu, l1, 1);
    l1 += __shfl_xor_sync(0xffffffffu, l1, 2);
    const float inv0 = 1.0f / l0, inv1 = 1.0f / l1;

    const int r = lid >> 2, c2 = (lid & 3) * 2;
    const int qg = q0 + wid * 16 + r;
    const size_t row0 = ((size_t)(zb * LQ_) + qg) * D_ + zh * HD_;
    const size_t row1 = row0 + 8 * D_;
#pragma unroll
    for (int jt = 0; jt < 16; jt++) {
        int col = jt * 8 + c2;
        *(uint32_t*)(ct + row0 + col) = pack_h2(oacc[jt][0] * inv0, oacc[jt][1] * inv0);
        *(uint32_t*)(ct + row1 + col) = pack_h2(oacc[jt][2] * inv1, oacc[jt][3] * inv1);
    }
}

// ---------------------------------------------------------------------------
extern "C" void kernel_launch(void* const* d_in, const int* in_sizes, int n_in,
                              void* d_out, int out_size)
{
    const float* x   = (const float*)d_in[0];
    const float* enc = (const float*)d_in[1];
    const float* Wq  = (const float*)d_in[2];
    const float* Wk  = (const float*)d_in[3];
    const float* Wv  = (const float*)d_in[4];
    const float* bq  = (const float*)d_in[5];
    const float* bk  = (const float*)d_in[6];
    const float* bv  = (const float*)d_in[7];
    const float* Wo  = (const float*)d_in[8];
    const float* bo  = (const float*)d_in[9];
    float* out = (float*)d_out;

    __half *xh, *eh, *wqh, *wql, *wk, *wv, *woh, *wol;
    __half *qh, *kh, *vth, *ct;
    cudaGetSymbolAddress((void**)&xh,  g_xh);
    cudaGetSymbolAddress((void**)&eh,  g_eh);
    cudaGetSymbolAddress((void**)&wqh, g_wqhi); cudaGetSymbolAddress((void**)&wql, g_wqlo);
    cudaGetSymbolAddress((void**)&wk,  g_wk);
    cudaGetSymbolAddress((void**)&wv,  g_wv);
    cudaGetSymbolAddress((void**)&woh, g_wohi); cudaGetSymbolAddress((void**)&wol, g_wolo);
    cudaGetSymbolAddress((void**)&qh,  g_qh);   cudaGetSymbolAddress((void**)&kh,  g_kh);
    cudaGetSymbolAddress((void**)&vth, g_vth);  cudaGetSymbolAddress((void**)&ct,  g_ct);

    cudaFuncSetAttribute((const void*)gemm_kernel<0, 2>, cudaFuncAttributeMaxDynamicSharedMemorySize, GEMM_SMEM);
    cudaFuncSetAttribute((const void*)gemm_kernel<3, 2>, cudaFuncAttributeMaxDynamicSharedMemorySize, GEMM_SMEM);
    cudaFuncSetAttribute((const void*)gemm_kernel<5, 1>, cudaFuncAttributeMaxDynamicSharedMemorySize, GEMM_SMEM);
    cudaFuncSetAttribute((const void*)flash_kernel, cudaFuncAttributeMaxDynamicSharedMemorySize, FLASH_SMEM);

    // 1) single prep launch
    prep_kernel<<<dim3(256, 6), 256>>>(x, enc, Wq, Wk, Wv, Wo,
                                       xh, eh, wqh, wql, wk, wv, woh, wol);

    // 2) Q projection (2-pass, pre-scaled by log2e/sqrt(HD))
    gemm_kernel<3, 2><<<dim3(4, 32), 256, GEMM_SMEM>>>(
        xh, D_, wqh, wql, nullptr, D_, nullptr, qh, nullptr, D_, D_, bq, nullptr, QSCALE_);

    // 3) merged K+V projections (1-pass, z: 0=K, 1=V transposed)
    gemm_kernel<5, 1><<<dim3(4, 128, 2), 256, GEMM_SMEM>>>(
        eh, D_, wk, nullptr, wv, D_, nullptr, kh, vth, D_, D_, bk, bv, 1.0f);

    // 4) fused flash attention (fp16, exp2) -> ctx fp16
    flash_kernel<<<dim3(LQ_ / 64, B_ * H_), 128, FLASH_SMEM>>>(qh, kh, vth, ct);

    // 5) output projection (2-pass) -> fp32 out
    gemm_kernel<0, 2><<<dim3(4, 32), 256, GEMM_SMEM>>>(
        ct, D_, woh, wol, nullptr, D_, out, nullptr, nullptr, D_, D_, bo, nullptr, 1.0f);
}